// round 3
// baseline (speedup 1.0000x reference)
#include <cuda_runtime.h>
#include <math.h>

// ---------------- problem-size constants (fixed by the benchmark) ----------------
#define NMAXV 5000
#define EMAXV 160000
#define HD 256

// ---------------- scratch (device globals; no allocations allowed) --------------
__device__ float g_x   [NMAXV * 256];
__device__ float g_pre [NMAXV * 256];
__device__ float g_esrc[NMAXV * 256];
__device__ float g_edst[NMAXV * 256];
__device__ float g_agg [NMAXV * 256];
__device__ float g_fc1o[NMAXV * 1024];
__device__ float g_fc2o[NMAXV * 2048];
__device__ float g_bond[EMAXV];
__device__ float g_rbf [EMAXV * 80];
__device__ float g_h1  [EMAXV * 64];
__device__ float g_y   [EMAXV * 256];
__device__ float g_ee  [EMAXV * 256];
__device__ float g_degs[NMAXV];
__device__ float g_degd[NMAXV];
__device__ float g_nl  [NMAXV];
__device__ float g_nr  [NMAXV];
__device__ float g_sum [256];
__device__ float g_sumsq[256];
__device__ float g_mean[256];
__device__ float g_rstd[256];

// ---------------- small utility kernels ----------------
__global__ void fill_kernel(float* p, int n, float v) {
    int i = blockIdx.x * blockDim.x + threadIdx.x;
    if (i < n) p[i] = v;
}

__global__ void deg_kernel(int E, const int* __restrict__ src, const int* __restrict__ dst,
                           float* degs, float* degd) {
    int e = blockIdx.x * blockDim.x + threadIdx.x;
    if (e < E) {
        atomicAdd(&degs[src[e]], 1.0f);
        atomicAdd(&degd[dst[e]], 1.0f);
    }
}

__global__ void norm_kernel(int N, const float* __restrict__ degs, const float* __restrict__ degd,
                            float* nl, float* nr) {
    int i = blockIdx.x * blockDim.x + threadIdx.x;
    if (i < N) {
        nl[i] = rsqrtf(fmaxf(degs[i], 1.0f));
        nr[i] = rsqrtf(fmaxf(degd[i], 1.0f));
    }
}

__global__ void bond_kernel(int E, const float* __restrict__ r, float* bond) {
    int e = blockIdx.x * blockDim.x + threadIdx.x;
    if (e < E) {
        float a = r[e * 3 + 0], b = r[e * 3 + 1], c = r[e * 3 + 2];
        bond[e] = sqrtf(a * a + b * b + c * c);
    }
}

__global__ void rbf_kernel(int total, const float* __restrict__ bond, float* rbf) {
    int idx = blockIdx.x * blockDim.x + threadIdx.x;
    if (idx < total) {
        int e = idx / 80;
        int j = idx - e * 80;
        const float gamma = 79.0f / 8.0f;          // 1/mean(diff(centers))
        float cj = (8.0f / 79.0f) * (float)j;      // linspace(0, 8, 80)
        float d = bond[e] - cj;
        rbf[idx] = expf(-gamma * d * d);
    }
}

// ---------------- BatchNorm (training-mode batch stats) ----------------
// partial column sums: grid (C/32, chunks), block (32, 8)
__global__ void bn_stats_partial(int M, int C, const float* __restrict__ h,
                                 float* sum, float* sumsq) {
    int c = blockIdx.x * 32 + threadIdx.x;
    int rowsPerChunk = (M + gridDim.y - 1) / gridDim.y;
    int r0 = blockIdx.y * rowsPerChunk;
    int r1 = min(M, r0 + rowsPerChunk);
    float s = 0.f, s2 = 0.f;
    if (c < C) {
        for (int r = r0 + threadIdx.y; r < r1; r += 8) {
            float v = h[(long)r * C + c];
            s += v; s2 += v * v;
        }
    }
    __shared__ float sh[2][8][32];
    sh[0][threadIdx.y][threadIdx.x] = s;
    sh[1][threadIdx.y][threadIdx.x] = s2;
    __syncthreads();
    if (threadIdx.y == 0 && c < C) {
        float ts = 0.f, t2 = 0.f;
        #pragma unroll
        for (int i = 0; i < 8; i++) { ts += sh[0][i][threadIdx.x]; t2 += sh[1][i][threadIdx.x]; }
        atomicAdd(&sum[c], ts);
        atomicAdd(&sumsq[c], t2);
    }
}

__global__ void bn_finalize(int C, float invM, const float* sum, const float* sumsq,
                            float* mean, float* rstd) {
    int c = blockIdx.x * blockDim.x + threadIdx.x;
    if (c < C) {
        float m = sum[c] * invM;
        float var = fmaxf(sumsq[c] * invM - m * m, 0.0f);
        mean[c] = m;
        rstd[c] = rsqrtf(var + 1e-5f);
    }
}

__global__ void bn_apply_relu(int total, int C, const float* __restrict__ h,
                              const float* __restrict__ mean, const float* __restrict__ rstd,
                              const float* __restrict__ g, const float* __restrict__ beta,
                              float* out) {
    int idx = blockIdx.x * blockDim.x + threadIdx.x;
    if (idx < total) {
        int c = idx % C;
        float v = g[c] * (h[idx] - mean[c]) * rstd[c] + beta[c];
        out[idx] = fmaxf(v, 0.0f);
    }
}

// ---------------- edge gate + scatter-aggregate ----------------
__global__ void edge_gate_agg(int E, const float* __restrict__ x,
                              const float* __restrict__ esrc, const float* __restrict__ edst,
                              const float* __restrict__ ee,
                              const int* __restrict__ src, const int* __restrict__ dst,
                              const float* __restrict__ nl, float* agg) {
    int e = blockIdx.x;
    if (e >= E) return;
    int s = src[e], d = dst[e];
    float nls = nl[s];
    int c = threadIdx.x;
    float gsum = esrc[s * HD + c] + edst[d * HD + c] + ee[(long)e * HD + c];
    float sig = 1.0f / (1.0f + expf(-gsum));
    float msg = x[s * HD + c] * nls * sig;
    atomicAdd(&agg[d * HD + c], msg);
}

// ---------------- generic SGEMM: C = epilogue(A[MxK] @ B[KxN] + bias) ----------------
// EPI 0: store   EPI 1: relu   EPI 2: C += acc*norm[row] + bias  (GCN residual)
template <int EPI>
__global__ __launch_bounds__(256) void sgemm_kernel(
    int M, int N, int K,
    const float* __restrict__ A, const float* __restrict__ B,
    const float* __restrict__ bias, float* __restrict__ C,
    const float* __restrict__ norm) {
    const int BM = 128, BN = 128, BK = 8, TM = 8, TN = 8;
    __shared__ float As[BK][BM];
    __shared__ float Bs[BK][BN];
    int tid = threadIdx.x;
    int row0 = blockIdx.y * BM;
    int col0 = blockIdx.x * BN;
    int tx = tid & 15, ty = tid >> 4;

    float acc[TM][TN];
    #pragma unroll
    for (int i = 0; i < TM; i++)
        #pragma unroll
        for (int j = 0; j < TN; j++) acc[i][j] = 0.0f;

    int aRow = tid >> 1;
    int aK0 = (tid & 1) * 4;
    int bK = tid >> 5;
    int bCol0 = (tid & 31) * 4;

    for (int k0 = 0; k0 < K; k0 += BK) {
        // load A tile (BM x BK), transposed into As[k][m]
        int r = row0 + aRow;
        #pragma unroll
        for (int i = 0; i < 4; i++) {
            int k = k0 + aK0 + i;
            As[aK0 + i][aRow] = (r < M && k < K) ? A[(long)r * K + k] : 0.0f;
        }
        // load B tile (BK x BN)
        {
            int k = k0 + bK;
            #pragma unroll
            for (int i = 0; i < 4; i++) {
                int c = col0 + bCol0 + i;
                Bs[bK][bCol0 + i] = (c < N && k < K) ? B[(long)k * N + c] : 0.0f;
            }
        }
        __syncthreads();
        #pragma unroll
        for (int kk = 0; kk < BK; kk++) {
            float a[TM], b[TN];
            float4 a0 = *reinterpret_cast<const float4*>(&As[kk][ty * TM]);
            float4 a1 = *reinterpret_cast<const float4*>(&As[kk][ty * TM + 4]);
            float4 b0 = *reinterpret_cast<const float4*>(&Bs[kk][tx * TN]);
            float4 b1 = *reinterpret_cast<const float4*>(&Bs[kk][tx * TN + 4]);
            a[0]=a0.x; a[1]=a0.y; a[2]=a0.z; a[3]=a0.w; a[4]=a1.x; a[5]=a1.y; a[6]=a1.z; a[7]=a1.w;
            b[0]=b0.x; b[1]=b0.y; b[2]=b0.z; b[3]=b0.w; b[4]=b1.x; b[5]=b1.y; b[6]=b1.z; b[7]=b1.w;
            #pragma unroll
            for (int i = 0; i < TM; i++)
                #pragma unroll
                for (int j = 0; j < TN; j++) acc[i][j] += a[i] * b[j];
        }
        __syncthreads();
    }

    #pragma unroll
    for (int i = 0; i < TM; i++) {
        int r = row0 + ty * TM + i;
        if (r >= M) continue;
        float nr = (EPI == 2) ? norm[r] : 0.0f;
        #pragma unroll
        for (int j = 0; j < TN; j++) {
            int c = col0 + tx * TN + j;
            if (c >= N) continue;
            long idx = (long)r * N + c;
            if (EPI == 0) {
                C[idx] = acc[i][j] + bias[c];
            } else if (EPI == 1) {
                C[idx] = fmaxf(acc[i][j] + bias[c], 0.0f);
            } else {
                C[idx] = C[idx] + acc[i][j] * nr + bias[c];
            }
        }
    }
}

// ---------------- host-side helpers ----------------
static float* symaddr(const void* sym) {
    void* p = nullptr;
    cudaGetSymbolAddress(&p, sym);
    return (float*)p;
}

static inline void launch_gemm(int epi, int M, int N, int K,
                               const float* A, const float* B, const float* bias,
                               float* C, const float* norm) {
    dim3 grid((N + 127) / 128, (M + 127) / 128);
    if (epi == 0)      sgemm_kernel<0><<<grid, 256>>>(M, N, K, A, B, bias, C, norm);
    else if (epi == 1) sgemm_kernel<1><<<grid, 256>>>(M, N, K, A, B, bias, C, norm);
    else               sgemm_kernel<2><<<grid, 256>>>(M, N, K, A, B, bias, C, norm);
}

static inline void zero(float* p, long n) {
    fill_kernel<<<(int)((n + 255) / 256), 256>>>(p, (int)n, 0.0f);
}

static void run_bn(int M, int C, const float* h, const float* g, const float* beta, float* out,
                   float* psum, float* psumsq, float* pmean, float* prstd) {
    zero(psum, C);
    zero(psumsq, C);
    int chunks = (M > 20000) ? 128 : 32;
    dim3 grid(C / 32, chunks);
    dim3 blk(32, 8);
    bn_stats_partial<<<grid, blk>>>(M, C, h, psum, psumsq);
    bn_finalize<<<(C + 127) / 128, 128>>>(C, 1.0f / (float)M, psum, psumsq, pmean, prstd);
    long total = (long)M * C;
    bn_apply_relu<<<(int)((total + 255) / 256), 256>>>((int)total, C, h, pmean, prstd, g, beta, out);
}

extern "C" void kernel_launch(void* const* d_in, const int* in_sizes, int n_in,
                              void* d_out, int out_size) {
    const float* atom_features = (const float*)d_in[0];
    const float* r             = (const float*)d_in[1];
    const int*   src           = (const int*)d_in[2];
    const int*   dst           = (const int*)d_in[3];
    const float* ae_w   = (const float*)d_in[4];
    const float* ae_b   = (const float*)d_in[5];
    const float* ae_g   = (const float*)d_in[6];
    const float* ae_be  = (const float*)d_in[7];
    const float* ee1_w  = (const float*)d_in[8];
    const float* ee1_b  = (const float*)d_in[9];
    const float* ee1_g  = (const float*)d_in[10];
    const float* ee1_be = (const float*)d_in[11];
    const float* ee2_w  = (const float*)d_in[12];
    const float* ee2_b  = (const float*)d_in[13];
    const float* ee2_g  = (const float*)d_in[14];
    const float* ee2_be = (const float*)d_in[15];
    const float* gcn_w  = (const float*)d_in[16];
    const float* gcn_b  = (const float*)d_in[17];
    const float* sg_w   = (const float*)d_in[18];
    const float* sg_b   = (const float*)d_in[19];
    const float* dg_w   = (const float*)d_in[20];
    const float* dg_b   = (const float*)d_in[21];
    const float* eg_w   = (const float*)d_in[22];
    const float* eg_b   = (const float*)d_in[23];
    const float* fc1_w  = (const float*)d_in[24];
    const float* fc1_b  = (const float*)d_in[25];
    const float* fc2_w  = (const float*)d_in[26];
    const float* fc2_b  = (const float*)d_in[27];
    const float* fc3_w  = (const float*)d_in[28];
    const float* fc3_b  = (const float*)d_in[29];

    const int N = in_sizes[0] / 92;
    const int E = in_sizes[2];

    float* px    = symaddr(g_x);
    float* ppre  = symaddr(g_pre);
    float* pesrc = symaddr(g_esrc);
    float* pedst = symaddr(g_edst);
    float* pagg  = symaddr(g_agg);
    float* pfc1  = symaddr(g_fc1o);
    float* pfc2  = symaddr(g_fc2o);
    float* pbond = symaddr(g_bond);
    float* prbf  = symaddr(g_rbf);
    float* ph1   = symaddr(g_h1);
    float* py    = symaddr(g_y);
    float* pee   = symaddr(g_ee);
    float* pdegs = symaddr(g_degs);
    float* pdegd = symaddr(g_degd);
    float* pnl   = symaddr(g_nl);
    float* pnr   = symaddr(g_nr);
    float* psum  = symaddr(g_sum);
    float* psq   = symaddr(g_sumsq);
    float* pmean = symaddr(g_mean);
    float* prstd = symaddr(g_rstd);

    // ---- degrees & norms ----
    zero(pdegs, N); zero(pdegd, N);
    deg_kernel<<<(E + 255) / 256, 256>>>(E, src, dst, pdegs, pdegd);
    norm_kernel<<<(N + 255) / 256, 256>>>(N, pdegs, pdegd, pnl, pnr);

    // ---- atom embedding MLP ----
    launch_gemm(0, N, 256, 92, atom_features, ae_w, ae_b, ppre, nullptr);
    run_bn(N, 256, ppre, ae_g, ae_be, px, psum, psq, pmean, prstd);

    // ---- RBF + edge embedding MLPs ----
    bond_kernel<<<(E + 255) / 256, 256>>>(E, r, pbond);
    {
        long tot = (long)E * 80;
        rbf_kernel<<<(int)((tot + 255) / 256), 256>>>((int)tot, pbond, prbf);
    }
    launch_gemm(0, E, 64, 80, prbf, ee1_w, ee1_b, ph1, nullptr);
    run_bn(E, 64, ph1, ee1_g, ee1_be, ph1, psum, psq, pmean, prstd);
    launch_gemm(0, E, 256, 64, ph1, ee2_w, ee2_b, py, nullptr);
    run_bn(E, 256, py, ee2_g, ee2_be, py, psum, psq, pmean, prstd);

    // ---- 4 gated GCN layers ----
    for (int i = 0; i < 4; i++) {
        const float* sgw = sg_w + (long)i * 256 * 256;
        const float* dgw = dg_w + (long)i * 256 * 256;
        const float* egw = eg_w + (long)i * 256 * 256;
        const float* gw  = gcn_w + (long)i * 256 * 256;
        const float* sgb = sg_b + i * 256;
        const float* dgb = dg_b + i * 256;
        const float* egb = eg_b + i * 256;
        const float* gb  = gcn_b + i * 256;

        launch_gemm(0, N, 256, 256, px, sgw, sgb, pesrc, nullptr);
        launch_gemm(0, N, 256, 256, px, dgw, dgb, pedst, nullptr);
        launch_gemm(0, E, 256, 256, py, egw, egb, pee, nullptr);

        zero(pagg, (long)N * 256);
        edge_gate_agg<<<E, 256>>>(E, px, pesrc, pedst, pee, src, dst, pnl, pagg);

        launch_gemm(2, N, 256, 256, pagg, gw, gb, px, pnr);
    }

    // ---- readout MLP ----
    launch_gemm(1, N, 1024, 256, px, fc1_w, fc1_b, pfc1, nullptr);
    launch_gemm(1, N, 2048, 1024, pfc1, fc2_w, fc2_b, pfc2, nullptr);
    launch_gemm(1, N, 10000, 2048, pfc2, fc3_w, fc3_b, (float*)d_out, nullptr);
}

// round 6
// speedup vs baseline: 2.3153x; 2.3153x over previous
#include <cuda_runtime.h>
#include <cuda_bf16.h>
#include <stdint.h>
#include <math.h>

// ---------------- problem-size constants (fixed by the benchmark) ----------------
#define NMAXV 5000
#define EMAXV 160000
#define HD 256

// ---------------- fp32 scratch ----------------
__device__ float g_x   [NMAXV * 256];
__device__ float g_pre [NMAXV * 256];
__device__ float g_esrc[NMAXV * 256];
__device__ float g_edst[NMAXV * 256];
__device__ float g_agg [NMAXV * 256];
__device__ float g_fc1o[NMAXV * 1024];
__device__ float g_fc2o[NMAXV * 2048];
__device__ float g_bond[EMAXV];
__device__ float g_rbf [EMAXV * 80];
__device__ float g_h1  [EMAXV * 64];
__device__ float g_y   [EMAXV * 256];
__device__ float g_ee  [EMAXV * 256];
__device__ float g_degs[NMAXV];
__device__ float g_degd[NMAXV];
__device__ float g_nl  [NMAXV];
__device__ float g_nr  [NMAXV];
__device__ float g_sum [256];
__device__ float g_sumsq[256];
__device__ float g_mean[256];
__device__ float g_rstd[256];

// ---------------- bf16 split (hi/lo) scratch: activations ----------------
__device__ __nv_bfloat16 g_xa_hi[NMAXV * 96],    g_xa_lo[NMAXV * 96];
__device__ __nv_bfloat16 g_x_hi [NMAXV * 256],   g_x_lo [NMAXV * 256];
__device__ __nv_bfloat16 g_agg_hi[NMAXV * 256],  g_agg_lo[NMAXV * 256];
__device__ __nv_bfloat16 g_fc1_hi[NMAXV * 1024], g_fc1_lo[NMAXV * 1024];
__device__ __nv_bfloat16 g_fc2_hi[NMAXV * 2048], g_fc2_lo[NMAXV * 2048];
__device__ __nv_bfloat16 g_rbf_hi[EMAXV * 80],   g_rbf_lo[EMAXV * 80];
__device__ __nv_bfloat16 g_h1_hi [EMAXV * 64],   g_h1_lo [EMAXV * 64];
__device__ __nv_bfloat16 g_y_hi  [EMAXV * 256],  g_y_lo  [EMAXV * 256];

// ---------------- bf16 split scratch: transposed weights [N][Kpad] ----------------
__device__ __nv_bfloat16 g_aewT_hi [256 * 96],    g_aewT_lo [256 * 96];
__device__ __nv_bfloat16 g_ee1wT_hi[64 * 80],     g_ee1wT_lo[64 * 80];
__device__ __nv_bfloat16 g_ee2wT_hi[256 * 64],    g_ee2wT_lo[256 * 64];
__device__ __nv_bfloat16 g_sgwT_hi [4 * 256 * 256], g_sgwT_lo [4 * 256 * 256];
__device__ __nv_bfloat16 g_dgwT_hi [4 * 256 * 256], g_dgwT_lo [4 * 256 * 256];
__device__ __nv_bfloat16 g_egwT_hi [4 * 256 * 256], g_egwT_lo [4 * 256 * 256];
__device__ __nv_bfloat16 g_gwT_hi  [4 * 256 * 256], g_gwT_lo  [4 * 256 * 256];
__device__ __nv_bfloat16 g_fc1wT_hi[1024 * 256],  g_fc1wT_lo[1024 * 256];
__device__ __nv_bfloat16 g_fc2wT_hi[2048 * 1024], g_fc2wT_lo[2048 * 1024];
__device__ __nv_bfloat16 g_fc3wT_hi[10000 * 2048],g_fc3wT_lo[10000 * 2048];

// ---------------- small utility kernels ----------------
__global__ void fill_kernel(float* p, int n, float v) {
    int i = blockIdx.x * blockDim.x + threadIdx.x;
    if (i < n) p[i] = v;
}

__global__ void deg_kernel(int E, const int* __restrict__ src, const int* __restrict__ dst,
                           float* degs, float* degd) {
    int e = blockIdx.x * blockDim.x + threadIdx.x;
    if (e < E) {
        atomicAdd(&degs[src[e]], 1.0f);
        atomicAdd(&degd[dst[e]], 1.0f);
    }
}

__global__ void norm_kernel(int N, const float* __restrict__ degs, const float* __restrict__ degd,
                            float* nl, float* nr) {
    int i = blockIdx.x * blockDim.x + threadIdx.x;
    if (i < N) {
        nl[i] = rsqrtf(fmaxf(degs[i], 1.0f));
        nr[i] = rsqrtf(fmaxf(degd[i], 1.0f));
    }
}

__global__ void bond_kernel(int E, const float* __restrict__ r, float* bond) {
    int e = blockIdx.x * blockDim.x + threadIdx.x;
    if (e < E) {
        float a = r[e * 3 + 0], b = r[e * 3 + 1], c = r[e * 3 + 2];
        bond[e] = sqrtf(a * a + b * b + c * c);
    }
}

__global__ void rbf_kernel(int total, const float* __restrict__ bond, float* rbf) {
    int idx = blockIdx.x * blockDim.x + threadIdx.x;
    if (idx < total) {
        int e = idx / 80;
        int j = idx - e * 80;
        const float gamma = 79.0f / 8.0f;
        float cj = (8.0f / 79.0f) * (float)j;
        float d = bond[e] - cj;
        rbf[idx] = expf(-gamma * d * d);
    }
}

// split fp32 -> (hi, lo) bf16 with column padding [M x K] -> [M x Kp]
__global__ void conv_pad_kernel(const float* __restrict__ src,
                                __nv_bfloat16* __restrict__ hi, __nv_bfloat16* __restrict__ lo,
                                int M, int K, int Kp) {
    long idx = (long)blockIdx.x * blockDim.x + threadIdx.x;
    long total = (long)M * Kp;
    if (idx >= total) return;
    int r = (int)(idx / Kp);
    int c = (int)(idx - (long)r * Kp);
    float v = (c < K) ? src[(long)r * K + c] : 0.0f;
    __nv_bfloat16 h = __float2bfloat16(v);
    float res = v - __bfloat162float(h);
    hi[idx] = h;
    lo[idx] = __float2bfloat16(res);
}

// transpose + split: W[K x N] fp32 -> WT hi/lo [N x Kp] bf16
__global__ void transconv_kernel(const float* __restrict__ W,
                                 __nv_bfloat16* __restrict__ Thi, __nv_bfloat16* __restrict__ Tlo,
                                 int K, int N, int Kp) {
    __shared__ float t[32][33];
    int k0 = blockIdx.y * 32, n0 = blockIdx.x * 32;
    int tx = threadIdx.x, ty = threadIdx.y; // 32 x 8
    #pragma unroll
    for (int i = ty; i < 32; i += 8) {
        int k = k0 + i, n = n0 + tx;
        t[i][tx] = (k < K && n < N) ? W[(long)k * N + n] : 0.0f;
    }
    __syncthreads();
    #pragma unroll
    for (int i = ty; i < 32; i += 8) {
        int n = n0 + i, k = k0 + tx;
        if (n < N && k < Kp) {
            float v = t[tx][i];
            __nv_bfloat16 h = __float2bfloat16(v);
            float res = v - __bfloat162float(h);
            Thi[(long)n * Kp + k] = h;
            Tlo[(long)n * Kp + k] = __float2bfloat16(res);
        }
    }
}

// ---------------- BatchNorm (training-mode batch stats) ----------------
__global__ void bn_stats_partial(int M, int C, const float* __restrict__ h,
                                 float* sum, float* sumsq) {
    int c = blockIdx.x * 32 + threadIdx.x;
    int rowsPerChunk = (M + gridDim.y - 1) / gridDim.y;
    int r0 = blockIdx.y * rowsPerChunk;
    int r1 = min(M, r0 + rowsPerChunk);
    float s = 0.f, s2 = 0.f;
    if (c < C) {
        for (int r = r0 + threadIdx.y; r < r1; r += 8) {
            float v = h[(long)r * C + c];
            s += v; s2 += v * v;
        }
    }
    __shared__ float sh[2][8][32];
    sh[0][threadIdx.y][threadIdx.x] = s;
    sh[1][threadIdx.y][threadIdx.x] = s2;
    __syncthreads();
    if (threadIdx.y == 0 && c < C) {
        float ts = 0.f, t2 = 0.f;
        #pragma unroll
        for (int i = 0; i < 8; i++) { ts += sh[0][i][threadIdx.x]; t2 += sh[1][i][threadIdx.x]; }
        atomicAdd(&sum[c], ts);
        atomicAdd(&sumsq[c], t2);
    }
}

__global__ void bn_finalize(int C, float invM, const float* sum, const float* sumsq,
                            float* mean, float* rstd) {
    int c = blockIdx.x * blockDim.x + threadIdx.x;
    if (c < C) {
        float m = sum[c] * invM;
        float var = fmaxf(sumsq[c] * invM - m * m, 0.0f);
        mean[c] = m;
        rstd[c] = rsqrtf(var + 1e-5f);
    }
}

__global__ void bn_apply_relu(long total, int C, const float* __restrict__ h,
                              const float* __restrict__ mean, const float* __restrict__ rstd,
                              const float* __restrict__ g, const float* __restrict__ beta,
                              float* out) {
    long idx = (long)blockIdx.x * blockDim.x + threadIdx.x;
    if (idx < total) {
        int c = (int)(idx % C);
        float v = g[c] * (h[idx] - mean[c]) * rstd[c] + beta[c];
        out[idx] = fmaxf(v, 0.0f);
    }
}

// ---------------- edge gate + scatter-aggregate ----------------
__global__ void edge_gate_agg(int E, const float* __restrict__ x,
                              const float* __restrict__ esrc, const float* __restrict__ edst,
                              const float* __restrict__ ee,
                              const int* __restrict__ src, const int* __restrict__ dst,
                              const float* __restrict__ nl, float* agg) {
    int e = blockIdx.x;
    if (e >= E) return;
    int s = src[e], d = dst[e];
    float nls = nl[s];
    int c = threadIdx.x;
    float gsum = esrc[s * HD + c] + edst[d * HD + c] + ee[(long)e * HD + c];
    float sig = 1.0f / (1.0f + expf(-gsum));
    float msg = x[s * HD + c] * nls * sig;
    atomicAdd(&agg[d * HD + c], msg);
}

// ---------------- split-bf16 tensor-core GEMM ----------------
// C[M x N] = epilogue( A[M x K] @ B[K x N] + bias )
// A given as hi/lo bf16 [M x K] row-major, B given TRANSPOSED as hi/lo bf16 [N x K].
// K must be a multiple of 16 (pre-padded with zeros).
// EPI 0: store  EPI 1: relu  EPI 2: C += acc*norm[row] + bias (GCN residual)

__device__ __forceinline__ void cp16(uint32_t saddr, const void* gaddr, bool valid) {
    int sz = valid ? 16 : 0;
    asm volatile("cp.async.cg.shared.global [%0], [%1], 16, %2;\n"
                 :: "r"(saddr), "l"(gaddr), "r"(sz));
}

#define LDSM4(R0, R1, R2, R3, addr) \
    asm volatile("ldmatrix.sync.aligned.m8n8.x4.shared.b16 {%0,%1,%2,%3}, [%4];" \
                 : "=r"(R0), "=r"(R1), "=r"(R2), "=r"(R3) : "r"(addr))
#define LDSM2(R0, R1, addr) \
    asm volatile("ldmatrix.sync.aligned.m8n8.x2.shared.b16 {%0,%1}, [%2];" \
                 : "=r"(R0), "=r"(R1) : "r"(addr))

#define MMA16816(d, a, b) \
    asm volatile("mma.sync.aligned.m16n8k16.row.col.f32.bf16.bf16.f32 " \
                 "{%0,%1,%2,%3}, {%4,%5,%6,%7}, {%8,%9}, {%0,%1,%2,%3};" \
                 : "+f"((d)[0]), "+f"((d)[1]), "+f"((d)[2]), "+f"((d)[3]) \
                 : "r"((a)[0]), "r"((a)[1]), "r"((a)[2]), "r"((a)[3]), \
                   "r"((b)[0]), "r"((b)[1]))

template <int EPI>
__global__ __launch_bounds__(256) void mma_gemm(
    int M, int N, int K,
    const __nv_bfloat16* __restrict__ Ahi, const __nv_bfloat16* __restrict__ Alo,
    const __nv_bfloat16* __restrict__ Bhi, const __nv_bfloat16* __restrict__ Blo,
    const float* __restrict__ bias, float* __restrict__ C,
    const float* __restrict__ norm) {
    // padded smem tiles: row stride 24 bf16 = 48B (conflict-free for ldmatrix)
    __shared__ __nv_bfloat16 sA[2][2][128][24];
    __shared__ __nv_bfloat16 sB[2][2][128][24];

    const int tid = threadIdx.x;
    const int m0 = blockIdx.y * 128;
    const int n0 = blockIdx.x * 128;
    const int wid = tid >> 5, lane = tid & 31;
    const int wm = (wid & 1) * 64;       // warp m offset within block
    const int wn = (wid >> 1) * 32;      // warp n offset within block

    float acc[4][4][4];
    #pragma unroll
    for (int i = 0; i < 4; i++)
        #pragma unroll
        for (int j = 0; j < 4; j++)
            #pragma unroll
            for (int q = 0; q < 4; q++) acc[i][j][q] = 0.0f;

    const int nk = K / 16;

    // async tile load: 1024 16B chunks per stage, 4 per thread
    auto load_stage = [&](int s, int k0) {
        #pragma unroll
        for (int it = 0; it < 4; it++) {
            int t = tid + it * 256;
            int half = t >> 8;            // 0:Ahi 1:Alo 2:Bhi 3:Blo
            int f = t & 255;
            int row = f >> 1;
            int cc = (f & 1) * 8;
            if (half < 2) {
                bool v = (m0 + row) < M;
                int rr = v ? (m0 + row) : 0;
                const __nv_bfloat16* g = (half == 0 ? Ahi : Alo) + (size_t)rr * K + k0 + cc;
                uint32_t sa = (uint32_t)__cvta_generic_to_shared(&sA[s][half][row][cc]);
                cp16(sa, g, v);
            } else {
                bool v = (n0 + row) < N;
                int rr = v ? (n0 + row) : 0;
                const __nv_bfloat16* g = (half == 2 ? Bhi : Blo) + (size_t)rr * K + k0 + cc;
                uint32_t sa = (uint32_t)__cvta_generic_to_shared(&sB[s][half - 2][row][cc]);
                cp16(sa, g, v);
            }
        }
        asm volatile("cp.async.commit_group;\n");
    };

    load_stage(0, 0);

    for (int kt = 0; kt < nk; kt++) {
        int cur = kt & 1;
        if (kt + 1 < nk) {
            load_stage((kt + 1) & 1, (kt + 1) * 16);
            asm volatile("cp.async.wait_group 1;\n");
        } else {
            asm volatile("cp.async.wait_group 0;\n");
        }
        __syncthreads();

        // ---- load fragments ----
        uint32_t afh[4][4], afl[4][4];
        #pragma unroll
        for (int mi = 0; mi < 4; mi++) {
            int row = wm + mi * 16 + (lane & 15);
            int col = ((lane >> 4) & 1) * 8;
            uint32_t ah = (uint32_t)__cvta_generic_to_shared(&sA[cur][0][row][col]);
            uint32_t al = (uint32_t)__cvta_generic_to_shared(&sA[cur][1][row][col]);
            LDSM4(afh[mi][0], afh[mi][1], afh[mi][2], afh[mi][3], ah);
            LDSM4(afl[mi][0], afl[mi][1], afl[mi][2], afl[mi][3], al);
        }
        uint32_t bfh[4][2], bfl[4][2];
        #pragma unroll
        for (int ni = 0; ni < 4; ni++) {
            int l = lane & 15;
            int row = wn + ni * 8 + (l & 7);
            int col = (l >> 3) * 8;
            uint32_t bh = (uint32_t)__cvta_generic_to_shared(&sB[cur][0][row][col]);
            uint32_t bl = (uint32_t)__cvta_generic_to_shared(&sB[cur][1][row][col]);
            LDSM2(bfh[ni][0], bfh[ni][1], bh);
            LDSM2(bfl[ni][0], bfl[ni][1], bl);
        }
        // ---- 3-product split MMA ----
        #pragma unroll
        for (int mi = 0; mi < 4; mi++)
            #pragma unroll
            for (int ni = 0; ni < 4; ni++) {
                MMA16816(acc[mi][ni], afh[mi], bfh[ni]);
                MMA16816(acc[mi][ni], afh[mi], bfl[ni]);
                MMA16816(acc[mi][ni], afl[mi], bfh[ni]);
            }
        __syncthreads();
    }

    // ---- epilogue ----
    #pragma unroll
    for (int mi = 0; mi < 4; mi++) {
        #pragma unroll
        for (int half = 0; half < 2; half++) {
            int r = m0 + wm + mi * 16 + (lane >> 2) + half * 8;
            if (r >= M) continue;
            float nr = (EPI == 2) ? norm[r] : 0.0f;
            #pragma unroll
            for (int ni = 0; ni < 4; ni++) {
                int c = n0 + wn + ni * 8 + (lane & 3) * 2;
                if (c >= N) continue;
                long idx = (long)r * N + c;
                float v0 = acc[mi][ni][half * 2 + 0];
                float v1 = acc[mi][ni][half * 2 + 1];
                float b0 = bias[c], b1 = bias[c + 1];
                if (EPI == 0) {
                    C[idx] = v0 + b0; C[idx + 1] = v1 + b1;
                } else if (EPI == 1) {
                    C[idx] = fmaxf(v0 + b0, 0.0f); C[idx + 1] = fmaxf(v1 + b1, 0.0f);
                } else {
                    C[idx]     = C[idx]     + v0 * nr + b0;
                    C[idx + 1] = C[idx + 1] + v1 * nr + b1;
                }
            }
        }
    }
}

// ---------------- host-side helpers ----------------
static float* symaddr(const void* sym) {
    void* p = nullptr;
    cudaGetSymbolAddress(&p, sym);
    return (float*)p;
}
static __nv_bfloat16* symaddr_bf(const void* sym) {
    void* p = nullptr;
    cudaGetSymbolAddress(&p, sym);
    return (__nv_bfloat16*)p;
}

static inline void launch_mma(int epi, int M, int N, int K,
                              const __nv_bfloat16* Ahi, const __nv_bfloat16* Alo,
                              const __nv_bfloat16* Bhi, const __nv_bfloat16* Blo,
                              const float* bias, float* C, const float* norm) {
    dim3 grid((N + 127) / 128, (M + 127) / 128);
    if (epi == 0)      mma_gemm<0><<<grid, 256>>>(M, N, K, Ahi, Alo, Bhi, Blo, bias, C, norm);
    else if (epi == 1) mma_gemm<1><<<grid, 256>>>(M, N, K, Ahi, Alo, Bhi, Blo, bias, C, norm);
    else               mma_gemm<2><<<grid, 256>>>(M, N, K, Ahi, Alo, Bhi, Blo, bias, C, norm);
}

static inline void zero(float* p, long n) {
    fill_kernel<<<(int)((n + 255) / 256), 256>>>(p, (int)n, 0.0f);
}

static inline void conv_pad(const float* src, __nv_bfloat16* hi, __nv_bfloat16* lo,
                            int M, int K, int Kp) {
    long total = (long)M * Kp;
    conv_pad_kernel<<<(int)((total + 255) / 256), 256>>>(src, hi, lo, M, K, Kp);
}

static inline void transconv(const float* W, __nv_bfloat16* Thi, __nv_bfloat16* Tlo,
                             int K, int N, int Kp) {
    dim3 grid((N + 31) / 32, (Kp + 31) / 32);
    transconv_kernel<<<grid, dim3(32, 8)>>>(W, Thi, Tlo, K, N, Kp);
}

static void run_bn(int M, int C, const float* h, const float* g, const float* beta, float* out,
                   float* psum, float* psumsq, float* pmean, float* prstd) {
    zero(psum, C);
    zero(psumsq, C);
    int chunks = (M > 20000) ? 128 : 32;
    dim3 grid(C / 32, chunks);
    dim3 blk(32, 8);
    bn_stats_partial<<<grid, blk>>>(M, C, h, psum, psumsq);
    bn_finalize<<<(C + 127) / 128, 128>>>(C, 1.0f / (float)M, psum, psumsq, pmean, prstd);
    long total = (long)M * C;
    bn_apply_relu<<<(int)((total + 255) / 256), 256>>>(total, C, h, pmean, prstd, g, beta, out);
}

extern "C" void kernel_launch(void* const* d_in, const int* in_sizes, int n_in,
                              void* d_out, int out_size) {
    const float* atom_features = (const float*)d_in[0];
    const float* r             = (const float*)d_in[1];
    const int*   src           = (const int*)d_in[2];
    const int*   dst           = (const int*)d_in[3];
    const float* ae_w   = (const float*)d_in[4];
    const float* ae_b   = (const float*)d_in[5];
    const float* ae_g   = (const float*)d_in[6];
    const float* ae_be  = (const float*)d_in[7];
    const float* ee1_w  = (const float*)d_in[8];
    const float* ee1_b  = (const float*)d_in[9];
    const float* ee1_g  = (const float*)d_in[10];
    const float* ee1_be = (const float*)d_in[11];
    const float* ee2_w  = (const float*)d_in[12];
    const float* ee2_b  = (const float*)d_in[13];
    const float* ee2_g  = (const float*)d_in[14];
    const float* ee2_be = (const float*)d_in[15];
    const float* gcn_w  = (const float*)d_in[16];
    const float* gcn_b  = (const float*)d_in[17];
    const float* sg_w   = (const float*)d_in[18];
    const float* sg_b   = (const float*)d_in[19];
    const float* dg_w   = (const float*)d_in[20];
    const float* dg_b   = (const float*)d_in[21];
    const float* eg_w   = (const float*)d_in[22];
    const float* eg_b   = (const float*)d_in[23];
    const float* fc1_w  = (const float*)d_in[24];
    const float* fc1_b  = (const float*)d_in[25];
    const float* fc2_w  = (const float*)d_in[26];
    const float* fc2_b  = (const float*)d_in[27];
    const float* fc3_w  = (const float*)d_in[28];
    const float* fc3_b  = (const float*)d_in[29];

    const int N = in_sizes[0] / 92;
    const int E = in_sizes[2];

    float* px    = symaddr(g_x);
    float* ppre  = symaddr(g_pre);
    float* pesrc = symaddr(g_esrc);
    float* pedst = symaddr(g_edst);
    float* pagg  = symaddr(g_agg);
    float* pfc1  = symaddr(g_fc1o);
    float* pfc2  = symaddr(g_fc2o);
    float* pbond = symaddr(g_bond);
    float* prbf  = symaddr(g_rbf);
    float* ph1   = symaddr(g_h1);
    float* py    = symaddr(g_y);
    float* pee   = symaddr(g_ee);
    float* pdegs = symaddr(g_degs);
    float* pdegd = symaddr(g_degd);
    float* pnl   = symaddr(g_nl);
    float* pnr   = symaddr(g_nr);
    float* psum  = symaddr(g_sum);
    float* psq   = symaddr(g_sumsq);
    float* pmean = symaddr(g_mean);
    float* prstd = symaddr(g_rstd);

    __nv_bfloat16 *xa_h = symaddr_bf(g_xa_hi),  *xa_l = symaddr_bf(g_xa_lo);
    __nv_bfloat16 *x_h  = symaddr_bf(g_x_hi),   *x_l  = symaddr_bf(g_x_lo);
    __nv_bfloat16 *ag_h = symaddr_bf(g_agg_hi), *ag_l = symaddr_bf(g_agg_lo);
    __nv_bfloat16 *f1_h = symaddr_bf(g_fc1_hi), *f1_l = symaddr_bf(g_fc1_lo);
    __nv_bfloat16 *f2_h = symaddr_bf(g_fc2_hi), *f2_l = symaddr_bf(g_fc2_lo);
    __nv_bfloat16 *rb_h = symaddr_bf(g_rbf_hi), *rb_l = symaddr_bf(g_rbf_lo);
    __nv_bfloat16 *h1_h = symaddr_bf(g_h1_hi),  *h1_l = symaddr_bf(g_h1_lo);
    __nv_bfloat16 *y_h  = symaddr_bf(g_y_hi),   *y_l  = symaddr_bf(g_y_lo);

    __nv_bfloat16 *aew_h = symaddr_bf(g_aewT_hi),  *aew_l = symaddr_bf(g_aewT_lo);
    __nv_bfloat16 *e1w_h = symaddr_bf(g_ee1wT_hi), *e1w_l = symaddr_bf(g_ee1wT_lo);
    __nv_bfloat16 *e2w_h = symaddr_bf(g_ee2wT_hi), *e2w_l = symaddr_bf(g_ee2wT_lo);
    __nv_bfloat16 *sgw_h = symaddr_bf(g_sgwT_hi),  *sgw_l = symaddr_bf(g_sgwT_lo);
    __nv_bfloat16 *dgw_h = symaddr_bf(g_dgwT_hi),  *dgw_l = symaddr_bf(g_dgwT_lo);
    __nv_bfloat16 *egw_h = symaddr_bf(g_egwT_hi),  *egw_l = symaddr_bf(g_egwT_lo);
    __nv_bfloat16 *gw_h  = symaddr_bf(g_gwT_hi),   *gw_l  = symaddr_bf(g_gwT_lo);
    __nv_bfloat16 *f1w_h = symaddr_bf(g_fc1wT_hi), *f1w_l = symaddr_bf(g_fc1wT_lo);
    __nv_bfloat16 *f2w_h = symaddr_bf(g_fc2wT_hi), *f2w_l = symaddr_bf(g_fc2wT_lo);
    __nv_bfloat16 *f3w_h = symaddr_bf(g_fc3wT_hi), *f3w_l = symaddr_bf(g_fc3wT_lo);

    // ---- weight transpose + split (per launch; cheap) ----
    transconv(ae_w, aew_h, aew_l, 92, 256, 96);
    transconv(ee1_w, e1w_h, e1w_l, 80, 64, 80);
    transconv(ee2_w, e2w_h, e2w_l, 64, 256, 64);
    for (int i = 0; i < 4; i++) {
        long wo = (long)i * 256 * 256;
        transconv(sg_w + wo, sgw_h + wo, sgw_l + wo, 256, 256, 256);
        transconv(dg_w + wo, dgw_h + wo, dgw_l + wo, 256, 256, 256);
        transconv(eg_w + wo, egw_h + wo, egw_l + wo, 256, 256, 256);
        transconv(gcn_w + wo, gw_h + wo, gw_l + wo, 256, 256, 256);
    }
    transconv(fc1_w, f1w_h, f1w_l, 256, 1024, 256);
    transconv(fc2_w, f2w_h, f2w_l, 1024, 2048, 1024);
    transconv(fc3_w, f3w_h, f3w_l, 2048, 10000, 2048);

    // ---- degrees & norms ----
    zero(pdegs, N); zero(pdegd, N);
    deg_kernel<<<(E + 255) / 256, 256>>>(E, src, dst, pdegs, pdegd);
    norm_kernel<<<(N + 255) / 256, 256>>>(N, pdegs, pdegd, pnl, pnr);

    // ---- atom embedding MLP ----
    conv_pad(atom_features, xa_h, xa_l, N, 92, 96);
    launch_mma(0, N, 256, 96, xa_h, xa_l, aew_h, aew_l, ae_b, ppre, nullptr);
    run_bn(N, 256, ppre, ae_g, ae_be, px, psum, psq, pmean, prstd);
    conv_pad(px, x_h, x_l, N, 256, 256);

    // ---- RBF + edge embedding MLPs ----
    bond_kernel<<<(E + 255) / 256, 256>>>(E, r, pbond);
    {
        long tot = (long)E * 80;
        rbf_kernel<<<(int)((tot + 255) / 256), 256>>>((int)tot, pbond, prbf);
    }
    conv_pad(prbf, rb_h, rb_l, E, 80, 80);
    launch_mma(0, E, 64, 80, rb_h, rb_l, e1w_h, e1w_l, ee1_b, ph1, nullptr);
    run_bn(E, 64, ph1, ee1_g, ee1_be, ph1, psum, psq, pmean, prstd);
    conv_pad(ph1, h1_h, h1_l, E, 64, 64);
    launch_mma(0, E, 256, 64, h1_h, h1_l, e2w_h, e2w_l, ee2_b, py, nullptr);
    run_bn(E, 256, py, ee2_g, ee2_be, py, psum, psq, pmean, prstd);
    conv_pad(py, y_h, y_l, E, 256, 256);

    // ---- 4 gated GCN layers ----
    for (int i = 0; i < 4; i++) {
        long wo = (long)i * 256 * 256;
        const float* sgb = sg_b + i * 256;
        const float* dgb = dg_b + i * 256;
        const float* egb = eg_b + i * 256;
        const float* gb  = gcn_b + i * 256;

        launch_mma(0, N, 256, 256, x_h, x_l, sgw_h + wo, sgw_l + wo, sgb, pesrc, nullptr);
        launch_mma(0, N, 256, 256, x_h, x_l, dgw_h + wo, dgw_l + wo, dgb, pedst, nullptr);
        launch_mma(0, E, 256, 256, y_h, y_l, egw_h + wo, egw_l + wo, egb, pee, nullptr);

        zero(pagg, (long)N * 256);
        edge_gate_agg<<<E, 256>>>(E, px, pesrc, pedst, pee, src, dst, pnl, pagg);
        conv_pad(pagg, ag_h, ag_l, N, 256, 256);

        launch_mma(2, N, 256, 256, ag_h, ag_l, gw_h + wo, gw_l + wo, gb, px, pnr);
        conv_pad(px, x_h, x_l, N, 256, 256);
    }

    // ---- readout MLP ----
    launch_mma(1, N, 1024, 256, x_h, x_l, f1w_h, f1w_l, fc1_b, pfc1, nullptr);
    conv_pad(pfc1, f1_h, f1_l, N, 1024, 1024);
    launch_mma(1, N, 2048, 1024, f1_h, f1_l, f2w_h, f2w_l, fc2_b, pfc2, nullptr);
    conv_pad(pfc2, f2_h, f2_l, N, 2048, 2048);
    launch_mma(1, N, 10000, 2048, f2_h, f2_l, f3w_h, f3w_l, fc3_b, (float*)d_out, nullptr);
}

// round 7
// speedup vs baseline: 3.1806x; 1.3737x over previous
#include <cuda_runtime.h>
#include <cuda_bf16.h>
#include <stdint.h>
#include <math.h>

// ---------------- problem-size constants (fixed by the benchmark) ----------------
#define NMAXV 5000
#define EMAXV 160000
#define HD 256

// ---------------- fp32 scratch ----------------
__device__ float g_x   [NMAXV * 256];
__device__ float g_pre [NMAXV * 256];
__device__ float g_esrc[NMAXV * 256];
__device__ float g_edst[NMAXV * 256];
__device__ float g_agg [NMAXV * 256];
__device__ float g_bond[EMAXV];
__device__ float g_h1  [EMAXV * 64];
__device__ float g_y   [EMAXV * 256];
__device__ float g_ee  [EMAXV * 256];
__device__ float g_degs[NMAXV];
__device__ float g_degd[NMAXV];
__device__ float g_nl  [NMAXV];
__device__ float g_nr  [NMAXV];
__device__ float g_sum [256];
__device__ float g_sumsq[256];
__device__ float g_mean[256];
__device__ float g_rstd[256];

// ---------------- bf16 split (hi/lo) scratch: activations ----------------
__device__ __nv_bfloat16 g_xa_hi[NMAXV * 96],    g_xa_lo[NMAXV * 96];
__device__ __nv_bfloat16 g_x_hi [NMAXV * 256],   g_x_lo [NMAXV * 256];
__device__ __nv_bfloat16 g_agg_hi[NMAXV * 256],  g_agg_lo[NMAXV * 256];
__device__ __nv_bfloat16 g_fc1_hi[NMAXV * 1024], g_fc1_lo[NMAXV * 1024];
__device__ __nv_bfloat16 g_fc2_hi[NMAXV * 2048], g_fc2_lo[NMAXV * 2048];
__device__ __nv_bfloat16 g_rbf_hi[EMAXV * 80],   g_rbf_lo[EMAXV * 80];
__device__ __nv_bfloat16 g_h1_hi [EMAXV * 64],   g_h1_lo [EMAXV * 64];
__device__ __nv_bfloat16 g_y_hi  [EMAXV * 256],  g_y_lo  [EMAXV * 256];

// ---------------- bf16 split scratch: transposed weights [N][Kpad] ----------------
__device__ __nv_bfloat16 g_aewT_hi [256 * 96],    g_aewT_lo [256 * 96];
__device__ __nv_bfloat16 g_ee1wT_hi[64 * 80],     g_ee1wT_lo[64 * 80];
__device__ __nv_bfloat16 g_ee2wT_hi[256 * 64],    g_ee2wT_lo[256 * 64];
__device__ __nv_bfloat16 g_sgwT_hi [4 * 256 * 256], g_sgwT_lo [4 * 256 * 256];
__device__ __nv_bfloat16 g_dgwT_hi [4 * 256 * 256], g_dgwT_lo [4 * 256 * 256];
__device__ __nv_bfloat16 g_egwT_hi [4 * 256 * 256], g_egwT_lo [4 * 256 * 256];
__device__ __nv_bfloat16 g_gwT_hi  [4 * 256 * 256], g_gwT_lo  [4 * 256 * 256];
__device__ __nv_bfloat16 g_fc1wT_hi[1024 * 256],  g_fc1wT_lo[1024 * 256];
__device__ __nv_bfloat16 g_fc2wT_hi[2048 * 1024], g_fc2wT_lo[2048 * 1024];
__device__ __nv_bfloat16 g_fc3wT_hi[10000 * 2048],g_fc3wT_lo[10000 * 2048];

// ---------------- small utility kernels ----------------
__global__ void fill_kernel(float* p, int n, float v) {
    int i = blockIdx.x * blockDim.x + threadIdx.x;
    if (i < n) p[i] = v;
}

__global__ void deg_kernel(int E, const int* __restrict__ src, const int* __restrict__ dst,
                           float* degs, float* degd) {
    int e = blockIdx.x * blockDim.x + threadIdx.x;
    if (e < E) {
        atomicAdd(&degs[src[e]], 1.0f);
        atomicAdd(&degd[dst[e]], 1.0f);
    }
}

__global__ void norm_kernel(int N, const float* __restrict__ degs, const float* __restrict__ degd,
                            float* nl, float* nr) {
    int i = blockIdx.x * blockDim.x + threadIdx.x;
    if (i < N) {
        nl[i] = rsqrtf(fmaxf(degs[i], 1.0f));
        nr[i] = rsqrtf(fmaxf(degd[i], 1.0f));
    }
}

__global__ void bond_kernel(int E, const float* __restrict__ r, float* bond) {
    int e = blockIdx.x * blockDim.x + threadIdx.x;
    if (e < E) {
        float a = r[e * 3 + 0], b = r[e * 3 + 1], c = r[e * 3 + 2];
        bond[e] = sqrtf(a * a + b * b + c * c);
    }
}

// RBF with fused hi/lo split output (fp32 rbf never materialized)
__global__ void rbf_split_kernel(int total, const float* __restrict__ bond,
                                 __nv_bfloat16* __restrict__ hi, __nv_bfloat16* __restrict__ lo) {
    int idx = blockIdx.x * blockDim.x + threadIdx.x;
    if (idx < total) {
        int e = idx / 80;
        int j = idx - e * 80;
        const float gamma = 79.0f / 8.0f;
        float cj = (8.0f / 79.0f) * (float)j;
        float d = bond[e] - cj;
        float v = expf(-gamma * d * d);
        __nv_bfloat16 h = __float2bfloat16(v);
        hi[idx] = h;
        lo[idx] = __float2bfloat16(v - __bfloat162float(h));
    }
}

// split fp32 -> (hi, lo) bf16 with column padding [M x K] -> [M x Kp]
__global__ void conv_pad_kernel(const float* __restrict__ src,
                                __nv_bfloat16* __restrict__ hi, __nv_bfloat16* __restrict__ lo,
                                int M, int K, int Kp) {
    long idx = (long)blockIdx.x * blockDim.x + threadIdx.x;
    long total = (long)M * Kp;
    if (idx >= total) return;
    int r = (int)(idx / Kp);
    int c = (int)(idx - (long)r * Kp);
    float v = (c < K) ? src[(long)r * K + c] : 0.0f;
    __nv_bfloat16 h = __float2bfloat16(v);
    hi[idx] = h;
    lo[idx] = __float2bfloat16(v - __bfloat162float(h));
}

// transpose + split: W[K x N] fp32 -> WT hi/lo [N x Kp] bf16
__global__ void transconv_kernel(const float* __restrict__ W,
                                 __nv_bfloat16* __restrict__ Thi, __nv_bfloat16* __restrict__ Tlo,
                                 int K, int N, int Kp) {
    __shared__ float t[32][33];
    int k0 = blockIdx.y * 32, n0 = blockIdx.x * 32;
    int tx = threadIdx.x, ty = threadIdx.y; // 32 x 8
    #pragma unroll
    for (int i = ty; i < 32; i += 8) {
        int k = k0 + i, n = n0 + tx;
        t[i][tx] = (k < K && n < N) ? W[(long)k * N + n] : 0.0f;
    }
    __syncthreads();
    #pragma unroll
    for (int i = ty; i < 32; i += 8) {
        int n = n0 + i, k = k0 + tx;
        if (n < N && k < Kp) {
            float v = t[tx][i];
            __nv_bfloat16 h = __float2bfloat16(v);
            Thi[(long)n * Kp + k] = h;
            Tlo[(long)n * Kp + k] = __float2bfloat16(v - __bfloat162float(h));
        }
    }
}

// ---------------- BatchNorm (training-mode batch stats) ----------------
__global__ void bn_stats_partial(int M, int C, const float* __restrict__ h,
                                 float* sum, float* sumsq) {
    int c = blockIdx.x * 32 + threadIdx.x;
    int rowsPerChunk = (M + gridDim.y - 1) / gridDim.y;
    int r0 = blockIdx.y * rowsPerChunk;
    int r1 = min(M, r0 + rowsPerChunk);
    float s = 0.f, s2 = 0.f;
    if (c < C) {
        for (int r = r0 + threadIdx.y; r < r1; r += 8) {
            float v = h[(long)r * C + c];
            s += v; s2 += v * v;
        }
    }
    __shared__ float sh[2][8][32];
    sh[0][threadIdx.y][threadIdx.x] = s;
    sh[1][threadIdx.y][threadIdx.x] = s2;
    __syncthreads();
    if (threadIdx.y == 0 && c < C) {
        float ts = 0.f, t2 = 0.f;
        #pragma unroll
        for (int i = 0; i < 8; i++) { ts += sh[0][i][threadIdx.x]; t2 += sh[1][i][threadIdx.x]; }
        atomicAdd(&sum[c], ts);
        atomicAdd(&sumsq[c], t2);
    }
}

__global__ void bn_finalize(int C, float invM, const float* sum, const float* sumsq,
                            float* mean, float* rstd) {
    int c = blockIdx.x * blockDim.x + threadIdx.x;
    if (c < C) {
        float m = sum[c] * invM;
        float var = fmaxf(sumsq[c] * invM - m * m, 0.0f);
        mean[c] = m;
        rstd[c] = rsqrtf(var + 1e-5f);
    }
}

// BN apply + ReLU + fused split. outf may be null (skip fp32 write).
__global__ void bn_apply_relu_split(long total, int C, const float* __restrict__ h,
                                    const float* __restrict__ mean, const float* __restrict__ rstd,
                                    const float* __restrict__ g, const float* __restrict__ beta,
                                    float* outf,
                                    __nv_bfloat16* __restrict__ ohi, __nv_bfloat16* __restrict__ olo) {
    long idx = (long)blockIdx.x * blockDim.x + threadIdx.x;
    if (idx < total) {
        int c = (int)(idx % C);
        float v = g[c] * (h[idx] - mean[c]) * rstd[c] + beta[c];
        v = fmaxf(v, 0.0f);
        if (outf) outf[idx] = v;
        __nv_bfloat16 hb = __float2bfloat16(v);
        ohi[idx] = hb;
        olo[idx] = __float2bfloat16(v - __bfloat162float(hb));
    }
}

// ---------------- edge gate + scatter-aggregate (float4, 4 edges/block) ----------------
__global__ void edge_gate_agg(int E, const float* __restrict__ x,
                              const float* __restrict__ esrc, const float* __restrict__ edst,
                              const float* __restrict__ ee,
                              const int* __restrict__ src, const int* __restrict__ dst,
                              const float* __restrict__ nl, float* agg) {
    int e = blockIdx.x * 4 + (threadIdx.x >> 6);
    if (e >= E) return;
    int j = (threadIdx.x & 63) * 4;
    int s = src[e], d = dst[e];
    float nls = nl[s];
    float4 es = *(const float4*)&esrc[s * HD + j];
    float4 ed = *(const float4*)&edst[d * HD + j];
    float4 ev = *(const float4*)&ee[(long)e * HD + j];
    float4 xv = *(const float4*)&x[s * HD + j];
    float m0 = xv.x * nls / (1.0f + expf(-(es.x + ed.x + ev.x)));
    float m1 = xv.y * nls / (1.0f + expf(-(es.y + ed.y + ev.y)));
    float m2 = xv.z * nls / (1.0f + expf(-(es.z + ed.z + ev.z)));
    float m3 = xv.w * nls / (1.0f + expf(-(es.w + ed.w + ev.w)));
    float* a = &agg[d * HD + j];
    atomicAdd(a + 0, m0);
    atomicAdd(a + 1, m1);
    atomicAdd(a + 2, m2);
    atomicAdd(a + 3, m3);
}

// ---------------- split-bf16 tensor-core GEMM (3-stage cp.async pipeline) --------
// C[M x N] = epilogue( A[M x K] @ B[K x N] + bias )
// A hi/lo bf16 [M x K] row-major, B TRANSPOSED hi/lo bf16 [N x K]. K multiple of 16.
// EPI 0: C = acc+bias
// EPI 1: relu(acc+bias)   (if SPLIT: write only hi/lo; no fp32)
// EPI 2: C += acc*norm[row] + bias  (residual; if SPLIT also write hi/lo)

__device__ __forceinline__ void cp16(uint32_t saddr, const void* gaddr, bool valid) {
    int sz = valid ? 16 : 0;
    asm volatile("cp.async.cg.shared.global [%0], [%1], 16, %2;\n"
                 :: "r"(saddr), "l"(gaddr), "r"(sz));
}

#define LDSM4(R0, R1, R2, R3, addr) \
    asm volatile("ldmatrix.sync.aligned.m8n8.x4.shared.b16 {%0,%1,%2,%3}, [%4];" \
                 : "=r"(R0), "=r"(R1), "=r"(R2), "=r"(R3) : "r"(addr))
#define LDSM2(R0, R1, addr) \
    asm volatile("ldmatrix.sync.aligned.m8n8.x2.shared.b16 {%0,%1}, [%2];" \
                 : "=r"(R0), "=r"(R1) : "r"(addr))

#define MMA16816(d, a, b) \
    asm volatile("mma.sync.aligned.m16n8k16.row.col.f32.bf16.bf16.f32 " \
                 "{%0,%1,%2,%3}, {%4,%5,%6,%7}, {%8,%9}, {%0,%1,%2,%3};" \
                 : "+f"((d)[0]), "+f"((d)[1]), "+f"((d)[2]), "+f"((d)[3]) \
                 : "r"((a)[0]), "r"((a)[1]), "r"((a)[2]), "r"((a)[3]), \
                   "r"((b)[0]), "r"((b)[1]))

#define GEMM_SMEM_ELEMS (3 * 2 * 128 * 24)
#define GEMM_SMEM_BYTES (2 * GEMM_SMEM_ELEMS * 2)

template <int EPI, int SPLIT>
__global__ __launch_bounds__(256, 2) void mma_gemm(
    int M, int N, int K,
    const __nv_bfloat16* __restrict__ Ahi, const __nv_bfloat16* __restrict__ Alo,
    const __nv_bfloat16* __restrict__ Bhi, const __nv_bfloat16* __restrict__ Blo,
    const float* __restrict__ bias, float* __restrict__ C,
    const float* __restrict__ norm,
    __nv_bfloat16* __restrict__ Ohi, __nv_bfloat16* __restrict__ Olo) {
    extern __shared__ __nv_bfloat16 dsm[];
    // sA[3][2][128][24], sB[3][2][128][24]
    __nv_bfloat16 (*sA)[2][128][24] = reinterpret_cast<__nv_bfloat16 (*)[2][128][24]>(dsm);
    __nv_bfloat16 (*sB)[2][128][24] = reinterpret_cast<__nv_bfloat16 (*)[2][128][24]>(dsm + GEMM_SMEM_ELEMS);

    const int tid = threadIdx.x;
    const int m0 = blockIdx.y * 128;
    const int n0 = blockIdx.x * 128;
    const int wid = tid >> 5, lane = tid & 31;
    const int wm = (wid & 1) * 64;
    const int wn = (wid >> 1) * 32;

    float acc[4][4][4];
    #pragma unroll
    for (int i = 0; i < 4; i++)
        #pragma unroll
        for (int j = 0; j < 4; j++)
            #pragma unroll
            for (int q = 0; q < 4; q++) acc[i][j][q] = 0.0f;

    const int nk = K / 16;

    auto load_stage = [&](int s, int k0) {
        #pragma unroll
        for (int it = 0; it < 4; it++) {
            int t = tid + it * 256;
            int half = t >> 8;            // 0:Ahi 1:Alo 2:Bhi 3:Blo
            int f = t & 255;
            int row = f >> 1;
            int cc = (f & 1) * 8;
            if (half < 2) {
                bool v = (m0 + row) < M;
                int rr = v ? (m0 + row) : 0;
                const __nv_bfloat16* g = (half == 0 ? Ahi : Alo) + (size_t)rr * K + k0 + cc;
                uint32_t sa = (uint32_t)__cvta_generic_to_shared(&sA[s][half][row][cc]);
                cp16(sa, g, v);
            } else {
                bool v = (n0 + row) < N;
                int rr = v ? (n0 + row) : 0;
                const __nv_bfloat16* g = (half == 2 ? Bhi : Blo) + (size_t)rr * K + k0 + cc;
                uint32_t sa = (uint32_t)__cvta_generic_to_shared(&sB[s][half - 2][row][cc]);
                cp16(sa, g, v);
            }
        }
        asm volatile("cp.async.commit_group;\n");
    };

    // prologue: prefetch stages 0 and 1 (always commit both groups)
    load_stage(0, 0);
    if (nk > 1) load_stage(1, 16);
    else asm volatile("cp.async.commit_group;\n");

    for (int kt = 0; kt < nk; kt++) {
        int cur = kt % 3;
        asm volatile("cp.async.wait_group 1;\n");
        __syncthreads();

        uint32_t afh[4][4], afl[4][4];
        #pragma unroll
        for (int mi = 0; mi < 4; mi++) {
            int row = wm + mi * 16 + (lane & 15);
            int col = ((lane >> 4) & 1) * 8;
            uint32_t ah = (uint32_t)__cvta_generic_to_shared(&sA[cur][0][row][col]);
            uint32_t al = (uint32_t)__cvta_generic_to_shared(&sA[cur][1][row][col]);
            LDSM4(afh[mi][0], afh[mi][1], afh[mi][2], afh[mi][3], ah);
            LDSM4(afl[mi][0], afl[mi][1], afl[mi][2], afl[mi][3], al);
        }
        uint32_t bfh[4][2], bfl[4][2];
        #pragma unroll
        for (int ni = 0; ni < 4; ni++) {
            int l = lane & 15;
            int row = wn + ni * 8 + (l & 7);
            int col = (l >> 3) * 8;
            uint32_t bh = (uint32_t)__cvta_generic_to_shared(&sB[cur][0][row][col]);
            uint32_t bl = (uint32_t)__cvta_generic_to_shared(&sB[cur][1][row][col]);
            LDSM2(bfh[ni][0], bfh[ni][1], bh);
            LDSM2(bfl[ni][0], bfl[ni][1], bl);
        }
        #pragma unroll
        for (int mi = 0; mi < 4; mi++)
            #pragma unroll
            for (int ni = 0; ni < 4; ni++) {
                MMA16816(acc[mi][ni], afh[mi], bfh[ni]);
                MMA16816(acc[mi][ni], afh[mi], bfl[ni]);
                MMA16816(acc[mi][ni], afl[mi], bfh[ni]);
            }

        // prefetch stage kt+2 (writes stage (cur+2)%3 — never the one being
        // computed this iteration or next; safe without trailing barrier)
        if (kt + 2 < nk) load_stage((kt + 2) % 3, (kt + 2) * 16);
        else asm volatile("cp.async.commit_group;\n");
    }

    // ---- epilogue ----
    #pragma unroll
    for (int mi = 0; mi < 4; mi++) {
        #pragma unroll
        for (int half = 0; half < 2; half++) {
            int r = m0 + wm + mi * 16 + (lane >> 2) + half * 8;
            if (r >= M) continue;
            float nr = (EPI == 2) ? norm[r] : 0.0f;
            #pragma unroll
            for (int ni = 0; ni < 4; ni++) {
                int c = n0 + wn + ni * 8 + (lane & 3) * 2;
                if (c >= N) continue;
                long idx = (long)r * N + c;
                float v0 = acc[mi][ni][half * 2 + 0] + bias[c];
                float v1 = acc[mi][ni][half * 2 + 1] + bias[c + 1];
                if (EPI == 0) {
                    C[idx] = v0; C[idx + 1] = v1;
                } else if (EPI == 1) {
                    v0 = fmaxf(v0, 0.0f); v1 = fmaxf(v1, 0.0f);
                    if (!SPLIT) { C[idx] = v0; C[idx + 1] = v1; }
                } else {
                    float nrr = nr;
                    v0 = C[idx]     + acc[mi][ni][half * 2 + 0] * nrr + bias[c]     - acc[mi][ni][half * 2 + 0] - bias[c];
                    // (recompute cleanly below to avoid compiler confusion)
                    v0 = C[idx]     + acc[mi][ni][half * 2 + 0] * nrr + bias[c];
                    v1 = C[idx + 1] + acc[mi][ni][half * 2 + 1] * nrr + bias[c + 1];
                    C[idx] = v0; C[idx + 1] = v1;
                }
                if (SPLIT) {
                    __nv_bfloat16 h0 = __float2bfloat16(v0);
                    __nv_bfloat16 h1 = __float2bfloat16(v1);
                    __nv_bfloat162 hh; hh.x = h0; hh.y = h1;
                    __nv_bfloat162 ll;
                    ll.x = __float2bfloat16(v0 - __bfloat162float(h0));
                    ll.y = __float2bfloat16(v1 - __bfloat162float(h1));
                    *reinterpret_cast<__nv_bfloat162*>(&Ohi[idx]) = hh;
                    *reinterpret_cast<__nv_bfloat162*>(&Olo[idx]) = ll;
                }
            }
        }
    }
}

// ---------------- host-side helpers ----------------
static float* symaddr(const void* sym) {
    void* p = nullptr;
    cudaGetSymbolAddress(&p, sym);
    return (float*)p;
}
static __nv_bfloat16* symaddr_bf(const void* sym) {
    void* p = nullptr;
    cudaGetSymbolAddress(&p, sym);
    return (__nv_bfloat16*)p;
}

static inline void launch_mma(int epi, int split, int M, int N, int K,
                              const __nv_bfloat16* Ahi, const __nv_bfloat16* Alo,
                              const __nv_bfloat16* Bhi, const __nv_bfloat16* Blo,
                              const float* bias, float* C, const float* norm,
                              __nv_bfloat16* Ohi, __nv_bfloat16* Olo) {
    dim3 grid((N + 127) / 128, (M + 127) / 128);
    if (epi == 0) {
        cudaFuncSetAttribute(mma_gemm<0,0>, cudaFuncAttributeMaxDynamicSharedMemorySize, GEMM_SMEM_BYTES);
        mma_gemm<0,0><<<grid, 256, GEMM_SMEM_BYTES>>>(M, N, K, Ahi, Alo, Bhi, Blo, bias, C, norm, Ohi, Olo);
    } else if (epi == 1 && split) {
        cudaFuncSetAttribute(mma_gemm<1,1>, cudaFuncAttributeMaxDynamicSharedMemorySize, GEMM_SMEM_BYTES);
        mma_gemm<1,1><<<grid, 256, GEMM_SMEM_BYTES>>>(M, N, K, Ahi, Alo, Bhi, Blo, bias, C, norm, Ohi, Olo);
    } else if (epi == 1) {
        cudaFuncSetAttribute(mma_gemm<1,0>, cudaFuncAttributeMaxDynamicSharedMemorySize, GEMM_SMEM_BYTES);
        mma_gemm<1,0><<<grid, 256, GEMM_SMEM_BYTES>>>(M, N, K, Ahi, Alo, Bhi, Blo, bias, C, norm, Ohi, Olo);
    } else {
        cudaFuncSetAttribute(mma_gemm<2,1>, cudaFuncAttributeMaxDynamicSharedMemorySize, GEMM_SMEM_BYTES);
        mma_gemm<2,1><<<grid, 256, GEMM_SMEM_BYTES>>>(M, N, K, Ahi, Alo, Bhi, Blo, bias, C, norm, Ohi, Olo);
    }
}

static inline void zero(float* p, long n) {
    fill_kernel<<<(int)((n + 255) / 256), 256>>>(p, (int)n, 0.0f);
}

static inline void conv_pad(const float* src, __nv_bfloat16* hi, __nv_bfloat16* lo,
                            int M, int K, int Kp) {
    long total = (long)M * Kp;
    conv_pad_kernel<<<(int)((total + 255) / 256), 256>>>(src, hi, lo, M, K, Kp);
}

static inline void transconv(const float* W, __nv_bfloat16* Thi, __nv_bfloat16* Tlo,
                             int K, int N, int Kp) {
    dim3 grid((N + 31) / 32, (Kp + 31) / 32);
    transconv_kernel<<<grid, dim3(32, 8)>>>(W, Thi, Tlo, K, N, Kp);
}

static void run_bn_split(int M, int C, const float* h, const float* g, const float* beta,
                         float* outf, __nv_bfloat16* ohi, __nv_bfloat16* olo,
                         float* psum, float* psumsq, float* pmean, float* prstd) {
    zero(psum, C);
    zero(psumsq, C);
    int chunks = (M > 20000) ? 128 : 32;
    dim3 grid(C / 32, chunks);
    dim3 blk(32, 8);
    bn_stats_partial<<<grid, blk>>>(M, C, h, psum, psumsq);
    bn_finalize<<<(C + 127) / 128, 128>>>(C, 1.0f / (float)M, psum, psumsq, pmean, prstd);
    long total = (long)M * C;
    bn_apply_relu_split<<<(int)((total + 255) / 256), 256>>>(total, C, h, pmean, prstd, g, beta,
                                                             outf, ohi, olo);
}

extern "C" void kernel_launch(void* const* d_in, const int* in_sizes, int n_in,
                              void* d_out, int out_size) {
    const float* atom_features = (const float*)d_in[0];
    const float* r             = (const float*)d_in[1];
    const int*   src           = (const int*)d_in[2];
    const int*   dst           = (const int*)d_in[3];
    const float* ae_w   = (const float*)d_in[4];
    const float* ae_b   = (const float*)d_in[5];
    const float* ae_g   = (const float*)d_in[6];
    const float* ae_be  = (const float*)d_in[7];
    const float* ee1_w  = (const float*)d_in[8];
    const float* ee1_b  = (const float*)d_in[9];
    const float* ee1_g  = (const float*)d_in[10];
    const float* ee1_be = (const float*)d_in[11];
    const float* ee2_w  = (const float*)d_in[12];
    const float* ee2_b  = (const float*)d_in[13];
    const float* ee2_g  = (const float*)d_in[14];
    const float* ee2_be = (const float*)d_in[15];
    const float* gcn_w  = (const float*)d_in[16];
    const float* gcn_b  = (const float*)d_in[17];
    const float* sg_w   = (const float*)d_in[18];
    const float* sg_b   = (const float*)d_in[19];
    const float* dg_w   = (const float*)d_in[20];
    const float* dg_b   = (const float*)d_in[21];
    const float* eg_w   = (const float*)d_in[22];
    const float* eg_b   = (const float*)d_in[23];
    const float* fc1_w  = (const float*)d_in[24];
    const float* fc1_b  = (const float*)d_in[25];
    const float* fc2_w  = (const float*)d_in[26];
    const float* fc2_b  = (const float*)d_in[27];
    const float* fc3_w  = (const float*)d_in[28];
    const float* fc3_b  = (const float*)d_in[29];

    const int N = in_sizes[0] / 92;
    const int E = in_sizes[2];

    float* px    = symaddr(g_x);
    float* ppre  = symaddr(g_pre);
    float* pesrc = symaddr(g_esrc);
    float* pedst = symaddr(g_edst);
    float* pagg  = symaddr(g_agg);
    float* pbond = symaddr(g_bond);
    float* ph1   = symaddr(g_h1);
    float* py    = symaddr(g_y);
    float* pee   = symaddr(g_ee);
    float* pdegs = symaddr(g_degs);
    float* pdegd = symaddr(g_degd);
    float* pnl   = symaddr(g_nl);
    float* pnr   = symaddr(g_nr);
    float* psum  = symaddr(g_sum);
    float* psq   = symaddr(g_sumsq);
    float* pmean = symaddr(g_mean);
    float* prstd = symaddr(g_rstd);

    __nv_bfloat16 *xa_h = symaddr_bf(g_xa_hi),  *xa_l = symaddr_bf(g_xa_lo);
    __nv_bfloat16 *x_h  = symaddr_bf(g_x_hi),   *x_l  = symaddr_bf(g_x_lo);
    __nv_bfloat16 *ag_h = symaddr_bf(g_agg_hi), *ag_l = symaddr_bf(g_agg_lo);
    __nv_bfloat16 *f1_h = symaddr_bf(g_fc1_hi), *f1_l = symaddr_bf(g_fc1_lo);
    __nv_bfloat16 *f2_h = symaddr_bf(g_fc2_hi), *f2_l = symaddr_bf(g_fc2_lo);
    __nv_bfloat16 *rb_h = symaddr_bf(g_rbf_hi), *rb_l = symaddr_bf(g_rbf_lo);
    __nv_bfloat16 *h1_h = symaddr_bf(g_h1_hi),  *h1_l = symaddr_bf(g_h1_lo);
    __nv_bfloat16 *y_h  = symaddr_bf(g_y_hi),   *y_l  = symaddr_bf(g_y_lo);

    __nv_bfloat16 *aew_h = symaddr_bf(g_aewT_hi),  *aew_l = symaddr_bf(g_aewT_lo);
    __nv_bfloat16 *e1w_h = symaddr_bf(g_ee1wT_hi), *e1w_l = symaddr_bf(g_ee1wT_lo);
    __nv_bfloat16 *e2w_h = symaddr_bf(g_ee2wT_hi), *e2w_l = symaddr_bf(g_ee2wT_lo);
    __nv_bfloat16 *sgw_h = symaddr_bf(g_sgwT_hi),  *sgw_l = symaddr_bf(g_sgwT_lo);
    __nv_bfloat16 *dgw_h = symaddr_bf(g_dgwT_hi),  *dgw_l = symaddr_bf(g_dgwT_lo);
    __nv_bfloat16 *egw_h = symaddr_bf(g_egwT_hi),  *egw_l = symaddr_bf(g_egwT_lo);
    __nv_bfloat16 *gw_h  = symaddr_bf(g_gwT_hi),   *gw_l  = symaddr_bf(g_gwT_lo);
    __nv_bfloat16 *f1w_h = symaddr_bf(g_fc1wT_hi), *f1w_l = symaddr_bf(g_fc1wT_lo);
    __nv_bfloat16 *f2w_h = symaddr_bf(g_fc2wT_hi), *f2w_l = symaddr_bf(g_fc2wT_lo);
    __nv_bfloat16 *f3w_h = symaddr_bf(g_fc3wT_hi), *f3w_l = symaddr_bf(g_fc3wT_lo);

    // ---- weight transpose + split ----
    transconv(ae_w, aew_h, aew_l, 92, 256, 96);
    transconv(ee1_w, e1w_h, e1w_l, 80, 64, 80);
    transconv(ee2_w, e2w_h, e2w_l, 64, 256, 64);
    for (int i = 0; i < 4; i++) {
        long wo = (long)i * 256 * 256;
        transconv(sg_w + wo, sgw_h + wo, sgw_l + wo, 256, 256, 256);
        transconv(dg_w + wo, dgw_h + wo, dgw_l + wo, 256, 256, 256);
        transconv(eg_w + wo, egw_h + wo, egw_l + wo, 256, 256, 256);
        transconv(gcn_w + wo, gw_h + wo, gw_l + wo, 256, 256, 256);
    }
    transconv(fc1_w, f1w_h, f1w_l, 256, 1024, 256);
    transconv(fc2_w, f2w_h, f2w_l, 1024, 2048, 1024);
    transconv(fc3_w, f3w_h, f3w_l, 2048, 10000, 2048);

    // ---- degrees & norms ----
    zero(pdegs, N); zero(pdegd, N);
    deg_kernel<<<(E + 255) / 256, 256>>>(E, src, dst, pdegs, pdegd);
    norm_kernel<<<(N + 255) / 256, 256>>>(N, pdegs, pdegd, pnl, pnr);

    // ---- atom embedding MLP ----
    conv_pad(atom_features, xa_h, xa_l, N, 92, 96);
    launch_mma(0, 0, N, 256, 96, xa_h, xa_l, aew_h, aew_l, ae_b, ppre, nullptr, nullptr, nullptr);
    run_bn_split(N, 256, ppre, ae_g, ae_be, px, x_h, x_l, psum, psq, pmean, prstd);

    // ---- RBF + edge embedding MLPs ----
    bond_kernel<<<(E + 255) / 256, 256>>>(E, r, pbond);
    {
        long tot = (long)E * 80;
        rbf_split_kernel<<<(int)((tot + 255) / 256), 256>>>((int)tot, pbond, rb_h, rb_l);
    }
    launch_mma(0, 0, E, 64, 80, rb_h, rb_l, e1w_h, e1w_l, ee1_b, ph1, nullptr, nullptr, nullptr);
    run_bn_split(E, 64, ph1, ee1_g, ee1_be, nullptr, h1_h, h1_l, psum, psq, pmean, prstd);
    launch_mma(0, 0, E, 256, 64, h1_h, h1_l, e2w_h, e2w_l, ee2_b, py, nullptr, nullptr, nullptr);
    run_bn_split(E, 256, py, ee2_g, ee2_be, nullptr, y_h, y_l, psum, psq, pmean, prstd);

    // ---- 4 gated GCN layers ----
    for (int i = 0; i < 4; i++) {
        long wo = (long)i * 256 * 256;
        const float* sgb = sg_b + i * 256;
        const float* dgb = dg_b + i * 256;
        const float* egb = eg_b + i * 256;
        const float* gb  = gcn_b + i * 256;

        launch_mma(0, 0, N, 256, 256, x_h, x_l, sgw_h + wo, sgw_l + wo, sgb, pesrc, nullptr, nullptr, nullptr);
        launch_mma(0, 0, N, 256, 256, x_h, x_l, dgw_h + wo, dgw_l + wo, dgb, pedst, nullptr, nullptr, nullptr);
        launch_mma(0, 0, E, 256, 256, y_h, y_l, egw_h + wo, egw_l + wo, egb, pee, nullptr, nullptr, nullptr);

        zero(pagg, (long)N * 256);
        edge_gate_agg<<<(E + 3) / 4, 256>>>(E, px, pesrc, pedst, pee, src, dst, pnl, pagg);
        conv_pad(pagg, ag_h, ag_l, N, 256, 256);

        // residual + fused split of new x
        launch_mma(2, 1, N, 256, 256, ag_h, ag_l, gw_h + wo, gw_l + wo, gb, px, pnr, x_h, x_l);
    }

    // ---- readout MLP (fc1/fc2 write only split form) ----
    launch_mma(1, 1, N, 1024, 256, x_h, x_l, f1w_h, f1w_l, fc1_b, nullptr, nullptr, f1_h, f1_l);
    launch_mma(1, 1, N, 2048, 1024, f1_h, f1_l, f2w_h, f2w_l, fc2_b, nullptr, nullptr, f2_h, f2_l);
    launch_mma(1, 0, N, 10000, 2048, f2_h, f2_l, f3w_h, f3w_l, fc3_b, (float*)d_out, nullptr, nullptr, nullptr);
}

// round 8
// speedup vs baseline: 3.2417x; 1.0192x over previous
#include <cuda_runtime.h>
#include <cuda_bf16.h>
#include <stdint.h>
#include <math.h>

// ---------------- problem-size constants (fixed by the benchmark) ----------------
#define NMAXV 5000
#define EMAXV 160000
#define HD 256

// ---------------- fp32 scratch ----------------
__device__ float g_x   [NMAXV * 256];
__device__ float g_pre [NMAXV * 256];
__device__ float g_esrc[NMAXV * 256];
__device__ float g_edst[NMAXV * 256];
__device__ float g_agg [NMAXV * 256];
__device__ float g_bond[EMAXV];
__device__ float g_h1  [EMAXV * 64];
__device__ float g_y   [EMAXV * 256];
__device__ float g_ee  [EMAXV * 256];
__device__ float g_degs[NMAXV];
__device__ float g_degd[NMAXV];
__device__ float g_nl  [NMAXV];
__device__ float g_nr  [NMAXV];
__device__ float g_bps [128 * 256];   // BN partial sums [chunk][C]
__device__ float g_bpq [128 * 256];   // BN partial sumsq
__device__ float g_mean[256];
__device__ float g_rstd[256];

// ---------------- bf16 split (hi/lo) scratch: activations ----------------
__device__ __nv_bfloat16 g_xa_hi[NMAXV * 96],    g_xa_lo[NMAXV * 96];
__device__ __nv_bfloat16 g_x_hi [NMAXV * 256],   g_x_lo [NMAXV * 256];
__device__ __nv_bfloat16 g_agg_hi[NMAXV * 256],  g_agg_lo[NMAXV * 256];
__device__ __nv_bfloat16 g_fc1_hi[NMAXV * 1024], g_fc1_lo[NMAXV * 1024];
__device__ __nv_bfloat16 g_fc2_hi[NMAXV * 2048], g_fc2_lo[NMAXV * 2048];
__device__ __nv_bfloat16 g_rbf_hi[EMAXV * 80],   g_rbf_lo[EMAXV * 80];
__device__ __nv_bfloat16 g_h1_hi [EMAXV * 64],   g_h1_lo [EMAXV * 64];
__device__ __nv_bfloat16 g_y_hi  [EMAXV * 256],  g_y_lo  [EMAXV * 256];

// ---------------- bf16 split scratch: transposed weights [N][Kpad] ----------------
__device__ __nv_bfloat16 g_aewT_hi [256 * 96],    g_aewT_lo [256 * 96];
__device__ __nv_bfloat16 g_ee1wT_hi[64 * 80],     g_ee1wT_lo[64 * 80];
__device__ __nv_bfloat16 g_ee2wT_hi[256 * 64],    g_ee2wT_lo[256 * 64];
__device__ __nv_bfloat16 g_sgwT_hi [4 * 256 * 256], g_sgwT_lo [4 * 256 * 256];
__device__ __nv_bfloat16 g_dgwT_hi [4 * 256 * 256], g_dgwT_lo [4 * 256 * 256];
__device__ __nv_bfloat16 g_egwT_hi [4 * 256 * 256], g_egwT_lo [4 * 256 * 256];
__device__ __nv_bfloat16 g_gwT_hi  [4 * 256 * 256], g_gwT_lo  [4 * 256 * 256];
__device__ __nv_bfloat16 g_fc1wT_hi[1024 * 256],  g_fc1wT_lo[1024 * 256];
__device__ __nv_bfloat16 g_fc2wT_hi[2048 * 1024], g_fc2wT_lo[2048 * 1024];
__device__ __nv_bfloat16 g_fc3wT_hi[10000 * 2048],g_fc3wT_lo[10000 * 2048];

// ---------------- small utility kernels ----------------
__global__ void fill_kernel(float* p, int n, float v) {
    int i = blockIdx.x * blockDim.x + threadIdx.x;
    if (i < n) p[i] = v;
}

__global__ void deg_kernel(int E, const int* __restrict__ src, const int* __restrict__ dst,
                           float* degs, float* degd) {
    int e = blockIdx.x * blockDim.x + threadIdx.x;
    if (e < E) {
        atomicAdd(&degs[src[e]], 1.0f);
        atomicAdd(&degd[dst[e]], 1.0f);
    }
}

__global__ void norm_kernel(int N, const float* __restrict__ degs, const float* __restrict__ degd,
                            float* nl, float* nr) {
    int i = blockIdx.x * blockDim.x + threadIdx.x;
    if (i < N) {
        nl[i] = rsqrtf(fmaxf(degs[i], 1.0f));
        nr[i] = rsqrtf(fmaxf(degd[i], 1.0f));
    }
}

__global__ void bond_kernel(int E, const float* __restrict__ r, float* bond) {
    int e = blockIdx.x * blockDim.x + threadIdx.x;
    if (e < E) {
        float a = r[e * 3 + 0], b = r[e * 3 + 1], c = r[e * 3 + 2];
        bond[e] = sqrtf(a * a + b * b + c * c);
    }
}

// RBF with fused hi/lo split output
__global__ void rbf_split_kernel(int total, const float* __restrict__ bond,
                                 __nv_bfloat16* __restrict__ hi, __nv_bfloat16* __restrict__ lo) {
    int idx = blockIdx.x * blockDim.x + threadIdx.x;
    if (idx < total) {
        int e = idx / 80;
        int j = idx - e * 80;
        const float gamma = 79.0f / 8.0f;
        float cj = (8.0f / 79.0f) * (float)j;
        float d = bond[e] - cj;
        float v = expf(-gamma * d * d);
        __nv_bfloat16 h = __float2bfloat16(v);
        hi[idx] = h;
        lo[idx] = __float2bfloat16(v - __bfloat162float(h));
    }
}

// split fp32 -> (hi, lo) bf16 with column padding [M x K] -> [M x Kp]
__global__ void conv_pad_kernel(const float* __restrict__ src,
                                __nv_bfloat16* __restrict__ hi, __nv_bfloat16* __restrict__ lo,
                                int M, int K, int Kp) {
    long idx = (long)blockIdx.x * blockDim.x + threadIdx.x;
    long total = (long)M * Kp;
    if (idx >= total) return;
    int r = (int)(idx / Kp);
    int c = (int)(idx - (long)r * Kp);
    float v = (c < K) ? src[(long)r * K + c] : 0.0f;
    __nv_bfloat16 h = __float2bfloat16(v);
    hi[idx] = h;
    lo[idx] = __float2bfloat16(v - __bfloat162float(h));
}

// transpose + split: W[K x N] fp32 -> WT hi/lo [N x Kp] bf16
__global__ void transconv_kernel(const float* __restrict__ W,
                                 __nv_bfloat16* __restrict__ Thi, __nv_bfloat16* __restrict__ Tlo,
                                 int K, int N, int Kp) {
    __shared__ float t[32][33];
    int k0 = blockIdx.y * 32, n0 = blockIdx.x * 32;
    int tx = threadIdx.x, ty = threadIdx.y; // 32 x 8
    #pragma unroll
    for (int i = ty; i < 32; i += 8) {
        int k = k0 + i, n = n0 + tx;
        t[i][tx] = (k < K && n < N) ? W[(long)k * N + n] : 0.0f;
    }
    __syncthreads();
    #pragma unroll
    for (int i = ty; i < 32; i += 8) {
        int n = n0 + i, k = k0 + tx;
        if (n < N && k < Kp) {
            float v = t[tx][i];
            __nv_bfloat16 h = __float2bfloat16(v);
            Thi[(long)n * Kp + k] = h;
            Tlo[(long)n * Kp + k] = __float2bfloat16(v - __bfloat162float(h));
        }
    }
}

// ---------------- BatchNorm (training-mode batch stats) ----------------
// partials written per chunk (no atomics, no pre-zero)
__global__ void bn_stats_partial(int M, int C, const float* __restrict__ h,
                                 float* psum, float* psumsq) {
    int c = blockIdx.x * 32 + threadIdx.x;
    int rowsPerChunk = (M + gridDim.y - 1) / gridDim.y;
    int r0 = blockIdx.y * rowsPerChunk;
    int r1 = min(M, r0 + rowsPerChunk);
    float s = 0.f, s2 = 0.f;
    if (c < C) {
        for (int r = r0 + threadIdx.y; r < r1; r += 8) {
            float v = h[(long)r * C + c];
            s += v; s2 += v * v;
        }
    }
    __shared__ float sh[2][8][32];
    sh[0][threadIdx.y][threadIdx.x] = s;
    sh[1][threadIdx.y][threadIdx.x] = s2;
    __syncthreads();
    if (threadIdx.y == 0 && c < C) {
        float ts = 0.f, t2 = 0.f;
        #pragma unroll
        for (int i = 0; i < 8; i++) { ts += sh[0][i][threadIdx.x]; t2 += sh[1][i][threadIdx.x]; }
        psum[blockIdx.y * C + c] = ts;
        psumsq[blockIdx.y * C + c] = t2;
    }
}

__global__ void bn_finalize(int C, int chunks, float invM,
                            const float* __restrict__ psum, const float* __restrict__ psumsq,
                            float* mean, float* rstd) {
    int c = blockIdx.x * blockDim.x + threadIdx.x;
    if (c < C) {
        float s = 0.f, s2 = 0.f;
        for (int k = 0; k < chunks; k++) { s += psum[k * C + c]; s2 += psumsq[k * C + c]; }
        float m = s * invM;
        float var = fmaxf(s2 * invM - m * m, 0.0f);
        mean[c] = m;
        rstd[c] = rsqrtf(var + 1e-5f);
    }
}

// BN apply + ReLU + fused split. outf may be null (skip fp32 write).
__global__ void bn_apply_relu_split(long total, int C, const float* __restrict__ h,
                                    const float* __restrict__ mean, const float* __restrict__ rstd,
                                    const float* __restrict__ g, const float* __restrict__ beta,
                                    float* outf,
                                    __nv_bfloat16* __restrict__ ohi, __nv_bfloat16* __restrict__ olo) {
    long idx = (long)blockIdx.x * blockDim.x + threadIdx.x;
    if (idx < total) {
        int c = (int)(idx % C);
        float v = g[c] * (h[idx] - mean[c]) * rstd[c] + beta[c];
        v = fmaxf(v, 0.0f);
        if (outf) outf[idx] = v;
        __nv_bfloat16 hb = __float2bfloat16(v);
        ohi[idx] = hb;
        olo[idx] = __float2bfloat16(v - __bfloat162float(hb));
    }
}

// ---------------- edge gate + scatter-aggregate (float4, 4 edges/block) ----------------
__global__ void edge_gate_agg(int E, const float* __restrict__ x,
                              const float* __restrict__ esrc, const float* __restrict__ edst,
                              const float* __restrict__ ee,
                              const int* __restrict__ src, const int* __restrict__ dst,
                              const float* __restrict__ nl, float* agg) {
    int e = blockIdx.x * 4 + (threadIdx.x >> 6);
    if (e >= E) return;
    int j = (threadIdx.x & 63) * 4;
    int s = src[e], d = dst[e];
    float nls = nl[s];
    float4 es = *(const float4*)&esrc[s * HD + j];
    float4 ed = *(const float4*)&edst[d * HD + j];
    float4 ev = *(const float4*)&ee[(long)e * HD + j];
    float4 xv = *(const float4*)&x[s * HD + j];
    float m0 = xv.x * nls / (1.0f + expf(-(es.x + ed.x + ev.x)));
    float m1 = xv.y * nls / (1.0f + expf(-(es.y + ed.y + ev.y)));
    float m2 = xv.z * nls / (1.0f + expf(-(es.z + ed.z + ev.z)));
    float m3 = xv.w * nls / (1.0f + expf(-(es.w + ed.w + ev.w)));
    float* a = &agg[d * HD + j];
    atomicAdd(a + 0, m0);
    atomicAdd(a + 1, m1);
    atomicAdd(a + 2, m2);
    atomicAdd(a + 3, m3);
}

// ---------------- split-bf16 tensor-core GEMM (3-stage cp.async, 64x64 warp tile) --
// C[M x N] = epilogue( A[M x K] @ B[K x N] + bias )
// A hi/lo bf16 [M x K] row-major, B TRANSPOSED hi/lo bf16 [N x K]. K multiple of 16.
// Block 128x128, 128 threads (4 warps), each warp 64x64.
// EPI 0: C = acc+bias
// EPI 1: relu(acc+bias)   (if SPLIT: write only hi/lo; no fp32)
// EPI 2: C += acc*norm[row] + bias  (residual; if SPLIT also write hi/lo)

__device__ __forceinline__ void cp16(uint32_t saddr, const void* gaddr, bool valid) {
    int sz = valid ? 16 : 0;
    asm volatile("cp.async.cg.shared.global [%0], [%1], 16, %2;\n"
                 :: "r"(saddr), "l"(gaddr), "r"(sz));
}

#define LDSM4(R0, R1, R2, R3, addr) \
    asm volatile("ldmatrix.sync.aligned.m8n8.x4.shared.b16 {%0,%1,%2,%3}, [%4];" \
                 : "=r"(R0), "=r"(R1), "=r"(R2), "=r"(R3) : "r"(addr))

#define MMA16816(d, a, b) \
    asm volatile("mma.sync.aligned.m16n8k16.row.col.f32.bf16.bf16.f32 " \
                 "{%0,%1,%2,%3}, {%4,%5,%6,%7}, {%8,%9}, {%0,%1,%2,%3};" \
                 : "+f"((d)[0]), "+f"((d)[1]), "+f"((d)[2]), "+f"((d)[3]) \
                 : "r"((a)[0]), "r"((a)[1]), "r"((a)[2]), "r"((a)[3]), \
                   "r"((b)[0]), "r"((b)[1]))

#define GEMM_SMEM_ELEMS (3 * 2 * 128 * 24)
#define GEMM_SMEM_BYTES (2 * GEMM_SMEM_ELEMS * 2)

template <int EPI, int SPLIT>
__global__ __launch_bounds__(128, 2) void mma_gemm(
    int M, int N, int K,
    const __nv_bfloat16* __restrict__ Ahi, const __nv_bfloat16* __restrict__ Alo,
    const __nv_bfloat16* __restrict__ Bhi, const __nv_bfloat16* __restrict__ Blo,
    const float* __restrict__ bias, float* __restrict__ C,
    const float* __restrict__ norm,
    __nv_bfloat16* __restrict__ Ohi, __nv_bfloat16* __restrict__ Olo) {
    extern __shared__ __nv_bfloat16 dsm[];
    __nv_bfloat16 (*sA)[2][128][24] = reinterpret_cast<__nv_bfloat16 (*)[2][128][24]>(dsm);
    __nv_bfloat16 (*sB)[2][128][24] = reinterpret_cast<__nv_bfloat16 (*)[2][128][24]>(dsm + GEMM_SMEM_ELEMS);

    const int tid = threadIdx.x;
    const int m0 = blockIdx.y * 128;
    const int n0 = blockIdx.x * 128;
    const int wid = tid >> 5, lane = tid & 31;
    const int wm = (wid & 1) * 64;
    const int wn = (wid >> 1) * 64;

    float acc[4][8][4];
    #pragma unroll
    for (int i = 0; i < 4; i++)
        #pragma unroll
        for (int j = 0; j < 8; j++)
            #pragma unroll
            for (int q = 0; q < 4; q++) acc[i][j][q] = 0.0f;

    const int nk = K / 16;

    // stage load: 1024 16B chunks, 128 threads -> 8 per thread
    auto load_stage = [&](int s, int k0) {
        #pragma unroll
        for (int it = 0; it < 8; it++) {
            int t = tid + it * 128;
            int half = t >> 8;            // 0:Ahi 1:Alo 2:Bhi 3:Blo
            int f = t & 255;
            int row = f >> 1;
            int cc = (f & 1) * 8;
            if (half < 2) {
                bool v = (m0 + row) < M;
                int rr = v ? (m0 + row) : 0;
                const __nv_bfloat16* g = (half == 0 ? Ahi : Alo) + (size_t)rr * K + k0 + cc;
                uint32_t sa = (uint32_t)__cvta_generic_to_shared(&sA[s][half][row][cc]);
                cp16(sa, g, v);
            } else {
                bool v = (n0 + row) < N;
                int rr = v ? (n0 + row) : 0;
                const __nv_bfloat16* g = (half == 2 ? Bhi : Blo) + (size_t)rr * K + k0 + cc;
                uint32_t sa = (uint32_t)__cvta_generic_to_shared(&sB[s][half - 2][row][cc]);
                cp16(sa, g, v);
            }
        }
        asm volatile("cp.async.commit_group;\n");
    };

    load_stage(0, 0);
    if (nk > 1) load_stage(1, 16);
    else asm volatile("cp.async.commit_group;\n");

    for (int kt = 0; kt < nk; kt++) {
        int cur = kt % 3;
        asm volatile("cp.async.wait_group 1;\n");
        __syncthreads();

        // A fragments: 4 m-tiles (hi + lo)
        uint32_t afh[4][4], afl[4][4];
        #pragma unroll
        for (int mi = 0; mi < 4; mi++) {
            int row = wm + mi * 16 + (lane & 15);
            int col = ((lane >> 4) & 1) * 8;
            uint32_t ah = (uint32_t)__cvta_generic_to_shared(&sA[cur][0][row][col]);
            uint32_t al = (uint32_t)__cvta_generic_to_shared(&sA[cur][1][row][col]);
            LDSM4(afh[mi][0], afh[mi][1], afh[mi][2], afh[mi][3], ah);
            LDSM4(afl[mi][0], afl[mi][1], afl[mi][2], afl[mi][3], al);
        }
        // B fragments: 8 n-tiles, packed 2 per LDSM4 (hi + lo)
        uint32_t bfh[8][2], bfl[8][2];
        #pragma unroll
        for (int p = 0; p < 4; p++) {
            int row = wn + (2 * p + ((lane >> 4) & 1)) * 8 + (lane & 7);
            int col = ((lane >> 3) & 1) * 8;
            uint32_t bh = (uint32_t)__cvta_generic_to_shared(&sB[cur][0][row][col]);
            uint32_t bl = (uint32_t)__cvta_generic_to_shared(&sB[cur][1][row][col]);
            LDSM4(bfh[2*p][0], bfh[2*p][1], bfh[2*p+1][0], bfh[2*p+1][1], bh);
            LDSM4(bfl[2*p][0], bfl[2*p][1], bfl[2*p+1][0], bfl[2*p+1][1], bl);
        }
        #pragma unroll
        for (int mi = 0; mi < 4; mi++)
            #pragma unroll
            for (int ni = 0; ni < 8; ni++) {
                MMA16816(acc[mi][ni], afh[mi], bfh[ni]);
                MMA16816(acc[mi][ni], afh[mi], bfl[ni]);
                MMA16816(acc[mi][ni], afl[mi], bfh[ni]);
            }

        if (kt + 2 < nk) load_stage((kt + 2) % 3, (kt + 2) * 16);
        else asm volatile("cp.async.commit_group;\n");
    }

    // ---- epilogue ----
    #pragma unroll
    for (int mi = 0; mi < 4; mi++) {
        #pragma unroll
        for (int half = 0; half < 2; half++) {
            int r = m0 + wm + mi * 16 + (lane >> 2) + half * 8;
            if (r >= M) continue;
            float nr = (EPI == 2) ? norm[r] : 0.0f;
            #pragma unroll
            for (int ni = 0; ni < 8; ni++) {
                int c = n0 + wn + ni * 8 + (lane & 3) * 2;
                if (c >= N) continue;
                long idx = (long)r * N + c;
                float a0 = acc[mi][ni][half * 2 + 0];
                float a1 = acc[mi][ni][half * 2 + 1];
                float v0, v1;
                if (EPI == 0) {
                    v0 = a0 + bias[c]; v1 = a1 + bias[c + 1];
                    C[idx] = v0; C[idx + 1] = v1;
                } else if (EPI == 1) {
                    v0 = fmaxf(a0 + bias[c], 0.0f); v1 = fmaxf(a1 + bias[c + 1], 0.0f);
                    if (!SPLIT) { C[idx] = v0; C[idx + 1] = v1; }
                } else {
                    v0 = C[idx]     + a0 * nr + bias[c];
                    v1 = C[idx + 1] + a1 * nr + bias[c + 1];
                    C[idx] = v0; C[idx + 1] = v1;
                }
                if (SPLIT) {
                    __nv_bfloat16 h0 = __float2bfloat16(v0);
                    __nv_bfloat16 h1 = __float2bfloat16(v1);
                    __nv_bfloat162 hh; hh.x = h0; hh.y = h1;
                    __nv_bfloat162 ll;
                    ll.x = __float2bfloat16(v0 - __bfloat162float(h0));
                    ll.y = __float2bfloat16(v1 - __bfloat162float(h1));
                    *reinterpret_cast<__nv_bfloat162*>(&Ohi[idx]) = hh;
                    *reinterpret_cast<__nv_bfloat162*>(&Olo[idx]) = ll;
                }
            }
        }
    }
}

// ---------------- host-side helpers ----------------
static float* symaddr(const void* sym) {
    void* p = nullptr;
    cudaGetSymbolAddress(&p, sym);
    return (float*)p;
}
static __nv_bfloat16* symaddr_bf(const void* sym) {
    void* p = nullptr;
    cudaGetSymbolAddress(&p, sym);
    return (__nv_bfloat16*)p;
}

static inline void launch_mma(int epi, int split, int M, int N, int K,
                              const __nv_bfloat16* Ahi, const __nv_bfloat16* Alo,
                              const __nv_bfloat16* Bhi, const __nv_bfloat16* Blo,
                              const float* bias, float* C, const float* norm,
                              __nv_bfloat16* Ohi, __nv_bfloat16* Olo) {
    dim3 grid((N + 127) / 128, (M + 127) / 128);
    if (epi == 0) {
        cudaFuncSetAttribute(mma_gemm<0,0>, cudaFuncAttributeMaxDynamicSharedMemorySize, GEMM_SMEM_BYTES);
        mma_gemm<0,0><<<grid, 128, GEMM_SMEM_BYTES>>>(M, N, K, Ahi, Alo, Bhi, Blo, bias, C, norm, Ohi, Olo);
    } else if (epi == 1 && split) {
        cudaFuncSetAttribute(mma_gemm<1,1>, cudaFuncAttributeMaxDynamicSharedMemorySize, GEMM_SMEM_BYTES);
        mma_gemm<1,1><<<grid, 128, GEMM_SMEM_BYTES>>>(M, N, K, Ahi, Alo, Bhi, Blo, bias, C, norm, Ohi, Olo);
    } else if (epi == 1) {
        cudaFuncSetAttribute(mma_gemm<1,0>, cudaFuncAttributeMaxDynamicSharedMemorySize, GEMM_SMEM_BYTES);
        mma_gemm<1,0><<<grid, 128, GEMM_SMEM_BYTES>>>(M, N, K, Ahi, Alo, Bhi, Blo, bias, C, norm, Ohi, Olo);
    } else {
        cudaFuncSetAttribute(mma_gemm<2,1>, cudaFuncAttributeMaxDynamicSharedMemorySize, GEMM_SMEM_BYTES);
        mma_gemm<2,1><<<grid, 128, GEMM_SMEM_BYTES>>>(M, N, K, Ahi, Alo, Bhi, Blo, bias, C, norm, Ohi, Olo);
    }
}

static inline void zero(float* p, long n) {
    fill_kernel<<<(int)((n + 255) / 256), 256>>>(p, (int)n, 0.0f);
}

static inline void conv_pad(const float* src, __nv_bfloat16* hi, __nv_bfloat16* lo,
                            int M, int K, int Kp) {
    long total = (long)M * Kp;
    conv_pad_kernel<<<(int)((total + 255) / 256), 256>>>(src, hi, lo, M, K, Kp);
}

static inline void transconv(const float* W, __nv_bfloat16* Thi, __nv_bfloat16* Tlo,
                             int K, int N, int Kp) {
    dim3 grid((N + 31) / 32, (Kp + 31) / 32);
    transconv_kernel<<<grid, dim3(32, 8)>>>(W, Thi, Tlo, K, N, Kp);
}

static void run_bn_split(int M, int C, const float* h, const float* g, const float* beta,
                         float* outf, __nv_bfloat16* ohi, __nv_bfloat16* olo,
                         float* pbs, float* pbq, float* pmean, float* prstd) {
    int chunks = (M > 20000) ? 128 : 32;
    dim3 grid(C / 32, chunks);
    dim3 blk(32, 8);
    bn_stats_partial<<<grid, blk>>>(M, C, h, pbs, pbq);
    bn_finalize<<<(C + 127) / 128, 128>>>(C, chunks, 1.0f / (float)M, pbs, pbq, pmean, prstd);
    long total = (long)M * C;
    bn_apply_relu_split<<<(int)((total + 255) / 256), 256>>>(total, C, h, pmean, prstd, g, beta,
                                                             outf, ohi, olo);
}

extern "C" void kernel_launch(void* const* d_in, const int* in_sizes, int n_in,
                              void* d_out, int out_size) {
    const float* atom_features = (const float*)d_in[0];
    const float* r             = (const float*)d_in[1];
    const int*   src           = (const int*)d_in[2];
    const int*   dst           = (const int*)d_in[3];
    const float* ae_w   = (const float*)d_in[4];
    const float* ae_b   = (const float*)d_in[5];
    const float* ae_g   = (const float*)d_in[6];
    const float* ae_be  = (const float*)d_in[7];
    const float* ee1_w  = (const float*)d_in[8];
    const float* ee1_b  = (const float*)d_in[9];
    const float* ee1_g  = (const float*)d_in[10];
    const float* ee1_be = (const float*)d_in[11];
    const float* ee2_w  = (const float*)d_in[12];
    const float* ee2_b  = (const float*)d_in[13];
    const float* ee2_g  = (const float*)d_in[14];
    const float* ee2_be = (const float*)d_in[15];
    const float* gcn_w  = (const float*)d_in[16];
    const float* gcn_b  = (const float*)d_in[17];
    const float* sg_w   = (const float*)d_in[18];
    const float* sg_b   = (const float*)d_in[19];
    const float* dg_w   = (const float*)d_in[20];
    const float* dg_b   = (const float*)d_in[21];
    const float* eg_w   = (const float*)d_in[22];
    const float* eg_b   = (const float*)d_in[23];
    const float* fc1_w  = (const float*)d_in[24];
    const float* fc1_b  = (const float*)d_in[25];
    const float* fc2_w  = (const float*)d_in[26];
    const float* fc2_b  = (const float*)d_in[27];
    const float* fc3_w  = (const float*)d_in[28];
    const float* fc3_b  = (const float*)d_in[29];

    const int N = in_sizes[0] / 92;
    const int E = in_sizes[2];

    float* px    = symaddr(g_x);
    float* ppre  = symaddr(g_pre);
    float* pesrc = symaddr(g_esrc);
    float* pedst = symaddr(g_edst);
    float* pagg  = symaddr(g_agg);
    float* pbond = symaddr(g_bond);
    float* ph1   = symaddr(g_h1);
    float* py    = symaddr(g_y);
    float* pee   = symaddr(g_ee);
    float* pdegs = symaddr(g_degs);
    float* pdegd = symaddr(g_degd);
    float* pnl   = symaddr(g_nl);
    float* pnr   = symaddr(g_nr);
    float* pbs   = symaddr(g_bps);
    float* pbq   = symaddr(g_bpq);
    float* pmean = symaddr(g_mean);
    float* prstd = symaddr(g_rstd);

    __nv_bfloat16 *xa_h = symaddr_bf(g_xa_hi),  *xa_l = symaddr_bf(g_xa_lo);
    __nv_bfloat16 *x_h  = symaddr_bf(g_x_hi),   *x_l  = symaddr_bf(g_x_lo);
    __nv_bfloat16 *ag_h = symaddr_bf(g_agg_hi), *ag_l = symaddr_bf(g_agg_lo);
    __nv_bfloat16 *f1_h = symaddr_bf(g_fc1_hi), *f1_l = symaddr_bf(g_fc1_lo);
    __nv_bfloat16 *f2_h = symaddr_bf(g_fc2_hi), *f2_l = symaddr_bf(g_fc2_lo);
    __nv_bfloat16 *rb_h = symaddr_bf(g_rbf_hi), *rb_l = symaddr_bf(g_rbf_lo);
    __nv_bfloat16 *h1_h = symaddr_bf(g_h1_hi),  *h1_l = symaddr_bf(g_h1_lo);
    __nv_bfloat16 *y_h  = symaddr_bf(g_y_hi),   *y_l  = symaddr_bf(g_y_lo);

    __nv_bfloat16 *aew_h = symaddr_bf(g_aewT_hi),  *aew_l = symaddr_bf(g_aewT_lo);
    __nv_bfloat16 *e1w_h = symaddr_bf(g_ee1wT_hi), *e1w_l = symaddr_bf(g_ee1wT_lo);
    __nv_bfloat16 *e2w_h = symaddr_bf(g_ee2wT_hi), *e2w_l = symaddr_bf(g_ee2wT_lo);
    __nv_bfloat16 *sgw_h = symaddr_bf(g_sgwT_hi),  *sgw_l = symaddr_bf(g_sgwT_lo);
    __nv_bfloat16 *dgw_h = symaddr_bf(g_dgwT_hi),  *dgw_l = symaddr_bf(g_dgwT_lo);
    __nv_bfloat16 *egw_h = symaddr_bf(g_egwT_hi),  *egw_l = symaddr_bf(g_egwT_lo);
    __nv_bfloat16 *gw_h  = symaddr_bf(g_gwT_hi),   *gw_l  = symaddr_bf(g_gwT_lo);
    __nv_bfloat16 *f1w_h = symaddr_bf(g_fc1wT_hi), *f1w_l = symaddr_bf(g_fc1wT_lo);
    __nv_bfloat16 *f2w_h = symaddr_bf(g_fc2wT_hi), *f2w_l = symaddr_bf(g_fc2wT_lo);
    __nv_bfloat16 *f3w_h = symaddr_bf(g_fc3wT_hi), *f3w_l = symaddr_bf(g_fc3wT_lo);

    // ---- weight transpose + split ----
    transconv(ae_w, aew_h, aew_l, 92, 256, 96);
    transconv(ee1_w, e1w_h, e1w_l, 80, 64, 80);
    transconv(ee2_w, e2w_h, e2w_l, 64, 256, 64);
    for (int i = 0; i < 4; i++) {
        long wo = (long)i * 256 * 256;
        transconv(sg_w + wo, sgw_h + wo, sgw_l + wo, 256, 256, 256);
        transconv(dg_w + wo, dgw_h + wo, dgw_l + wo, 256, 256, 256);
        transconv(eg_w + wo, egw_h + wo, egw_l + wo, 256, 256, 256);
        transconv(gcn_w + wo, gw_h + wo, gw_l + wo, 256, 256, 256);
    }
    transconv(fc1_w, f1w_h, f1w_l, 256, 1024, 256);
    transconv(fc2_w, f2w_h, f2w_l, 1024, 2048, 1024);
    transconv(fc3_w, f3w_h, f3w_l, 2048, 10000, 2048);

    // ---- degrees & norms ----
    zero(pdegs, N); zero(pdegd, N);
    deg_kernel<<<(E + 255) / 256, 256>>>(E, src, dst, pdegs, pdegd);
    norm_kernel<<<(N + 255) / 256, 256>>>(N, pdegs, pdegd, pnl, pnr);

    // ---- atom embedding MLP ----
    conv_pad(atom_features, xa_h, xa_l, N, 92, 96);
    launch_mma(0, 0, N, 256, 96, xa_h, xa_l, aew_h, aew_l, ae_b, ppre, nullptr, nullptr, nullptr);
    run_bn_split(N, 256, ppre, ae_g, ae_be, px, x_h, x_l, pbs, pbq, pmean, prstd);

    // ---- RBF + edge embedding MLPs ----
    bond_kernel<<<(E + 255) / 256, 256>>>(E, r, pbond);
    {
        long tot = (long)E * 80;
        rbf_split_kernel<<<(int)((tot + 255) / 256), 256>>>((int)tot, pbond, rb_h, rb_l);
    }
    launch_mma(0, 0, E, 64, 80, rb_h, rb_l, e1w_h, e1w_l, ee1_b, ph1, nullptr, nullptr, nullptr);
    run_bn_split(E, 64, ph1, ee1_g, ee1_be, nullptr, h1_h, h1_l, pbs, pbq, pmean, prstd);
    launch_mma(0, 0, E, 256, 64, h1_h, h1_l, e2w_h, e2w_l, ee2_b, py, nullptr, nullptr, nullptr);
    run_bn_split(E, 256, py, ee2_g, ee2_be, nullptr, y_h, y_l, pbs, pbq, pmean, prstd);

    // ---- 4 gated GCN layers ----
    for (int i = 0; i < 4; i++) {
        long wo = (long)i * 256 * 256;
        const float* sgb = sg_b + i * 256;
        const float* dgb = dg_b + i * 256;
        const float* egb = eg_b + i * 256;
        const float* gb  = gcn_b + i * 256;

        launch_mma(0, 0, N, 256, 256, x_h, x_l, sgw_h + wo, sgw_l + wo, sgb, pesrc, nullptr, nullptr, nullptr);
        launch_mma(0, 0, N, 256, 256, x_h, x_l, dgw_h + wo, dgw_l + wo, dgb, pedst, nullptr, nullptr, nullptr);
        launch_mma(0, 0, E, 256, 256, y_h, y_l, egw_h + wo, egw_l + wo, egb, pee, nullptr, nullptr, nullptr);

        zero(pagg, (long)N * 256);
        edge_gate_agg<<<(E + 3) / 4, 256>>>(E, px, pesrc, pedst, pee, src, dst, pnl, pagg);
        conv_pad(pagg, ag_h, ag_l, N, 256, 256);

        launch_mma(2, 1, N, 256, 256, ag_h, ag_l, gw_h + wo, gw_l + wo, gb, px, pnr, x_h, x_l);
    }

    // ---- readout MLP ----
    launch_mma(1, 1, N, 1024, 256, x_h, x_l, f1w_h, f1w_l, fc1_b, nullptr, nullptr, f1_h, f1_l);
    launch_mma(1, 1, N, 2048, 1024, f1_h, f1_l, f2w_h, f2w_l, fc2_b, nullptr, nullptr, f2_h, f2_l);
    launch_mma(1, 0, N, 10000, 2048, f2_h, f2_l, f3w_h, f3w_l, fc3_b, (float*)d_out, nullptr, nullptr, nullptr);
}

// round 9
// speedup vs baseline: 3.3098x; 1.0210x over previous
#include <cuda_runtime.h>
#include <cuda_bf16.h>
#include <stdint.h>
#include <math.h>

// ---------------- problem-size constants (fixed by the benchmark) ----------------
#define NMAXV 5000
#define EMAXV 160000
#define HD 256

// ---------------- fp32 scratch ----------------
__device__ float g_x   [NMAXV * 256];
__device__ float g_pre [NMAXV * 256];
__device__ float g_gate[NMAXV * 512];   // [node][0:256]=src gate, [256:512]=dst gate
__device__ float g_agg [NMAXV * 256];
__device__ float g_bond[EMAXV];
__device__ float g_h1  [EMAXV * 64];
__device__ float g_y   [EMAXV * 256];
__device__ float g_ee  [EMAXV * 256];
__device__ float g_degs[NMAXV];
__device__ float g_degd[NMAXV];
__device__ float g_nl  [NMAXV];
__device__ float g_nr  [NMAXV];
__device__ float g_bps [128 * 256];   // BN partial sums [chunk][C]
__device__ float g_bpq [128 * 256];   // BN partial sumsq
__device__ float g_mean[256];
__device__ float g_rstd[256];
__device__ float g_gateb[4 * 512];    // combined sg_b|dg_b per layer

// ---------------- bf16 split (hi/lo) scratch: activations ----------------
__device__ __nv_bfloat16 g_xa_hi[NMAXV * 96],    g_xa_lo[NMAXV * 96];
__device__ __nv_bfloat16 g_x_hi [NMAXV * 256],   g_x_lo [NMAXV * 256];
__device__ __nv_bfloat16 g_agg_hi[NMAXV * 256],  g_agg_lo[NMAXV * 256];
__device__ __nv_bfloat16 g_fc1_hi[NMAXV * 1024], g_fc1_lo[NMAXV * 1024];
__device__ __nv_bfloat16 g_fc2_hi[NMAXV * 2048], g_fc2_lo[NMAXV * 2048];
__device__ __nv_bfloat16 g_rbf_hi[EMAXV * 80],   g_rbf_lo[EMAXV * 80];
__device__ __nv_bfloat16 g_h1_hi [EMAXV * 64],   g_h1_lo [EMAXV * 64];
__device__ __nv_bfloat16 g_y_hi  [EMAXV * 256],  g_y_lo  [EMAXV * 256];

// ---------------- bf16 split scratch: transposed weights [N][Kpad] ----------------
__device__ __nv_bfloat16 g_aewT_hi [256 * 96],    g_aewT_lo [256 * 96];
__device__ __nv_bfloat16 g_ee1wT_hi[64 * 80],     g_ee1wT_lo[64 * 80];
__device__ __nv_bfloat16 g_ee2wT_hi[256 * 64],    g_ee2wT_lo[256 * 64];
__device__ __nv_bfloat16 g_gatewT_hi[4 * 512 * 256], g_gatewT_lo[4 * 512 * 256]; // sg|dg stacked
__device__ __nv_bfloat16 g_egwT_hi [4 * 256 * 256], g_egwT_lo [4 * 256 * 256];
__device__ __nv_bfloat16 g_gwT_hi  [4 * 256 * 256], g_gwT_lo  [4 * 256 * 256];
__device__ __nv_bfloat16 g_fc1wT_hi[1024 * 256],  g_fc1wT_lo[1024 * 256];
__device__ __nv_bfloat16 g_fc2wT_hi[2048 * 1024], g_fc2wT_lo[2048 * 1024];
__device__ __nv_bfloat16 g_fc3wT_hi[10000 * 2048],g_fc3wT_lo[10000 * 2048];

// ---------------- small utility kernels ----------------
__global__ void fill_kernel(float* p, int n, float v) {
    int i = blockIdx.x * blockDim.x + threadIdx.x;
    if (i < n) p[i] = v;
}

__global__ void gate_bias_concat(const float* __restrict__ sgb, const float* __restrict__ dgb,
                                 float* out) {
    int i = blockIdx.x * blockDim.x + threadIdx.x;  // 4*512
    if (i < 4 * 512) {
        int layer = i >> 9;
        int c = i & 511;
        out[i] = (c < 256) ? sgb[layer * 256 + c] : dgb[layer * 256 + (c - 256)];
    }
}

__global__ void deg_kernel(int E, const int* __restrict__ src, const int* __restrict__ dst,
                           float* degs, float* degd) {
    int e = blockIdx.x * blockDim.x + threadIdx.x;
    if (e < E) {
        atomicAdd(&degs[src[e]], 1.0f);
        atomicAdd(&degd[dst[e]], 1.0f);
    }
}

__global__ void norm_kernel(int N, const float* __restrict__ degs, const float* __restrict__ degd,
                            float* nl, float* nr) {
    int i = blockIdx.x * blockDim.x + threadIdx.x;
    if (i < N) {
        nl[i] = rsqrtf(fmaxf(degs[i], 1.0f));
        nr[i] = rsqrtf(fmaxf(degd[i], 1.0f));
    }
}

__global__ void bond_kernel(int E, const float* __restrict__ r, float* bond) {
    int e = blockIdx.x * blockDim.x + threadIdx.x;
    if (e < E) {
        float a = r[e * 3 + 0], b = r[e * 3 + 1], c = r[e * 3 + 2];
        bond[e] = sqrtf(a * a + b * b + c * c);
    }
}

// RBF with fused hi/lo split output
__global__ void rbf_split_kernel(int total, const float* __restrict__ bond,
                                 __nv_bfloat16* __restrict__ hi, __nv_bfloat16* __restrict__ lo) {
    int idx = blockIdx.x * blockDim.x + threadIdx.x;
    if (idx < total) {
        int e = idx / 80;
        int j = idx - e * 80;
        const float gamma = 79.0f / 8.0f;
        float cj = (8.0f / 79.0f) * (float)j;
        float d = bond[e] - cj;
        float v = expf(-gamma * d * d);
        __nv_bfloat16 h = __float2bfloat16(v);
        hi[idx] = h;
        lo[idx] = __float2bfloat16(v - __bfloat162float(h));
    }
}

// split fp32 -> (hi, lo) bf16 with column padding [M x K] -> [M x Kp]
__global__ void conv_pad_kernel(const float* __restrict__ src,
                                __nv_bfloat16* __restrict__ hi, __nv_bfloat16* __restrict__ lo,
                                int M, int K, int Kp) {
    long idx = (long)blockIdx.x * blockDim.x + threadIdx.x;
    long total = (long)M * Kp;
    if (idx >= total) return;
    int r = (int)(idx / Kp);
    int c = (int)(idx - (long)r * Kp);
    float v = (c < K) ? src[(long)r * K + c] : 0.0f;
    __nv_bfloat16 h = __float2bfloat16(v);
    hi[idx] = h;
    lo[idx] = __float2bfloat16(v - __bfloat162float(h));
}

// transpose + split: W[K x N] fp32 -> WT hi/lo [N x Kp] bf16
__global__ void transconv_kernel(const float* __restrict__ W,
                                 __nv_bfloat16* __restrict__ Thi, __nv_bfloat16* __restrict__ Tlo,
                                 int K, int N, int Kp) {
    __shared__ float t[32][33];
    int k0 = blockIdx.y * 32, n0 = blockIdx.x * 32;
    int tx = threadIdx.x, ty = threadIdx.y; // 32 x 8
    #pragma unroll
    for (int i = ty; i < 32; i += 8) {
        int k = k0 + i, n = n0 + tx;
        t[i][tx] = (k < K && n < N) ? W[(long)k * N + n] : 0.0f;
    }
    __syncthreads();
    #pragma unroll
    for (int i = ty; i < 32; i += 8) {
        int n = n0 + i, k = k0 + tx;
        if (n < N && k < Kp) {
            float v = t[tx][i];
            __nv_bfloat16 h = __float2bfloat16(v);
            Thi[(long)n * Kp + k] = h;
            Tlo[(long)n * Kp + k] = __float2bfloat16(v - __bfloat162float(h));
        }
    }
}

// ---------------- BatchNorm (training-mode batch stats) ----------------
__global__ void bn_stats_partial(int M, int C, const float* __restrict__ h,
                                 float* psum, float* psumsq) {
    int c = blockIdx.x * 32 + threadIdx.x;
    int rowsPerChunk = (M + gridDim.y - 1) / gridDim.y;
    int r0 = blockIdx.y * rowsPerChunk;
    int r1 = min(M, r0 + rowsPerChunk);
    float s = 0.f, s2 = 0.f;
    if (c < C) {
        for (int r = r0 + threadIdx.y; r < r1; r += 8) {
            float v = h[(long)r * C + c];
            s += v; s2 += v * v;
        }
    }
    __shared__ float sh[2][8][32];
    sh[0][threadIdx.y][threadIdx.x] = s;
    sh[1][threadIdx.y][threadIdx.x] = s2;
    __syncthreads();
    if (threadIdx.y == 0 && c < C) {
        float ts = 0.f, t2 = 0.f;
        #pragma unroll
        for (int i = 0; i < 8; i++) { ts += sh[0][i][threadIdx.x]; t2 += sh[1][i][threadIdx.x]; }
        psum[blockIdx.y * C + c] = ts;
        psumsq[blockIdx.y * C + c] = t2;
    }
}

__global__ void bn_finalize(int C, int chunks, float invM,
                            const float* __restrict__ psum, const float* __restrict__ psumsq,
                            float* mean, float* rstd) {
    int c = blockIdx.x * blockDim.x + threadIdx.x;
    if (c < C) {
        float s = 0.f, s2 = 0.f;
        for (int k = 0; k < chunks; k++) { s += psum[k * C + c]; s2 += psumsq[k * C + c]; }
        float m = s * invM;
        float var = fmaxf(s2 * invM - m * m, 0.0f);
        mean[c] = m;
        rstd[c] = rsqrtf(var + 1e-5f);
    }
}

__global__ void bn_apply_relu_split(long total, int C, const float* __restrict__ h,
                                    const float* __restrict__ mean, const float* __restrict__ rstd,
                                    const float* __restrict__ g, const float* __restrict__ beta,
                                    float* outf,
                                    __nv_bfloat16* __restrict__ ohi, __nv_bfloat16* __restrict__ olo) {
    long idx = (long)blockIdx.x * blockDim.x + threadIdx.x;
    if (idx < total) {
        int c = (int)(idx % C);
        float v = g[c] * (h[idx] - mean[c]) * rstd[c] + beta[c];
        v = fmaxf(v, 0.0f);
        if (outf) outf[idx] = v;
        __nv_bfloat16 hb = __float2bfloat16(v);
        ohi[idx] = hb;
        olo[idx] = __float2bfloat16(v - __bfloat162float(hb));
    }
}

// ---------------- edge gate + scatter-aggregate (float4, 4 edges/block) ----------------
// gate layout: gate[node*512 + 0:256] = src-gate, [256:512] = dst-gate
__global__ void edge_gate_agg(int E, const float* __restrict__ x,
                              const float* __restrict__ gate,
                              const float* __restrict__ ee,
                              const int* __restrict__ src, const int* __restrict__ dst,
                              const float* __restrict__ nl, float* agg) {
    int e = blockIdx.x * 4 + (threadIdx.x >> 6);
    if (e >= E) return;
    int j = (threadIdx.x & 63) * 4;
    int s = src[e], d = dst[e];
    float nls = nl[s];
    float4 es = *(const float4*)&gate[s * 512 + j];
    float4 ed = *(const float4*)&gate[d * 512 + 256 + j];
    float4 ev = *(const float4*)&ee[(long)e * HD + j];
    float4 xv = *(const float4*)&x[s * HD + j];
    float m0 = xv.x * nls / (1.0f + expf(-(es.x + ed.x + ev.x)));
    float m1 = xv.y * nls / (1.0f + expf(-(es.y + ed.y + ev.y)));
    float m2 = xv.z * nls / (1.0f + expf(-(es.z + ed.z + ev.z)));
    float m3 = xv.w * nls / (1.0f + expf(-(es.w + ed.w + ev.w)));
    float* a = &agg[d * HD + j];
    atomicAdd(a + 0, m0);
    atomicAdd(a + 1, m1);
    atomicAdd(a + 2, m2);
    atomicAdd(a + 3, m3);
}

// ---------------- split-bf16 tensor-core GEMM (3-stage cp.async, 64x64 warp tile) --
__device__ __forceinline__ void cp16(uint32_t saddr, const void* gaddr, bool valid) {
    int sz = valid ? 16 : 0;
    asm volatile("cp.async.cg.shared.global [%0], [%1], 16, %2;\n"
                 :: "r"(saddr), "l"(gaddr), "r"(sz));
}

#define LDSM4(R0, R1, R2, R3, addr) \
    asm volatile("ldmatrix.sync.aligned.m8n8.x4.shared.b16 {%0,%1,%2,%3}, [%4];" \
                 : "=r"(R0), "=r"(R1), "=r"(R2), "=r"(R3) : "r"(addr))

#define MMA16816(d, a, b) \
    asm volatile("mma.sync.aligned.m16n8k16.row.col.f32.bf16.bf16.f32 " \
                 "{%0,%1,%2,%3}, {%4,%5,%6,%7}, {%8,%9}, {%0,%1,%2,%3};" \
                 : "+f"((d)[0]), "+f"((d)[1]), "+f"((d)[2]), "+f"((d)[3]) \
                 : "r"((a)[0]), "r"((a)[1]), "r"((a)[2]), "r"((a)[3]), \
                   "r"((b)[0]), "r"((b)[1]))

#define GEMM_SMEM_ELEMS (3 * 2 * 128 * 24)
#define GEMM_SMEM_BYTES (2 * GEMM_SMEM_ELEMS * 2)

// swapg: if 1, blockIdx.x indexes M (B-tile shared by consecutive blocks; B read once)
template <int EPI, int SPLIT>
__global__ __launch_bounds__(128, 2) void mma_gemm(
    int M, int N, int K, int swapg,
    const __nv_bfloat16* __restrict__ Ahi, const __nv_bfloat16* __restrict__ Alo,
    const __nv_bfloat16* __restrict__ Bhi, const __nv_bfloat16* __restrict__ Blo,
    const float* __restrict__ bias, float* __restrict__ C,
    const float* __restrict__ norm,
    __nv_bfloat16* __restrict__ Ohi, __nv_bfloat16* __restrict__ Olo) {
    extern __shared__ __nv_bfloat16 dsm[];
    __nv_bfloat16 (*sA)[2][128][24] = reinterpret_cast<__nv_bfloat16 (*)[2][128][24]>(dsm);
    __nv_bfloat16 (*sB)[2][128][24] = reinterpret_cast<__nv_bfloat16 (*)[2][128][24]>(dsm + GEMM_SMEM_ELEMS);

    const int tid = threadIdx.x;
    const int m0 = (swapg ? blockIdx.x : blockIdx.y) * 128;
    const int n0 = (swapg ? blockIdx.y : blockIdx.x) * 128;
    const int wid = tid >> 5, lane = tid & 31;
    const int wm = (wid & 1) * 64;
    const int wn = (wid >> 1) * 64;

    float acc[4][8][4];
    #pragma unroll
    for (int i = 0; i < 4; i++)
        #pragma unroll
        for (int j = 0; j < 8; j++)
            #pragma unroll
            for (int q = 0; q < 4; q++) acc[i][j][q] = 0.0f;

    const int nk = K / 16;

    auto load_stage = [&](int s, int k0) {
        #pragma unroll
        for (int it = 0; it < 8; it++) {
            int t = tid + it * 128;
            int half = t >> 8;            // 0:Ahi 1:Alo 2:Bhi 3:Blo
            int f = t & 255;
            int row = f >> 1;
            int cc = (f & 1) * 8;
            if (half < 2) {
                bool v = (m0 + row) < M;
                int rr = v ? (m0 + row) : 0;
                const __nv_bfloat16* g = (half == 0 ? Ahi : Alo) + (size_t)rr * K + k0 + cc;
                uint32_t sa = (uint32_t)__cvta_generic_to_shared(&sA[s][half][row][cc]);
                cp16(sa, g, v);
            } else {
                bool v = (n0 + row) < N;
                int rr = v ? (n0 + row) : 0;
                const __nv_bfloat16* g = (half == 2 ? Bhi : Blo) + (size_t)rr * K + k0 + cc;
                uint32_t sa = (uint32_t)__cvta_generic_to_shared(&sB[s][half - 2][row][cc]);
                cp16(sa, g, v);
            }
        }
        asm volatile("cp.async.commit_group;\n");
    };

    load_stage(0, 0);
    if (nk > 1) load_stage(1, 16);
    else asm volatile("cp.async.commit_group;\n");

    for (int kt = 0; kt < nk; kt++) {
        int cur = kt % 3;
        asm volatile("cp.async.wait_group 1;\n");
        __syncthreads();

        uint32_t afh[4][4], afl[4][4];
        #pragma unroll
        for (int mi = 0; mi < 4; mi++) {
            int row = wm + mi * 16 + (lane & 15);
            int col = ((lane >> 4) & 1) * 8;
            uint32_t ah = (uint32_t)__cvta_generic_to_shared(&sA[cur][0][row][col]);
            uint32_t al = (uint32_t)__cvta_generic_to_shared(&sA[cur][1][row][col]);
            LDSM4(afh[mi][0], afh[mi][1], afh[mi][2], afh[mi][3], ah);
            LDSM4(afl[mi][0], afl[mi][1], afl[mi][2], afl[mi][3], al);
        }
        uint32_t bfh[8][2], bfl[8][2];
        #pragma unroll
        for (int p = 0; p < 4; p++) {
            int row = wn + (2 * p + ((lane >> 4) & 1)) * 8 + (lane & 7);
            int col = ((lane >> 3) & 1) * 8;
            uint32_t bh = (uint32_t)__cvta_generic_to_shared(&sB[cur][0][row][col]);
            uint32_t bl = (uint32_t)__cvta_generic_to_shared(&sB[cur][1][row][col]);
            LDSM4(bfh[2*p][0], bfh[2*p][1], bfh[2*p+1][0], bfh[2*p+1][1], bh);
            LDSM4(bfl[2*p][0], bfl[2*p][1], bfl[2*p+1][0], bfl[2*p+1][1], bl);
        }
        #pragma unroll
        for (int mi = 0; mi < 4; mi++)
            #pragma unroll
            for (int ni = 0; ni < 8; ni++) {
                MMA16816(acc[mi][ni], afh[mi], bfh[ni]);
                MMA16816(acc[mi][ni], afh[mi], bfl[ni]);
                MMA16816(acc[mi][ni], afl[mi], bfh[ni]);
            }

        if (kt + 2 < nk) load_stage((kt + 2) % 3, (kt + 2) * 16);
        else asm volatile("cp.async.commit_group;\n");
    }

    // ---- epilogue ----
    #pragma unroll
    for (int mi = 0; mi < 4; mi++) {
        #pragma unroll
        for (int half = 0; half < 2; half++) {
            int r = m0 + wm + mi * 16 + (lane >> 2) + half * 8;
            if (r >= M) continue;
            float nr = (EPI == 2) ? norm[r] : 0.0f;
            #pragma unroll
            for (int ni = 0; ni < 8; ni++) {
                int c = n0 + wn + ni * 8 + (lane & 3) * 2;
                if (c >= N) continue;
                long idx = (long)r * N + c;
                float a0 = acc[mi][ni][half * 2 + 0];
                float a1 = acc[mi][ni][half * 2 + 1];
                float v0, v1;
                if (EPI == 0) {
                    v0 = a0 + bias[c]; v1 = a1 + bias[c + 1];
                    C[idx] = v0; C[idx + 1] = v1;
                } else if (EPI == 1) {
                    v0 = fmaxf(a0 + bias[c], 0.0f); v1 = fmaxf(a1 + bias[c + 1], 0.0f);
                    if (!SPLIT) { C[idx] = v0; C[idx + 1] = v1; }
                } else {
                    v0 = C[idx]     + a0 * nr + bias[c];
                    v1 = C[idx + 1] + a1 * nr + bias[c + 1];
                    C[idx] = v0; C[idx + 1] = v1;
                }
                if (SPLIT) {
                    __nv_bfloat16 h0 = __float2bfloat16(v0);
                    __nv_bfloat16 h1 = __float2bfloat16(v1);
                    __nv_bfloat162 hh; hh.x = h0; hh.y = h1;
                    __nv_bfloat162 ll;
                    ll.x = __float2bfloat16(v0 - __bfloat162float(h0));
                    ll.y = __float2bfloat16(v1 - __bfloat162float(h1));
                    *reinterpret_cast<__nv_bfloat162*>(&Ohi[idx]) = hh;
                    *reinterpret_cast<__nv_bfloat162*>(&Olo[idx]) = ll;
                }
            }
        }
    }
}

// ---------------- host-side helpers ----------------
static float* symaddr(const void* sym) {
    void* p = nullptr;
    cudaGetSymbolAddress(&p, sym);
    return (float*)p;
}
static __nv_bfloat16* symaddr_bf(const void* sym) {
    void* p = nullptr;
    cudaGetSymbolAddress(&p, sym);
    return (__nv_bfloat16*)p;
}

static inline void launch_mma(int epi, int split, int swapg, int M, int N, int K,
                              const __nv_bfloat16* Ahi, const __nv_bfloat16* Alo,
                              const __nv_bfloat16* Bhi, const __nv_bfloat16* Blo,
                              const float* bias, float* C, const float* norm,
                              __nv_bfloat16* Ohi, __nv_bfloat16* Olo) {
    int mt = (M + 127) / 128, nt = (N + 127) / 128;
    dim3 grid(swapg ? mt : nt, swapg ? nt : mt);
    if (epi == 0) {
        cudaFuncSetAttribute(mma_gemm<0,0>, cudaFuncAttributeMaxDynamicSharedMemorySize, GEMM_SMEM_BYTES);
        mma_gemm<0,0><<<grid, 128, GEMM_SMEM_BYTES>>>(M, N, K, swapg, Ahi, Alo, Bhi, Blo, bias, C, norm, Ohi, Olo);
    } else if (epi == 1 && split) {
        cudaFuncSetAttribute(mma_gemm<1,1>, cudaFuncAttributeMaxDynamicSharedMemorySize, GEMM_SMEM_BYTES);
        mma_gemm<1,1><<<grid, 128, GEMM_SMEM_BYTES>>>(M, N, K, swapg, Ahi, Alo, Bhi, Blo, bias, C, norm, Ohi, Olo);
    } else if (epi == 1) {
        cudaFuncSetAttribute(mma_gemm<1,0>, cudaFuncAttributeMaxDynamicSharedMemorySize, GEMM_SMEM_BYTES);
        mma_gemm<1,0><<<grid, 128, GEMM_SMEM_BYTES>>>(M, N, K, swapg, Ahi, Alo, Bhi, Blo, bias, C, norm, Ohi, Olo);
    } else {
        cudaFuncSetAttribute(mma_gemm<2,1>, cudaFuncAttributeMaxDynamicSharedMemorySize, GEMM_SMEM_BYTES);
        mma_gemm<2,1><<<grid, 128, GEMM_SMEM_BYTES>>>(M, N, K, swapg, Ahi, Alo, Bhi, Blo, bias, C, norm, Ohi, Olo);
    }
}

static inline void zero(float* p, long n) {
    fill_kernel<<<(int)((n + 255) / 256), 256>>>(p, (int)n, 0.0f);
}

static inline void conv_pad(const float* src, __nv_bfloat16* hi, __nv_bfloat16* lo,
                            int M, int K, int Kp) {
    long total = (long)M * Kp;
    conv_pad_kernel<<<(int)((total + 255) / 256), 256>>>(src, hi, lo, M, K, Kp);
}

static inline void transconv(const float* W, __nv_bfloat16* Thi, __nv_bfloat16* Tlo,
                             int K, int N, int Kp) {
    dim3 grid((N + 31) / 32, (Kp + 31) / 32);
    transconv_kernel<<<grid, dim3(32, 8)>>>(W, Thi, Tlo, K, N, Kp);
}

static void run_bn_split(int M, int C, const float* h, const float* g, const float* beta,
                         float* outf, __nv_bfloat16* ohi, __nv_bfloat16* olo,
                         float* pbs, float* pbq, float* pmean, float* prstd) {
    int chunks = (M > 20000) ? 128 : 32;
    dim3 grid(C / 32, chunks);
    dim3 blk(32, 8);
    bn_stats_partial<<<grid, blk>>>(M, C, h, pbs, pbq);
    bn_finalize<<<(C + 127) / 128, 128>>>(C, chunks, 1.0f / (float)M, pbs, pbq, pmean, prstd);
    long total = (long)M * C;
    bn_apply_relu_split<<<(int)((total + 255) / 256), 256>>>(total, C, h, pmean, prstd, g, beta,
                                                             outf, ohi, olo);
}

extern "C" void kernel_launch(void* const* d_in, const int* in_sizes, int n_in,
                              void* d_out, int out_size) {
    const float* atom_features = (const float*)d_in[0];
    const float* r             = (const float*)d_in[1];
    const int*   src           = (const int*)d_in[2];
    const int*   dst           = (const int*)d_in[3];
    const float* ae_w   = (const float*)d_in[4];
    const float* ae_b   = (const float*)d_in[5];
    const float* ae_g   = (const float*)d_in[6];
    const float* ae_be  = (const float*)d_in[7];
    const float* ee1_w  = (const float*)d_in[8];
    const float* ee1_b  = (const float*)d_in[9];
    const float* ee1_g  = (const float*)d_in[10];
    const float* ee1_be = (const float*)d_in[11];
    const float* ee2_w  = (const float*)d_in[12];
    const float* ee2_b  = (const float*)d_in[13];
    const float* ee2_g  = (const float*)d_in[14];
    const float* ee2_be = (const float*)d_in[15];
    const float* gcn_w  = (const float*)d_in[16];
    const float* gcn_b  = (const float*)d_in[17];
    const float* sg_w   = (const float*)d_in[18];
    const float* sg_b   = (const float*)d_in[19];
    const float* dg_w   = (const float*)d_in[20];
    const float* dg_b   = (const float*)d_in[21];
    const float* eg_w   = (const float*)d_in[22];
    const float* eg_b   = (const float*)d_in[23];
    const float* fc1_w  = (const float*)d_in[24];
    const float* fc1_b  = (const float*)d_in[25];
    const float* fc2_w  = (const float*)d_in[26];
    const float* fc2_b  = (const float*)d_in[27];
    const float* fc3_w  = (const float*)d_in[28];
    const float* fc3_b  = (const float*)d_in[29];

    const int N = in_sizes[0] / 92;
    const int E = in_sizes[2];

    float* px    = symaddr(g_x);
    float* ppre  = symaddr(g_pre);
    float* pgate = symaddr(g_gate);
    float* pagg  = symaddr(g_agg);
    float* pbond = symaddr(g_bond);
    float* ph1   = symaddr(g_h1);
    float* py    = symaddr(g_y);
    float* pee   = symaddr(g_ee);
    float* pdegs = symaddr(g_degs);
    float* pdegd = symaddr(g_degd);
    float* pnl   = symaddr(g_nl);
    float* pnr   = symaddr(g_nr);
    float* pbs   = symaddr(g_bps);
    float* pbq   = symaddr(g_bpq);
    float* pmean = symaddr(g_mean);
    float* prstd = symaddr(g_rstd);
    float* pgb   = symaddr(g_gateb);

    __nv_bfloat16 *xa_h = symaddr_bf(g_xa_hi),  *xa_l = symaddr_bf(g_xa_lo);
    __nv_bfloat16 *x_h  = symaddr_bf(g_x_hi),   *x_l  = symaddr_bf(g_x_lo);
    __nv_bfloat16 *ag_h = symaddr_bf(g_agg_hi), *ag_l = symaddr_bf(g_agg_lo);
    __nv_bfloat16 *f1_h = symaddr_bf(g_fc1_hi), *f1_l = symaddr_bf(g_fc1_lo);
    __nv_bfloat16 *f2_h = symaddr_bf(g_fc2_hi), *f2_l = symaddr_bf(g_fc2_lo);
    __nv_bfloat16 *rb_h = symaddr_bf(g_rbf_hi), *rb_l = symaddr_bf(g_rbf_lo);
    __nv_bfloat16 *h1_h = symaddr_bf(g_h1_hi),  *h1_l = symaddr_bf(g_h1_lo);
    __nv_bfloat16 *y_h  = symaddr_bf(g_y_hi),   *y_l  = symaddr_bf(g_y_lo);

    __nv_bfloat16 *aew_h = symaddr_bf(g_aewT_hi),  *aew_l = symaddr_bf(g_aewT_lo);
    __nv_bfloat16 *e1w_h = symaddr_bf(g_ee1wT_hi), *e1w_l = symaddr_bf(g_ee1wT_lo);
    __nv_bfloat16 *e2w_h = symaddr_bf(g_ee2wT_hi), *e2w_l = symaddr_bf(g_ee2wT_lo);
    __nv_bfloat16 *gtw_h = symaddr_bf(g_gatewT_hi),*gtw_l = symaddr_bf(g_gatewT_lo);
    __nv_bfloat16 *egw_h = symaddr_bf(g_egwT_hi),  *egw_l = symaddr_bf(g_egwT_lo);
    __nv_bfloat16 *gw_h  = symaddr_bf(g_gwT_hi),   *gw_l  = symaddr_bf(g_gwT_lo);
    __nv_bfloat16 *f1w_h = symaddr_bf(g_fc1wT_hi), *f1w_l = symaddr_bf(g_fc1wT_lo);
    __nv_bfloat16 *f2w_h = symaddr_bf(g_fc2wT_hi), *f2w_l = symaddr_bf(g_fc2wT_lo);
    __nv_bfloat16 *f3w_h = symaddr_bf(g_fc3wT_hi), *f3w_l = symaddr_bf(g_fc3wT_lo);

    // ---- weight transpose + split ----
    transconv(ae_w, aew_h, aew_l, 92, 256, 96);
    transconv(ee1_w, e1w_h, e1w_l, 80, 64, 80);
    transconv(ee2_w, e2w_h, e2w_l, 64, 256, 64);
    for (int i = 0; i < 4; i++) {
        long wo = (long)i * 256 * 256;
        long go = (long)i * 512 * 256;
        // gate GEMM weight: [512 rows][256 k] = sg rows then dg rows
        transconv(sg_w + wo, gtw_h + go, gtw_l + go, 256, 256, 256);
        transconv(dg_w + wo, gtw_h + go + 256 * 256, gtw_l + go + 256 * 256, 256, 256, 256);
        transconv(eg_w + wo, egw_h + wo, egw_l + wo, 256, 256, 256);
        transconv(gcn_w + wo, gw_h + wo, gw_l + wo, 256, 256, 256);
    }
    transconv(fc1_w, f1w_h, f1w_l, 256, 1024, 256);
    transconv(fc2_w, f2w_h, f2w_l, 1024, 2048, 1024);
    transconv(fc3_w, f3w_h, f3w_l, 2048, 10000, 2048);
    gate_bias_concat<<<8, 256>>>(sg_b, dg_b, pgb);

    // ---- degrees & norms ----
    zero(pdegs, N); zero(pdegd, N);
    deg_kernel<<<(E + 255) / 256, 256>>>(E, src, dst, pdegs, pdegd);
    norm_kernel<<<(N + 255) / 256, 256>>>(N, pdegs, pdegd, pnl, pnr);

    // ---- atom embedding MLP ----
    conv_pad(atom_features, xa_h, xa_l, N, 92, 96);
    launch_mma(0, 0, 0, N, 256, 96, xa_h, xa_l, aew_h, aew_l, ae_b, ppre, nullptr, nullptr, nullptr);
    run_bn_split(N, 256, ppre, ae_g, ae_be, px, x_h, x_l, pbs, pbq, pmean, prstd);

    // ---- RBF + edge embedding MLPs ----
    bond_kernel<<<(E + 255) / 256, 256>>>(E, r, pbond);
    {
        long tot = (long)E * 80;
        rbf_split_kernel<<<(int)((tot + 255) / 256), 256>>>((int)tot, pbond, rb_h, rb_l);
    }
    launch_mma(0, 0, 0, E, 64, 80, rb_h, rb_l, e1w_h, e1w_l, ee1_b, ph1, nullptr, nullptr, nullptr);
    run_bn_split(E, 64, ph1, ee1_g, ee1_be, nullptr, h1_h, h1_l, pbs, pbq, pmean, prstd);
    launch_mma(0, 0, 0, E, 256, 64, h1_h, h1_l, e2w_h, e2w_l, ee2_b, py, nullptr, nullptr, nullptr);
    run_bn_split(E, 256, py, ee2_g, ee2_be, nullptr, y_h, y_l, pbs, pbq, pmean, prstd);

    // ---- 4 gated GCN layers ----
    for (int i = 0; i < 4; i++) {
        long wo = (long)i * 256 * 256;
        long go = (long)i * 512 * 256;
        const float* egb = eg_b + i * 256;
        const float* gb  = gcn_b + i * 256;

        // fused src+dst gate GEMM: [N x 512]
        launch_mma(0, 0, 0, N, 512, 256, x_h, x_l, gtw_h + go, gtw_l + go, pgb + i * 512, pgate, nullptr, nullptr, nullptr);
        launch_mma(0, 0, 0, E, 256, 256, y_h, y_l, egw_h + wo, egw_l + wo, egb, pee, nullptr, nullptr, nullptr);

        zero(pagg, (long)N * 256);
        edge_gate_agg<<<(E + 3) / 4, 256>>>(E, px, pgate, pee, src, dst, pnl, pagg);
        conv_pad(pagg, ag_h, ag_l, N, 256, 256);

        launch_mma(2, 1, 0, N, 256, 256, ag_h, ag_l, gw_h + wo, gw_l + wo, gb, px, pnr, x_h, x_l);
    }

    // ---- readout MLP (grid-swapped for big-B L2 behavior on fc2/fc3) ----
    launch_mma(1, 1, 0, N, 1024, 256, x_h, x_l, f1w_h, f1w_l, fc1_b, nullptr, nullptr, f1_h, f1_l);
    launch_mma(1, 1, 1, N, 2048, 1024, f1_h, f1_l, f2w_h, f2w_l, fc2_b, nullptr, nullptr, f2_h, f2_l);
    launch_mma(1, 0, 1, N, 10000, 2048, f2_h, f2_l, f3w_h, f3w_l, fc3_b, (float*)d_out, nullptr, nullptr, nullptr);
}

// round 12
// speedup vs baseline: 3.4757x; 1.0501x over previous
#include <cuda_runtime.h>
#include <cuda.h>
#include <cuda_bf16.h>
#include <stdint.h>
#include <math.h>

// ---------------- problem-size constants ----------------
#define NMAXV 5000
#define NPAD  5120
#define EMAXV 160000
#define HD 256

// ---------------- fp32 scratch ----------------
__device__ float g_x   [NMAXV * 256];
__device__ float g_pre [NMAXV * 256];
__device__ float g_gate[NMAXV * 512];
__device__ float g_agg [NMAXV * 256];
__device__ float g_bond[EMAXV];
__device__ float g_h1  [EMAXV * 64];
__device__ float g_y   [EMAXV * 256];
__device__ float g_degs[NMAXV];
__device__ float g_degd[NMAXV];
__device__ float g_nl  [NMAXV];
__device__ float g_nr  [NMAXV];
__device__ float g_bps [128 * 256];
__device__ float g_bpq [128 * 256];
__device__ float g_mean[256];
__device__ float g_rstd[256];
__device__ float g_gateb[4 * 512];
__device__ float g_ee  [EMAXV * 256];

// ---------------- bf16 split activations (rows padded; static zero-init) -------
__device__ __align__(128) __nv_bfloat16 g_xa_hi[NPAD * 128];
__device__ __align__(128) __nv_bfloat16 g_xa_lo[NPAD * 128];
__device__ __align__(128) __nv_bfloat16 g_x_hi [NPAD * 256];
__device__ __align__(128) __nv_bfloat16 g_x_lo [NPAD * 256];
__device__ __align__(128) __nv_bfloat16 g_agg_hi[NPAD * 256];
__device__ __align__(128) __nv_bfloat16 g_agg_lo[NPAD * 256];
__device__ __align__(128) __nv_bfloat16 g_fc1_hi[NPAD * 1024];
__device__ __align__(128) __nv_bfloat16 g_fc1_lo[NPAD * 1024];
__device__ __align__(128) __nv_bfloat16 g_fc2_hi[NPAD * 2048];
__device__ __align__(128) __nv_bfloat16 g_fc2_lo[NPAD * 2048];
__device__ __align__(128) __nv_bfloat16 g_rbf_hi[EMAXV * 128];
__device__ __align__(128) __nv_bfloat16 g_rbf_lo[EMAXV * 128];
__device__ __align__(128) __nv_bfloat16 g_h1_hi [EMAXV * 64];
__device__ __align__(128) __nv_bfloat16 g_h1_lo [EMAXV * 64];
__device__ __align__(128) __nv_bfloat16 g_y_hi  [EMAXV * 256];
__device__ __align__(128) __nv_bfloat16 g_y_lo  [EMAXV * 256];

// ---------------- bf16 split transposed weights [rowsPad][Kpad] ----------------
__device__ __align__(128) __nv_bfloat16 g_aewT_hi [256 * 128];
__device__ __align__(128) __nv_bfloat16 g_aewT_lo [256 * 128];
__device__ __align__(128) __nv_bfloat16 g_ee1wT_hi[128 * 128];
__device__ __align__(128) __nv_bfloat16 g_ee1wT_lo[128 * 128];
__device__ __align__(128) __nv_bfloat16 g_ee2wT_hi[256 * 64];
__device__ __align__(128) __nv_bfloat16 g_ee2wT_lo[256 * 64];
__device__ __align__(128) __nv_bfloat16 g_gatewT_hi[4 * 512 * 256];
__device__ __align__(128) __nv_bfloat16 g_gatewT_lo[4 * 512 * 256];
__device__ __align__(128) __nv_bfloat16 g_egwT_hi [4 * 256 * 256];
__device__ __align__(128) __nv_bfloat16 g_egwT_lo [4 * 256 * 256];
__device__ __align__(128) __nv_bfloat16 g_gwT_hi  [4 * 256 * 256];
__device__ __align__(128) __nv_bfloat16 g_gwT_lo  [4 * 256 * 256];
__device__ __align__(128) __nv_bfloat16 g_fc1wT_hi[1024 * 256];
__device__ __align__(128) __nv_bfloat16 g_fc1wT_lo[1024 * 256];
__device__ __align__(128) __nv_bfloat16 g_fc2wT_hi[2048 * 1024];
__device__ __align__(128) __nv_bfloat16 g_fc2wT_lo[2048 * 1024];
__device__ __align__(128) __nv_bfloat16 g_fc3wT_hi[10112 * 2048];
__device__ __align__(128) __nv_bfloat16 g_fc3wT_lo[10112 * 2048];

// ---------------- small utility kernels ----------------
__global__ void fill_kernel(float* p, int n, float v) {
    int i = blockIdx.x * blockDim.x + threadIdx.x;
    if (i < n) p[i] = v;
}

__global__ void gate_bias_concat(const float* __restrict__ sgb, const float* __restrict__ dgb,
                                 float* out) {
    int i = blockIdx.x * blockDim.x + threadIdx.x;
    if (i < 4 * 512) {
        int layer = i >> 9;
        int c = i & 511;
        out[i] = (c < 256) ? sgb[layer * 256 + c] : dgb[layer * 256 + (c - 256)];
    }
}

__global__ void deg_kernel(int E, const int* __restrict__ src, const int* __restrict__ dst,
                           float* degs, float* degd) {
    int e = blockIdx.x * blockDim.x + threadIdx.x;
    if (e < E) {
        atomicAdd(&degs[src[e]], 1.0f);
        atomicAdd(&degd[dst[e]], 1.0f);
    }
}

__global__ void norm_kernel(int N, const float* __restrict__ degs, const float* __restrict__ degd,
                            float* nl, float* nr) {
    int i = blockIdx.x * blockDim.x + threadIdx.x;
    if (i < N) {
        nl[i] = rsqrtf(fmaxf(degs[i], 1.0f));
        nr[i] = rsqrtf(fmaxf(degd[i], 1.0f));
    }
}

__global__ void bond_kernel(int E, const float* __restrict__ r, float* bond) {
    int e = blockIdx.x * blockDim.x + threadIdx.x;
    if (e < E) {
        float a = r[e * 3 + 0], b = r[e * 3 + 1], c = r[e * 3 + 2];
        bond[e] = sqrtf(a * a + b * b + c * c);
    }
}

__global__ void rbf_split_kernel(int total, const float* __restrict__ bond,
                                 __nv_bfloat16* __restrict__ hi, __nv_bfloat16* __restrict__ lo) {
    int idx = blockIdx.x * blockDim.x + threadIdx.x;
    if (idx < total) {
        int e = idx / 80;
        int j = idx - e * 80;
        const float gamma = 79.0f / 8.0f;
        float cj = (8.0f / 79.0f) * (float)j;
        float d = bond[e] - cj;
        float v = expf(-gamma * d * d);
        __nv_bfloat16 h = __float2bfloat16(v);
        long o = (long)e * 128 + j;
        hi[o] = h;
        lo[o] = __float2bfloat16(v - __bfloat162float(h));
    }
}

__global__ void conv_pad_kernel(const float* __restrict__ src,
                                __nv_bfloat16* __restrict__ hi, __nv_bfloat16* __restrict__ lo,
                                int M, int K, int Kp) {
    long idx = (long)blockIdx.x * blockDim.x + threadIdx.x;
    long total = (long)M * Kp;
    if (idx >= total) return;
    int r = (int)(idx / Kp);
    int c = (int)(idx - (long)r * Kp);
    float v = (c < K) ? src[(long)r * K + c] : 0.0f;
    __nv_bfloat16 h = __float2bfloat16(v);
    hi[idx] = h;
    lo[idx] = __float2bfloat16(v - __bfloat162float(h));
}

__global__ void transconv_kernel(const float* __restrict__ W,
                                 __nv_bfloat16* __restrict__ Thi, __nv_bfloat16* __restrict__ Tlo,
                                 int K, int N, int Kp) {
    __shared__ float t[32][33];
    int k0 = blockIdx.y * 32, n0 = blockIdx.x * 32;
    int tx = threadIdx.x, ty = threadIdx.y;
    #pragma unroll
    for (int i = ty; i < 32; i += 8) {
        int k = k0 + i, n = n0 + tx;
        t[i][tx] = (k < K && n < N) ? W[(long)k * N + n] : 0.0f;
    }
    __syncthreads();
    #pragma unroll
    for (int i = ty; i < 32; i += 8) {
        int n = n0 + i, k = k0 + tx;
        if (n < N && k < Kp) {
            float v = t[tx][i];
            __nv_bfloat16 h = __float2bfloat16(v);
            Thi[(long)n * Kp + k] = h;
            Tlo[(long)n * Kp + k] = __float2bfloat16(v - __bfloat162float(h));
        }
    }
}

// ---------------- BatchNorm ----------------
__global__ void bn_stats_partial(int M, int C, const float* __restrict__ h,
                                 float* psum, float* psumsq) {
    int c = blockIdx.x * 32 + threadIdx.x;
    int rowsPerChunk = (M + gridDim.y - 1) / gridDim.y;
    int r0 = blockIdx.y * rowsPerChunk;
    int r1 = min(M, r0 + rowsPerChunk);
    float s = 0.f, s2 = 0.f;
    if (c < C) {
        for (int r = r0 + threadIdx.y; r < r1; r += 8) {
            float v = h[(long)r * C + c];
            s += v; s2 += v * v;
        }
    }
    __shared__ float sh[2][8][32];
    sh[0][threadIdx.y][threadIdx.x] = s;
    sh[1][threadIdx.y][threadIdx.x] = s2;
    __syncthreads();
    if (threadIdx.y == 0 && c < C) {
        float ts = 0.f, t2 = 0.f;
        #pragma unroll
        for (int i = 0; i < 8; i++) { ts += sh[0][i][threadIdx.x]; t2 += sh[1][i][threadIdx.x]; }
        psum[blockIdx.y * C + c] = ts;
        psumsq[blockIdx.y * C + c] = t2;
    }
}

__global__ void bn_finalize(int C, int chunks, float invM,
                            const float* __restrict__ psum, const float* __restrict__ psumsq,
                            float* mean, float* rstd) {
    int c = blockIdx.x * blockDim.x + threadIdx.x;
    if (c < C) {
        float s = 0.f, s2 = 0.f;
        for (int k = 0; k < chunks; k++) { s += psum[k * C + c]; s2 += psumsq[k * C + c]; }
        float m = s * invM;
        float var = fmaxf(s2 * invM - m * m, 0.0f);
        mean[c] = m;
        rstd[c] = rsqrtf(var + 1e-5f);
    }
}

__global__ void bn_apply_relu_split(long total, int C, const float* __restrict__ h,
                                    const float* __restrict__ mean, const float* __restrict__ rstd,
                                    const float* __restrict__ g, const float* __restrict__ beta,
                                    float* outf,
                                    __nv_bfloat16* __restrict__ ohi, __nv_bfloat16* __restrict__ olo) {
    long idx = (long)blockIdx.x * blockDim.x + threadIdx.x;
    if (idx < total) {
        int c = (int)(idx % C);
        float v = g[c] * (h[idx] - mean[c]) * rstd[c] + beta[c];
        v = fmaxf(v, 0.0f);
        if (outf) outf[idx] = v;
        __nv_bfloat16 hb = __float2bfloat16(v);
        ohi[idx] = hb;
        olo[idx] = __float2bfloat16(v - __bfloat162float(hb));
    }
}

// ---------------- edge gate + scatter-aggregate ----------------
__global__ void edge_gate_agg(int E, const float* __restrict__ x,
                              const float* __restrict__ gate,
                              const float* __restrict__ ee,
                              const int* __restrict__ src, const int* __restrict__ dst,
                              const float* __restrict__ nl, float* agg) {
    int e = blockIdx.x * 4 + (threadIdx.x >> 6);
    if (e >= E) return;
    int j = (threadIdx.x & 63) * 4;
    int s = src[e], d = dst[e];
    float nls = nl[s];
    float4 es = *(const float4*)&gate[s * 512 + j];
    float4 ed = *(const float4*)&gate[d * 512 + 256 + j];
    float4 ev = *(const float4*)&ee[(long)e * HD + j];
    float4 xv = *(const float4*)&x[s * HD + j];
    float m0 = xv.x * nls / (1.0f + expf(-(es.x + ed.x + ev.x)));
    float m1 = xv.y * nls / (1.0f + expf(-(es.y + ed.y + ev.y)));
    float m2 = xv.z * nls / (1.0f + expf(-(es.z + ed.z + ev.z)));
    float m3 = xv.w * nls / (1.0f + expf(-(es.w + ed.w + ev.w)));
    float* a = &agg[d * HD + j];
    atomicAdd(a + 0, m0);
    atomicAdd(a + 1, m1);
    atomicAdd(a + 2, m2);
    atomicAdd(a + 3, m3);
}

// ================= TMA + mma.sync split-bf16 GEMM =================
// C[M x N] = epi( A @ B^T + bias ), A [M][K] hi/lo, B [N][K] hi/lo (row stride K).
// Block 128x128, 256 threads (8 warps, warp tile 64x32).
// K chunk 64, 3-stage TMA (SWIZZLE_128B) + mbarrier ring.

#define MBAR_INIT(addr, cnt) \
    asm volatile("mbarrier.init.shared.b64 [%0], %1;" :: "r"(addr), "r"(cnt) : "memory")
#define MBAR_EXPECT_TX(addr, bytes) \
    asm volatile("mbarrier.arrive.expect_tx.shared.b64 _, [%0], %1;" :: "r"(addr), "r"(bytes) : "memory")

__device__ __forceinline__ void mbar_wait(uint32_t addr, uint32_t parity) {
    asm volatile(
        "{\n\t"
        ".reg .pred P;\n\t"
        "WAITLOOP%=:\n\t"
        "mbarrier.try_wait.parity.acquire.cta.shared::cta.b64 P, [%0], %1, 0x989680;\n\t"
        "@!P bra WAITLOOP%=;\n\t"
        "}"
        :: "r"(addr), "r"(parity) : "memory");
}

#define TMA2D(saddr, mapp, cx, cy, mbar) \
    asm volatile("cp.async.bulk.tensor.2d.shared::cta.global.tile.mbarrier::complete_tx::bytes " \
                 "[%0], [%1, {%2, %3}], [%4];" \
                 :: "r"(saddr), "l"(mapp), "r"(cx), "r"(cy), "r"(mbar) : "memory")

#define LDSM4(R0, R1, R2, R3, addr) \
    asm volatile("ldmatrix.sync.aligned.m8n8.x4.shared.b16 {%0,%1,%2,%3}, [%4];" \
                 : "=r"(R0), "=r"(R1), "=r"(R2), "=r"(R3) : "r"(addr))

#define MMA16816(d, a, b) \
    asm volatile("mma.sync.aligned.m16n8k16.row.col.f32.bf16.bf16.f32 " \
                 "{%0,%1,%2,%3}, {%4,%5,%6,%7}, {%8,%9}, {%0,%1,%2,%3};" \
                 : "+f"((d)[0]), "+f"((d)[1]), "+f"((d)[2]), "+f"((d)[3]) \
                 : "r"((a)[0]), "r"((a)[1]), "r"((a)[2]), "r"((a)[3]), \
                   "r"((b)[0]), "r"((b)[1]))

// swizzled smem address for a 16B-aligned column in a TMA SWIZZLE_128B tile
__device__ __forceinline__ uint32_t swadr(uint32_t base, int rl, int cb) {
    return base + rl * 128 + (cb ^ ((rl & 7) << 4));
}

#define TG_STAGES 3
#define TG_STAGE_BYTES 65536
#define TG_SMEM_BYTES (2048 + TG_STAGES * TG_STAGE_BYTES)

template <int EPI, int SPLIT>
__global__ __launch_bounds__(256, 1) void tma_gemm(
    int M, int N, int K, int swapg,
    const __grid_constant__ CUtensorMap tmAh,
    const __grid_constant__ CUtensorMap tmAl,
    const __grid_constant__ CUtensorMap tmBh,
    const __grid_constant__ CUtensorMap tmBl,
    const float* __restrict__ bias, float* __restrict__ C,
    const float* __restrict__ norm,
    __nv_bfloat16* __restrict__ Ohi, __nv_bfloat16* __restrict__ Olo) {
    extern __shared__ char smem[];
    uint32_t sbraw = (uint32_t)__cvta_generic_to_shared(smem);
    uint32_t sb = (sbraw + 1023u) & ~1023u;

    const int tid = threadIdx.x, wid = tid >> 5, lane = tid & 31;
    const int m0 = (swapg ? blockIdx.x : blockIdx.y) * 128;
    const int n0 = (swapg ? blockIdx.y : blockIdx.x) * 128;
    const int nc = K / 64;
    const int wm = (wid & 1) * 64;
    const int wn = (wid >> 1) * 32;

    uint32_t fullb = sb;               // mbarrier[s] at sb + 8s
    uint32_t tile0 = sb + 1024;

    if (tid == 0) {
        #pragma unroll
        for (int s = 0; s < TG_STAGES; s++) MBAR_INIT(fullb + 8 * s, 1);
    }
    __syncthreads();

    auto issue = [&](int chunk, int s) {
        uint32_t fb = fullb + 8 * s;
        MBAR_EXPECT_TX(fb, TG_STAGE_BYTES);
        uint32_t tb = tile0 + s * TG_STAGE_BYTES;
        int k0 = chunk * 64;
        TMA2D(tb,         (const void*)&tmAh, k0, m0, fb);
        TMA2D(tb + 16384, (const void*)&tmAl, k0, m0, fb);
        TMA2D(tb + 32768, (const void*)&tmBh, k0, n0, fb);
        TMA2D(tb + 49152, (const void*)&tmBl, k0, n0, fb);
    };

    if (tid == 0) {
        int P = nc < TG_STAGES ? nc : TG_STAGES;
        for (int s = 0; s < P; s++) issue(s, s);
    }

    float acc[4][4][4];
    #pragma unroll
    for (int i = 0; i < 4; i++)
        #pragma unroll
        for (int j = 0; j < 4; j++)
            #pragma unroll
            for (int q = 0; q < 4; q++) acc[i][j][q] = 0.0f;

    for (int c = 0; c < nc; c++) {
        int s = c % TG_STAGES;
        uint32_t ph = (uint32_t)((c / TG_STAGES) & 1);
        mbar_wait(fullb + 8 * s, ph);
        uint32_t tb = tile0 + s * TG_STAGE_BYTES;
        uint32_t tAh = tb, tAl = tb + 16384, tBh = tb + 32768, tBl = tb + 49152;

        #pragma unroll
        for (int ks = 0; ks < 4; ks++) {
            int cbA = ks * 32 + ((lane >> 4) & 1) * 16;
            uint32_t afh[4][4], afl[4][4];
            #pragma unroll
            for (int mi = 0; mi < 4; mi++) {
                int rl = wm + mi * 16 + (lane & 15);
                LDSM4(afh[mi][0], afh[mi][1], afh[mi][2], afh[mi][3], swadr(tAh, rl, cbA));
                LDSM4(afl[mi][0], afl[mi][1], afl[mi][2], afl[mi][3], swadr(tAl, rl, cbA));
            }
            int cbB = ks * 32 + ((lane >> 3) & 1) * 16;
            uint32_t bfh[4][2], bfl[4][2];
            #pragma unroll
            for (int p = 0; p < 2; p++) {
                int rl = wn + (2 * p + ((lane >> 4) & 1)) * 8 + (lane & 7);
                LDSM4(bfh[2*p][0], bfh[2*p][1], bfh[2*p+1][0], bfh[2*p+1][1], swadr(tBh, rl, cbB));
                LDSM4(bfl[2*p][0], bfl[2*p][1], bfl[2*p+1][0], bfl[2*p+1][1], swadr(tBl, rl, cbB));
            }
            #pragma unroll
            for (int mi = 0; mi < 4; mi++)
                #pragma unroll
                for (int ni = 0; ni < 4; ni++) {
                    MMA16816(acc[mi][ni], afh[mi], bfh[ni]);
                    MMA16816(acc[mi][ni], afh[mi], bfl[ni]);
                    MMA16816(acc[mi][ni], afl[mi], bfh[ni]);
                }
        }
        __syncthreads();
        if (tid == 0 && c + TG_STAGES < nc) issue(c + TG_STAGES, s);
    }

    // ---- epilogue ----
    #pragma unroll
    for (int mi = 0; mi < 4; mi++) {
        #pragma unroll
        for (int half = 0; half < 2; half++) {
            int r = m0 + wm + mi * 16 + (lane >> 2) + half * 8;
            if (r >= M) continue;
            float nr = (EPI == 2) ? norm[r] : 0.0f;
            #pragma unroll
            for (int ni = 0; ni < 4; ni++) {
                int cc = n0 + wn + ni * 8 + (lane & 3) * 2;
                if (cc >= N) continue;
                long idx = (long)r * N + cc;
                float a0 = acc[mi][ni][half * 2 + 0];
                float a1 = acc[mi][ni][half * 2 + 1];
                float v0, v1;
                if (EPI == 0) {
                    v0 = a0 + bias[cc]; v1 = a1 + bias[cc + 1];
                    C[idx] = v0; C[idx + 1] = v1;
                } else if (EPI == 1) {
                    v0 = fmaxf(a0 + bias[cc], 0.0f); v1 = fmaxf(a1 + bias[cc + 1], 0.0f);
                    if (!SPLIT) { C[idx] = v0; C[idx + 1] = v1; }
                } else {
                    v0 = C[idx]     + a0 * nr + bias[cc];
                    v1 = C[idx + 1] + a1 * nr + bias[cc + 1];
                    C[idx] = v0; C[idx + 1] = v1;
                }
                if (SPLIT) {
                    __nv_bfloat16 h0 = __float2bfloat16(v0);
                    __nv_bfloat16 h1 = __float2bfloat16(v1);
                    __nv_bfloat162 hh; hh.x = h0; hh.y = h1;
                    __nv_bfloat162 ll;
                    ll.x = __float2bfloat16(v0 - __bfloat162float(h0));
                    ll.y = __float2bfloat16(v1 - __bfloat162float(h1));
                    *reinterpret_cast<__nv_bfloat162*>(&Ohi[idx]) = hh;
                    *reinterpret_cast<__nv_bfloat162*>(&Olo[idx]) = ll;
                }
            }
        }
    }
}

// ---------------- host-side helpers ----------------
static float* symaddr(const void* sym) {
    void* p = nullptr;
    cudaGetSymbolAddress(&p, sym);
    return (float*)p;
}
static __nv_bfloat16* symaddr_bf(const void* sym) {
    void* p = nullptr;
    cudaGetSymbolAddress(&p, sym);
    return (__nv_bfloat16*)p;
}

typedef CUresult (*encode_fn_t)(CUtensorMap*, CUtensorMapDataType, cuuint32_t, void*,
                                const cuuint64_t*, const cuuint64_t*, const cuuint32_t*,
                                const cuuint32_t*, CUtensorMapInterleave, CUtensorMapSwizzle,
                                CUtensorMapL2promotion, CUtensorMapFloatOOBfill);

static encode_fn_t get_encoder() {
    void* fp = nullptr;
    cudaDriverEntryPointQueryResult qr;
    cudaGetDriverEntryPoint("cuTensorMapEncodeTiled", &fp, cudaEnableDefault, &qr);
    return (encode_fn_t)fp;
}

static void make_map(encode_fn_t enc, CUtensorMap* m, const __nv_bfloat16* p,
                     long K, long rowsPad) {
    cuuint64_t gd[2] = {(cuuint64_t)K, (cuuint64_t)rowsPad};
    cuuint64_t gs[1] = {(cuuint64_t)(K * 2)};
    cuuint32_t box[2] = {64, 128};
    cuuint32_t es[2] = {1, 1};
    enc(m, CU_TENSOR_MAP_DATA_TYPE_BFLOAT16, 2, (void*)p, gd, gs, box, es,
        CU_TENSOR_MAP_INTERLEAVE_NONE, CU_TENSOR_MAP_SWIZZLE_128B,
        CU_TENSOR_MAP_L2_PROMOTION_L2_128B, CU_TENSOR_MAP_FLOAT_OOB_FILL_NONE);
}

static void launch_tc(encode_fn_t enc, int epi, int split, int swapg,
                      int M, int N, int K, int Mpad, int Npad,
                      const __nv_bfloat16* Ah, const __nv_bfloat16* Al,
                      const __nv_bfloat16* Bh, const __nv_bfloat16* Bl,
                      const float* bias, float* C, const float* norm,
                      __nv_bfloat16* Ohi, __nv_bfloat16* Olo) {
    CUtensorMap mAh, mAl, mBh, mBl;
    make_map(enc, &mAh, Ah, K, Mpad);
    make_map(enc, &mAl, Al, K, Mpad);
    make_map(enc, &mBh, Bh, K, Npad);
    make_map(enc, &mBl, Bl, K, Npad);
    int mt = (M + 127) / 128, ntt = (N + 127) / 128;
    dim3 grid(swapg ? mt : ntt, swapg ? ntt : mt);
    if (epi == 0) {
        cudaFuncSetAttribute(tma_gemm<0,0>, cudaFuncAttributeMaxDynamicSharedMemorySize, TG_SMEM_BYTES);
        tma_gemm<0,0><<<grid, 256, TG_SMEM_BYTES>>>(M, N, K, swapg, mAh, mAl, mBh, mBl, bias, C, norm, Ohi, Olo);
    } else if (epi == 1 && split) {
        cudaFuncSetAttribute(tma_gemm<1,1>, cudaFuncAttributeMaxDynamicSharedMemorySize, TG_SMEM_BYTES);
        tma_gemm<1,1><<<grid, 256, TG_SMEM_BYTES>>>(M, N, K, swapg, mAh, mAl, mBh, mBl, bias, C, norm, Ohi, Olo);
    } else if (epi == 1) {
        cudaFuncSetAttribute(tma_gemm<1,0>, cudaFuncAttributeMaxDynamicSharedMemorySize, TG_SMEM_BYTES);
        tma_gemm<1,0><<<grid, 256, TG_SMEM_BYTES>>>(M, N, K, swapg, mAh, mAl, mBh, mBl, bias, C, norm, Ohi, Olo);
    } else {
        cudaFuncSetAttribute(tma_gemm<2,1>, cudaFuncAttributeMaxDynamicSharedMemorySize, TG_SMEM_BYTES);
        tma_gemm<2,1><<<grid, 256, TG_SMEM_BYTES>>>(M, N, K, swapg, mAh, mAl, mBh, mBl, bias, C, norm, Ohi, Olo);
    }
}

static inline void zero(float* p, long n) {
    fill_kernel<<<(int)((n + 255) / 256), 256>>>(p, (int)n, 0.0f);
}

static inline void conv_pad(const float* src, __nv_bfloat16* hi, __nv_bfloat16* lo,
                            int M, int K, int Kp) {
    long total = (long)M * Kp;
    conv_pad_kernel<<<(int)((total + 255) / 256), 256>>>(src, hi, lo, M, K, Kp);
}

static inline void transconv(const float* W, __nv_bfloat16* Thi, __nv_bfloat16* Tlo,
                             int K, int N, int Kp) {
    dim3 grid((N + 31) / 32, (Kp + 31) / 32);
    transconv_kernel<<<grid, dim3(32, 8)>>>(W, Thi, Tlo, K, N, Kp);
}

static void run_bn_split(int M, int C, const float* h, const float* g, const float* beta,
                         float* outf, __nv_bfloat16* ohi, __nv_bfloat16* olo,
                         float* pbs, float* pbq, float* pmean, float* prstd) {
    int chunks = (M > 20000) ? 128 : 32;
    dim3 grid(C / 32, chunks);
    dim3 blk(32, 8);
    bn_stats_partial<<<grid, blk>>>(M, C, h, pbs, pbq);
    bn_finalize<<<(C + 127) / 128, 128>>>(C, chunks, 1.0f / (float)M, pbs, pbq, pmean, prstd);
    long total = (long)M * C;
    bn_apply_relu_split<<<(int)((total + 255) / 256), 256>>>(total, C, h, pmean, prstd, g, beta,
                                                             outf, ohi, olo);
}

extern "C" void kernel_launch(void* const* d_in, const int* in_sizes, int n_in,
                              void* d_out, int out_size) {
    const float* atom_features = (const float*)d_in[0];
    const float* r             = (const float*)d_in[1];
    const int*   src           = (const int*)d_in[2];
    const int*   dst           = (const int*)d_in[3];
    const float* ae_w   = (const float*)d_in[4];
    const float* ae_b   = (const float*)d_in[5];
    const float* ae_g   = (const float*)d_in[6];
    const float* ae_be  = (const float*)d_in[7];
    const float* ee1_w  = (const float*)d_in[8];
    const float* ee1_b  = (const float*)d_in[9];
    const float* ee1_g  = (const float*)d_in[10];
    const float* ee1_be = (const float*)d_in[11];
    const float* ee2_w  = (const float*)d_in[12];
    const float* ee2_b  = (const float*)d_in[13];
    const float* ee2_g  = (const float*)d_in[14];
    const float* ee2_be = (const float*)d_in[15];
    const float* gcn_w  = (const float*)d_in[16];
    const float* gcn_b  = (const float*)d_in[17];
    const float* sg_w   = (const float*)d_in[18];
    const float* sg_b   = (const float*)d_in[19];
    const float* dg_w   = (const float*)d_in[20];
    const float* dg_b   = (const float*)d_in[21];
    const float* eg_w   = (const float*)d_in[22];
    const float* eg_b   = (const float*)d_in[23];
    const float* fc1_w  = (const float*)d_in[24];
    const float* fc1_b  = (const float*)d_in[25];
    const float* fc2_w  = (const float*)d_in[26];
    const float* fc2_b  = (const float*)d_in[27];
    const float* fc3_w  = (const float*)d_in[28];
    const float* fc3_b  = (const float*)d_in[29];

    const int N = in_sizes[0] / 92;
    const int E = in_sizes[2];
    encode_fn_t enc = get_encoder();

    float* px    = symaddr(g_x);
    float* ppre  = symaddr(g_pre);
    float* pgate = symaddr(g_gate);
    float* pagg  = symaddr(g_agg);
    float* pbond = symaddr(g_bond);
    float* ph1   = symaddr(g_h1);
    float* py    = symaddr(g_y);
    float* pee   = symaddr(g_ee);
    float* pdegs = symaddr(g_degs);
    float* pdegd = symaddr(g_degd);
    float* pnl   = symaddr(g_nl);
    float* pnr   = symaddr(g_nr);
    float* pbs   = symaddr(g_bps);
    float* pbq   = symaddr(g_bpq);
    float* pmean = symaddr(g_mean);
    float* prstd = symaddr(g_rstd);
    float* pgb   = symaddr(g_gateb);

    __nv_bfloat16 *xa_h = symaddr_bf(g_xa_hi),  *xa_l = symaddr_bf(g_xa_lo);
    __nv_bfloat16 *x_h  = symaddr_bf(g_x_hi),   *x_l  = symaddr_bf(g_x_lo);
    __nv_bfloat16 *ag_h = symaddr_bf(g_agg_hi), *ag_l = symaddr_bf(g_agg_lo);
    __nv_bfloat16 *f1_h = symaddr_bf(g_fc1_hi), *f1_l = symaddr_bf(g_fc1_lo);
    __nv_bfloat16 *f2_h = symaddr_bf(g_fc2_hi), *f2_l = symaddr_bf(g_fc2_lo);
    __nv_bfloat16 *rb_h = symaddr_bf(g_rbf_hi), *rb_l = symaddr_bf(g_rbf_lo);
    __nv_bfloat16 *h1_h = symaddr_bf(g_h1_hi),  *h1_l = symaddr_bf(g_h1_lo);
    __nv_bfloat16 *y_h  = symaddr_bf(g_y_hi),   *y_l  = symaddr_bf(g_y_lo);

    __nv_bfloat16 *aew_h = symaddr_bf(g_aewT_hi),  *aew_l = symaddr_bf(g_aewT_lo);
    __nv_bfloat16 *e1w_h = symaddr_bf(g_ee1wT_hi), *e1w_l = symaddr_bf(g_ee1wT_lo);
    __nv_bfloat16 *e2w_h = symaddr_bf(g_ee2wT_hi), *e2w_l = symaddr_bf(g_ee2wT_lo);
    __nv_bfloat16 *gtw_h = symaddr_bf(g_gatewT_hi),*gtw_l = symaddr_bf(g_gatewT_lo);
    __nv_bfloat16 *egw_h = symaddr_bf(g_egwT_hi),  *egw_l = symaddr_bf(g_egwT_lo);
    __nv_bfloat16 *gw_h  = symaddr_bf(g_gwT_hi),   *gw_l  = symaddr_bf(g_gwT_lo);
    __nv_bfloat16 *f1w_h = symaddr_bf(g_fc1wT_hi), *f1w_l = symaddr_bf(g_fc1wT_lo);
    __nv_bfloat16 *f2w_h = symaddr_bf(g_fc2wT_hi), *f2w_l = symaddr_bf(g_fc2wT_lo);
    __nv_bfloat16 *f3w_h = symaddr_bf(g_fc3wT_hi), *f3w_l = symaddr_bf(g_fc3wT_lo);

    // ---- weight transpose + split (Kp multiple of 64) ----
    transconv(ae_w, aew_h, aew_l, 92, 256, 128);
    transconv(ee1_w, e1w_h, e1w_l, 80, 64, 128);
    transconv(ee2_w, e2w_h, e2w_l, 64, 256, 64);
    for (int i = 0; i < 4; i++) {
        long wo = (long)i * 256 * 256;
        long go = (long)i * 512 * 256;
        transconv(sg_w + wo, gtw_h + go, gtw_l + go, 256, 256, 256);
        transconv(dg_w + wo, gtw_h + go + 256 * 256, gtw_l + go + 256 * 256, 256, 256, 256);
        transconv(eg_w + wo, egw_h + wo, egw_l + wo, 256, 256, 256);
        transconv(gcn_w + wo, gw_h + wo, gw_l + wo, 256, 256, 256);
    }
    transconv(fc1_w, f1w_h, f1w_l, 256, 1024, 256);
    transconv(fc2_w, f2w_h, f2w_l, 1024, 2048, 1024);
    transconv(fc3_w, f3w_h, f3w_l, 2048, 10000, 2048);
    gate_bias_concat<<<8, 256>>>(sg_b, dg_b, pgb);

    // ---- degrees & norms ----
    zero(pdegs, N); zero(pdegd, N);
    deg_kernel<<<(E + 255) / 256, 256>>>(E, src, dst, pdegs, pdegd);
    norm_kernel<<<(N + 255) / 256, 256>>>(N, pdegs, pdegd, pnl, pnr);

    // ---- atom embedding MLP ----
    conv_pad(atom_features, xa_h, xa_l, N, 92, 128);
    launch_tc(enc, 0, 0, 0, N, 256, 128, NPAD, 256,
              xa_h, xa_l, aew_h, aew_l, ae_b, ppre, nullptr, nullptr, nullptr);
    run_bn_split(N, 256, ppre, ae_g, ae_be, px, x_h, x_l, pbs, pbq, pmean, prstd);

    // ---- RBF + edge embedding MLPs ----
    bond_kernel<<<(E + 255) / 256, 256>>>(E, r, pbond);
    {
        long tot = (long)E * 80;
        rbf_split_kernel<<<(int)((tot + 255) / 256), 256>>>((int)tot, pbond, rb_h, rb_l);
    }
    launch_tc(enc, 0, 0, 0, E, 64, 128, E, 128,
              rb_h, rb_l, e1w_h, e1w_l, ee1_b, ph1, nullptr, nullptr, nullptr);
    run_bn_split(E, 64, ph1, ee1_g, ee1_be, nullptr, h1_h, h1_l, pbs, pbq, pmean, prstd);
    launch_tc(enc, 0, 0, 0, E, 256, 64, E, 256,
              h1_h, h1_l, e2w_h, e2w_l, ee2_b, py, nullptr, nullptr, nullptr);
    run_bn_split(E, 256, py, ee2_g, ee2_be, nullptr, y_h, y_l, pbs, pbq, pmean, prstd);

    // ---- 4 gated GCN layers ----
    for (int i = 0; i < 4; i++) {
        long wo = (long)i * 256 * 256;
        long go = (long)i * 512 * 256;
        const float* egb = eg_b + i * 256;
        const float* gb  = gcn_b + i * 256;

        launch_tc(enc, 0, 0, 0, N, 512, 256, NPAD, 512,
                  x_h, x_l, gtw_h + go, gtw_l + go, pgb + i * 512, pgate, nullptr, nullptr, nullptr);
        launch_tc(enc, 0, 0, 0, E, 256, 256, E, 256,
                  y_h, y_l, egw_h + wo, egw_l + wo, egb, pee, nullptr, nullptr, nullptr);

        zero(pagg, (long)N * 256);
        edge_gate_agg<<<(E + 3) / 4, 256>>>(E, px, pgate, pee, src, dst, pnl, pagg);
        conv_pad(pagg, ag_h, ag_l, N, 256, 256);

        launch_tc(enc, 2, 1, 0, N, 256, 256, NPAD, 256,
                  ag_h, ag_l, gw_h + wo, gw_l + wo, gb, px, pnr, x_h, x_l);
    }

    // ---- readout MLP ----
    launch_tc(enc, 1, 1, 0, N, 1024, 256, NPAD, 1024,
              x_h, x_l, f1w_h, f1w_l, fc1_b, nullptr, nullptr, f1_h, f1_l);
    launch_tc(enc, 1, 1, 1, N, 2048, 1024, NPAD, 2048,
              f1_h, f1_l, f2w_h, f2w_l, fc2_b, nullptr, nullptr, f2_h, f2_l);
    launch_tc(enc, 1, 0, 1, N, 10000, 2048, NPAD, 10112,
              f2_h, f2_l, f3w_h, f3w_l, fc3_b, (float*)d_out, nullptr, nullptr, nullptr);
}

// round 15
// speedup vs baseline: 4.9281x; 1.4179x over previous
#include <cuda_runtime.h>
#include <cuda.h>
#include <cuda_bf16.h>
#include <cuda_fp16.h>
#include <stdint.h>
#include <math.h>

// ---------------- problem-size constants ----------------
#define NMAXV 5000
#define NPAD  5120
#define EMAXV 160000
#define HD 256

// ---------------- fp32 scratch ----------------
__device__ float g_x   [NMAXV * 256];
__device__ float g_pre [NMAXV * 256];
__device__ float g_gate[NMAXV * 512];
__device__ float g_agg [NMAXV * 256];
__device__ float g_bond[EMAXV];
__device__ float g_h1  [EMAXV * 64];
__device__ float g_y   [EMAXV * 256];
__device__ float g_degs[NMAXV];
__device__ float g_degd[NMAXV];
__device__ float g_nl  [NMAXV];
__device__ float g_nr  [NMAXV];
__device__ float g_bps [128 * 256];
__device__ float g_bpq [128 * 256];
__device__ float g_mean[256];
__device__ float g_rstd[256];
__device__ float g_gateb[4 * 512];
__device__ float g_ee  [EMAXV * 256];

// ---------------- bf16/fp16 activations (rows padded; static zero-init) -------
__device__ __align__(128) __nv_bfloat16 g_xa_hi[NPAD * 128];
__device__ __align__(128) __nv_bfloat16 g_xa_lo[NPAD * 128];
__device__ __align__(128) __nv_bfloat16 g_x_hi [NPAD * 256];
__device__ __align__(128) __nv_bfloat16 g_x_lo [NPAD * 256];
__device__ __align__(128) __nv_bfloat16 g_agg_hi[NPAD * 256];
__device__ __align__(128) __nv_bfloat16 g_agg_lo[NPAD * 256];
__device__ __align__(128) __nv_bfloat16 g_fc1_hi[NPAD * 1024];
__device__ __align__(128) __nv_bfloat16 g_fc1_lo[NPAD * 1024];
__device__ __align__(128) __half        g_fc2_h [NPAD * 2048];      // fp16 single
__device__ __align__(128) __nv_bfloat16 g_rbf_hi[EMAXV * 128];
__device__ __align__(128) __nv_bfloat16 g_rbf_lo[EMAXV * 128];
__device__ __align__(128) __nv_bfloat16 g_h1_hi [EMAXV * 64];
__device__ __align__(128) __nv_bfloat16 g_h1_lo [EMAXV * 64];
__device__ __align__(128) __half        g_y_h   [EMAXV * 256];      // fp16 single

// ---------------- weights: transposed [rowsPad][Kpad] ----------------
__device__ __align__(128) __nv_bfloat16 g_aewT_hi [256 * 128];
__device__ __align__(128) __nv_bfloat16 g_aewT_lo [256 * 128];
__device__ __align__(128) __nv_bfloat16 g_ee1wT_hi[128 * 128];
__device__ __align__(128) __nv_bfloat16 g_ee1wT_lo[128 * 128];
__device__ __align__(128) __nv_bfloat16 g_ee2wT_hi[256 * 64];
__device__ __align__(128) __nv_bfloat16 g_ee2wT_lo[256 * 64];
__device__ __align__(128) __nv_bfloat16 g_gatewT_hi[4 * 512 * 256];
__device__ __align__(128) __nv_bfloat16 g_gatewT_lo[4 * 512 * 256];
__device__ __align__(128) __half        g_egwT_h [4 * 256 * 256];   // fp16 single
__device__ __align__(128) __nv_bfloat16 g_gwT_hi  [4 * 256 * 256];
__device__ __align__(128) __nv_bfloat16 g_gwT_lo  [4 * 256 * 256];
__device__ __align__(128) __nv_bfloat16 g_fc1wT_hi[1024 * 256];
__device__ __align__(128) __nv_bfloat16 g_fc1wT_lo[1024 * 256];
__device__ __align__(128) __nv_bfloat16 g_fc2wT_hi[2048 * 1024];
__device__ __align__(128) __nv_bfloat16 g_fc2wT_lo[2048 * 1024];
__device__ __align__(128) __half        g_fc3wT_h [10112 * 2048];   // fp16 single

// ---------------- small utility kernels ----------------
__global__ void fill_kernel(float* p, int n, float v) {
    int i = blockIdx.x * blockDim.x + threadIdx.x;
    if (i < n) p[i] = v;
}

__global__ void gate_bias_concat(const float* __restrict__ sgb, const float* __restrict__ dgb,
                                 float* out) {
    int i = blockIdx.x * blockDim.x + threadIdx.x;
    if (i < 4 * 512) {
        int layer = i >> 9;
        int c = i & 511;
        out[i] = (c < 256) ? sgb[layer * 256 + c] : dgb[layer * 256 + (c - 256)];
    }
}

__global__ void deg_kernel(int E, const int* __restrict__ src, const int* __restrict__ dst,
                           float* degs, float* degd) {
    int e = blockIdx.x * blockDim.x + threadIdx.x;
    if (e < E) {
        atomicAdd(&degs[src[e]], 1.0f);
        atomicAdd(&degd[dst[e]], 1.0f);
    }
}

__global__ void norm_kernel(int N, const float* __restrict__ degs, const float* __restrict__ degd,
                            float* nl, float* nr) {
    int i = blockIdx.x * blockDim.x + threadIdx.x;
    if (i < N) {
        nl[i] = rsqrtf(fmaxf(degs[i], 1.0f));
        nr[i] = rsqrtf(fmaxf(degd[i], 1.0f));
    }
}

__global__ void bond_kernel(int E, const float* __restrict__ r, float* bond) {
    int e = blockIdx.x * blockDim.x + threadIdx.x;
    if (e < E) {
        float a = r[e * 3 + 0], b = r[e * 3 + 1], c = r[e * 3 + 2];
        bond[e] = sqrtf(a * a + b * b + c * c);
    }
}

__global__ void rbf_split_kernel(int total, const float* __restrict__ bond,
                                 __nv_bfloat16* __restrict__ hi, __nv_bfloat16* __restrict__ lo) {
    int idx = blockIdx.x * blockDim.x + threadIdx.x;
    if (idx < total) {
        int e = idx / 80;
        int j = idx - e * 80;
        const float gamma = 79.0f / 8.0f;
        float cj = (8.0f / 79.0f) * (float)j;
        float d = bond[e] - cj;
        float v = expf(-gamma * d * d);
        __nv_bfloat16 h = __float2bfloat16(v);
        long o = (long)e * 128 + j;
        hi[o] = h;
        lo[o] = __float2bfloat16(v - __bfloat162float(h));
    }
}

__global__ void conv_pad_kernel(const float* __restrict__ src,
                                __nv_bfloat16* __restrict__ hi, __nv_bfloat16* __restrict__ lo,
                                int M, int K, int Kp) {
    long idx = (long)blockIdx.x * blockDim.x + threadIdx.x;
    long total = (long)M * Kp;
    if (idx >= total) return;
    int r = (int)(idx / Kp);
    int c = (int)(idx - (long)r * Kp);
    float v = (c < K) ? src[(long)r * K + c] : 0.0f;
    __nv_bfloat16 h = __float2bfloat16(v);
    hi[idx] = h;
    lo[idx] = __float2bfloat16(v - __bfloat162float(h));
}

// transpose + convert: mode 0 = bf16 hi/lo pair, 1 = fp16 single (Tlo unused)
__global__ void transconv_kernel(const float* __restrict__ W,
                                 void* __restrict__ Thi, __nv_bfloat16* __restrict__ Tlo,
                                 int K, int N, int Kp, int mode) {
    __shared__ float t[32][33];
    int k0 = blockIdx.y * 32, n0 = blockIdx.x * 32;
    int tx = threadIdx.x, ty = threadIdx.y;
    #pragma unroll
    for (int i = ty; i < 32; i += 8) {
        int k = k0 + i, n = n0 + tx;
        t[i][tx] = (k < K && n < N) ? W[(long)k * N + n] : 0.0f;
    }
    __syncthreads();
    #pragma unroll
    for (int i = ty; i < 32; i += 8) {
        int n = n0 + i, k = k0 + tx;
        if (n < N && k < Kp) {
            float v = t[tx][i];
            long o = (long)n * Kp + k;
            if (mode == 0) {
                __nv_bfloat16 h = __float2bfloat16(v);
                ((__nv_bfloat16*)Thi)[o] = h;
                Tlo[o] = __float2bfloat16(v - __bfloat162float(h));
            } else {
                ((__half*)Thi)[o] = __float2half(v);
            }
        }
    }
}

// ---------------- BatchNorm ----------------
__global__ void bn_stats_partial(int M, int C, const float* __restrict__ h,
                                 float* psum, float* psumsq) {
    int c = blockIdx.x * 32 + threadIdx.x;
    int rowsPerChunk = (M + gridDim.y - 1) / gridDim.y;
    int r0 = blockIdx.y * rowsPerChunk;
    int r1 = min(M, r0 + rowsPerChunk);
    float s = 0.f, s2 = 0.f;
    if (c < C) {
        for (int r = r0 + threadIdx.y; r < r1; r += 8) {
            float v = h[(long)r * C + c];
            s += v; s2 += v * v;
        }
    }
    __shared__ float sh[2][8][32];
    sh[0][threadIdx.y][threadIdx.x] = s;
    sh[1][threadIdx.y][threadIdx.x] = s2;
    __syncthreads();
    if (threadIdx.y == 0 && c < C) {
        float ts = 0.f, t2 = 0.f;
        #pragma unroll
        for (int i = 0; i < 8; i++) { ts += sh[0][i][threadIdx.x]; t2 += sh[1][i][threadIdx.x]; }
        psum[blockIdx.y * C + c] = ts;
        psumsq[blockIdx.y * C + c] = t2;
    }
}

__global__ void bn_finalize(int C, int chunks, float invM,
                            const float* __restrict__ psum, const float* __restrict__ psumsq,
                            float* mean, float* rstd) {
    int c = blockIdx.x * blockDim.x + threadIdx.x;
    if (c < C) {
        float s = 0.f, s2 = 0.f;
        for (int k = 0; k < chunks; k++) { s += psum[k * C + c]; s2 += psumsq[k * C + c]; }
        float m = s * invM;
        float var = fmaxf(s2 * invM - m * m, 0.0f);
        mean[c] = m;
        rstd[c] = rsqrtf(var + 1e-5f);
    }
}

// BN apply + ReLU. mode 0: write bf16 hi/lo; mode 1: write fp16 single to ohi.
__global__ void bn_apply_relu_split(long total, int C, const float* __restrict__ h,
                                    const float* __restrict__ mean, const float* __restrict__ rstd,
                                    const float* __restrict__ g, const float* __restrict__ beta,
                                    float* outf, void* __restrict__ ohi,
                                    __nv_bfloat16* __restrict__ olo, int mode) {
    long idx = (long)blockIdx.x * blockDim.x + threadIdx.x;
    if (idx < total) {
        int c = (int)(idx % C);
        float v = g[c] * (h[idx] - mean[c]) * rstd[c] + beta[c];
        v = fmaxf(v, 0.0f);
        if (outf) outf[idx] = v;
        if (mode == 0) {
            __nv_bfloat16 hb = __float2bfloat16(v);
            ((__nv_bfloat16*)ohi)[idx] = hb;
            olo[idx] = __float2bfloat16(v - __bfloat162float(hb));
        } else {
            ((__half*)ohi)[idx] = __float2half(v);
        }
    }
}

// ---------------- edge gate + scatter-aggregate ----------------
__global__ void edge_gate_agg(int E, const float* __restrict__ x,
                              const float* __restrict__ gate,
                              const float* __restrict__ ee,
                              const int* __restrict__ src, const int* __restrict__ dst,
                              const float* __restrict__ nl, float* agg) {
    int e = blockIdx.x * 4 + (threadIdx.x >> 6);
    if (e >= E) return;
    int j = (threadIdx.x & 63) * 4;
    int s = src[e], d = dst[e];
    float nls = nl[s];
    float4 es = *(const float4*)&gate[s * 512 + j];
    float4 ed = *(const float4*)&gate[d * 512 + 256 + j];
    float4 ev = *(const float4*)&ee[(long)e * HD + j];
    float4 xv = *(const float4*)&x[s * HD + j];
    float m0 = xv.x * nls / (1.0f + expf(-(es.x + ed.x + ev.x)));
    float m1 = xv.y * nls / (1.0f + expf(-(es.y + ed.y + ev.y)));
    float m2 = xv.z * nls / (1.0f + expf(-(es.z + ed.z + ev.z)));
    float m3 = xv.w * nls / (1.0f + expf(-(es.w + ed.w + ev.w)));
    float* a = &agg[d * HD + j];
    atomicAdd(a + 0, m0);
    atomicAdd(a + 1, m1);
    atomicAdd(a + 2, m2);
    atomicAdd(a + 3, m3);
}

// ================= TMA + mma.sync GEMM =================
// PREC 0: split-bf16 3-product (error ~2^-16); PREC 1: fp16 single product.
// EPI 0: C=acc+bias  1: relu  2: residual (C += acc*norm + bias)
// SPLIT 0: none  1: write bf16 hi/lo  2: write fp16 single

#define MBAR_INIT(addr, cnt) \
    asm volatile("mbarrier.init.shared.b64 [%0], %1;" :: "r"(addr), "r"(cnt) : "memory")
#define MBAR_EXPECT_TX(addr, bytes) \
    asm volatile("mbarrier.arrive.expect_tx.shared.b64 _, [%0], %1;" :: "r"(addr), "r"(bytes) : "memory")

__device__ __forceinline__ void mbar_wait(uint32_t addr, uint32_t parity) {
    asm volatile(
        "{\n\t"
        ".reg .pred P;\n\t"
        "WAITLOOP%=:\n\t"
        "mbarrier.try_wait.parity.acquire.cta.shared::cta.b64 P, [%0], %1, 0x989680;\n\t"
        "@!P bra WAITLOOP%=;\n\t"
        "}"
        :: "r"(addr), "r"(parity) : "memory");
}

#define TMA2D(saddr, mapp, cx, cy, mbar) \
    asm volatile("cp.async.bulk.tensor.2d.shared::cta.global.tile.mbarrier::complete_tx::bytes " \
                 "[%0], [%1, {%2, %3}], [%4];" \
                 :: "r"(saddr), "l"(mapp), "r"(cx), "r"(cy), "r"(mbar) : "memory")

#define LDSM4(R0, R1, R2, R3, addr) \
    asm volatile("ldmatrix.sync.aligned.m8n8.x4.shared.b16 {%0,%1,%2,%3}, [%4];" \
                 : "=r"(R0), "=r"(R1), "=r"(R2), "=r"(R3) : "r"(addr))

#define MMABF16(d, a, b) \
    asm volatile("mma.sync.aligned.m16n8k16.row.col.f32.bf16.bf16.f32 " \
                 "{%0,%1,%2,%3}, {%4,%5,%6,%7}, {%8,%9}, {%0,%1,%2,%3};" \
                 : "+f"((d)[0]), "+f"((d)[1]), "+f"((d)[2]), "+f"((d)[3]) \
                 : "r"((a)[0]), "r"((a)[1]), "r"((a)[2]), "r"((a)[3]), \
                   "r"((b)[0]), "r"((b)[1]))

#define MMAFP16(d, a, b) \
    asm volatile("mma.sync.aligned.m16n8k16.row.col.f32.f16.f16.f32 " \
                 "{%0,%1,%2,%3}, {%4,%5,%6,%7}, {%8,%9}, {%0,%1,%2,%3};" \
                 : "+f"((d)[0]), "+f"((d)[1]), "+f"((d)[2]), "+f"((d)[3]) \
                 : "r"((a)[0]), "r"((a)[1]), "r"((a)[2]), "r"((a)[3]), \
                   "r"((b)[0]), "r"((b)[1]))

__device__ __forceinline__ uint32_t swadr(uint32_t base, int rl, int cb) {
    return base + rl * 128 + (cb ^ ((rl & 7) << 4));
}

template <int EPI, int SPLIT, int PREC>
__global__ __launch_bounds__(256, 1) void tma_gemm(
    int M, int N, int K, int swapg,
    const __grid_constant__ CUtensorMap tmAh,
    const __grid_constant__ CUtensorMap tmAl,
    const __grid_constant__ CUtensorMap tmBh,
    const __grid_constant__ CUtensorMap tmBl,
    const float* __restrict__ bias, float* __restrict__ C,
    const float* __restrict__ norm,
    void* __restrict__ Ohi, __nv_bfloat16* __restrict__ Olo) {
    constexpr int NSTG = PREC ? 5 : 3;
    constexpr int STB  = PREC ? 32768 : 65536;
    extern __shared__ char smem[];
    uint32_t sbraw = (uint32_t)__cvta_generic_to_shared(smem);
    uint32_t sb = (sbraw + 1023u) & ~1023u;

    const int tid = threadIdx.x, wid = tid >> 5, lane = tid & 31;
    const int m0 = (swapg ? blockIdx.x : blockIdx.y) * 128;
    const int n0 = (swapg ? blockIdx.y : blockIdx.x) * 128;
    const int nc = K / 64;
    const int wm = (wid & 1) * 64;
    const int wn = (wid >> 1) * 32;

    uint32_t fullb = sb;
    uint32_t tile0 = sb + 1024;

    if (tid == 0) {
        #pragma unroll
        for (int s = 0; s < NSTG; s++) MBAR_INIT(fullb + 8 * s, 1);
    }
    __syncthreads();

    auto issue = [&](int chunk, int s) {
        uint32_t fb = fullb + 8 * s;
        MBAR_EXPECT_TX(fb, STB);
        uint32_t tb = tile0 + s * STB;
        int k0 = chunk * 64;
        if (PREC) {
            TMA2D(tb,         (const void*)&tmAh, k0, m0, fb);
            TMA2D(tb + 16384, (const void*)&tmBh, k0, n0, fb);
        } else {
            TMA2D(tb,         (const void*)&tmAh, k0, m0, fb);
            TMA2D(tb + 16384, (const void*)&tmAl, k0, m0, fb);
            TMA2D(tb + 32768, (const void*)&tmBh, k0, n0, fb);
            TMA2D(tb + 49152, (const void*)&tmBl, k0, n0, fb);
        }
    };

    if (tid == 0) {
        int P = nc < NSTG ? nc : NSTG;
        for (int s = 0; s < P; s++) issue(s, s);
    }

    float acc[4][4][4];
    #pragma unroll
    for (int i = 0; i < 4; i++)
        #pragma unroll
        for (int j = 0; j < 4; j++)
            #pragma unroll
            for (int q = 0; q < 4; q++) acc[i][j][q] = 0.0f;

    for (int c = 0; c < nc; c++) {
        int s = c % NSTG;
        uint32_t ph = (uint32_t)((c / NSTG) & 1);
        mbar_wait(fullb + 8 * s, ph);
        uint32_t tb = tile0 + s * STB;
        uint32_t tAh = tb;
        uint32_t tBh = tb + (PREC ? 16384 : 32768);
        uint32_t tAl = tb + 16384, tBl = tb + 49152;

        #pragma unroll
        for (int ks = 0; ks < 4; ks++) {
            int cbA = ks * 32 + ((lane >> 4) & 1) * 16;
            uint32_t afh[4][4], afl[4][4];
            #pragma unroll
            for (int mi = 0; mi < 4; mi++) {
                int rl = wm + mi * 16 + (lane & 15);
                LDSM4(afh[mi][0], afh[mi][1], afh[mi][2], afh[mi][3], swadr(tAh, rl, cbA));
                if (!PREC)
                    LDSM4(afl[mi][0], afl[mi][1], afl[mi][2], afl[mi][3], swadr(tAl, rl, cbA));
            }
            int cbB = ks * 32 + ((lane >> 3) & 1) * 16;
            uint32_t bfh[4][2], bfl[4][2];
            #pragma unroll
            for (int p = 0; p < 2; p++) {
                int rl = wn + (2 * p + ((lane >> 4) & 1)) * 8 + (lane & 7);
                LDSM4(bfh[2*p][0], bfh[2*p][1], bfh[2*p+1][0], bfh[2*p+1][1], swadr(tBh, rl, cbB));
                if (!PREC)
                    LDSM4(bfl[2*p][0], bfl[2*p][1], bfl[2*p+1][0], bfl[2*p+1][1], swadr(tBl, rl, cbB));
            }
            #pragma unroll
            for (int mi = 0; mi < 4; mi++)
                #pragma unroll
                for (int ni = 0; ni < 4; ni++) {
                    if (PREC) {
                        MMAFP16(acc[mi][ni], afh[mi], bfh[ni]);
                    } else {
                        MMABF16(acc[mi][ni], afh[mi], bfh[ni]);
                        MMABF16(acc[mi][ni], afh[mi], bfl[ni]);
                        MMABF16(acc[mi][ni], afl[mi], bfh[ni]);
                    }
                }
        }
        __syncthreads();
        if (tid == 0 && c + NSTG < nc) issue(c + NSTG, s);
    }

    // ---- epilogue ----
    #pragma unroll
    for (int mi = 0; mi < 4; mi++) {
        #pragma unroll
        for (int half = 0; half < 2; half++) {
            int r = m0 + wm + mi * 16 + (lane >> 2) + half * 8;
            if (r >= M) continue;
            float nr = (EPI == 2) ? norm[r] : 0.0f;
            #pragma unroll
            for (int ni = 0; ni < 4; ni++) {
                int cc = n0 + wn + ni * 8 + (lane & 3) * 2;
                if (cc >= N) continue;
                long idx = (long)r * N + cc;
                float a0 = acc[mi][ni][half * 2 + 0];
                float a1 = acc[mi][ni][half * 2 + 1];
                float v0, v1;
                if (EPI == 0) {
                    v0 = a0 + bias[cc]; v1 = a1 + bias[cc + 1];
                    C[idx] = v0; C[idx + 1] = v1;
                } else if (EPI == 1) {
                    v0 = fmaxf(a0 + bias[cc], 0.0f); v1 = fmaxf(a1 + bias[cc + 1], 0.0f);
                    if (!SPLIT) { C[idx] = v0; C[idx + 1] = v1; }
                } else {
                    v0 = C[idx]     + a0 * nr + bias[cc];
                    v1 = C[idx + 1] + a1 * nr + bias[cc + 1];
                    C[idx] = v0; C[idx + 1] = v1;
                }
                if (SPLIT == 1) {
                    __nv_bfloat16 h0 = __float2bfloat16(v0);
                    __nv_bfloat16 h1 = __float2bfloat16(v1);
                    __nv_bfloat162 hh; hh.x = h0; hh.y = h1;
                    __nv_bfloat162 ll;
                    ll.x = __float2bfloat16(v0 - __bfloat162float(h0));
                    ll.y = __float2bfloat16(v1 - __bfloat162float(h1));
                    *reinterpret_cast<__nv_bfloat162*>(&((__nv_bfloat16*)Ohi)[idx]) = hh;
                    *reinterpret_cast<__nv_bfloat162*>(&Olo[idx]) = ll;
                } else if (SPLIT == 2) {
                    __half2 hh = __floats2half2_rn(v0, v1);
                    *reinterpret_cast<__half2*>(&((__half*)Ohi)[idx]) = hh;
                }
            }
        }
    }
}

// ---------------- host-side helpers ----------------
static float* symaddr(const void* sym) {
    void* p = nullptr;
    cudaGetSymbolAddress(&p, sym);
    return (float*)p;
}
static __nv_bfloat16* symaddr_bf(const void* sym) {
    void* p = nullptr;
    cudaGetSymbolAddress(&p, sym);
    return (__nv_bfloat16*)p;
}
static __half* symaddr_h(const void* sym) {
    void* p = nullptr;
    cudaGetSymbolAddress(&p, sym);
    return (__half*)p;
}

typedef CUresult (*encode_fn_t)(CUtensorMap*, CUtensorMapDataType, cuuint32_t, void*,
                                const cuuint64_t*, const cuuint64_t*, const cuuint32_t*,
                                const cuuint32_t*, CUtensorMapInterleave, CUtensorMapSwizzle,
                                CUtensorMapL2promotion, CUtensorMapFloatOOBfill);

static encode_fn_t get_encoder() {
    void* fp = nullptr;
    cudaDriverEntryPointQueryResult qr;
    cudaGetDriverEntryPoint("cuTensorMapEncodeTiled", &fp, cudaEnableDefault, &qr);
    return (encode_fn_t)fp;
}

static void make_map(encode_fn_t enc, CUtensorMap* m, const void* p,
                     long K, long rowsPad, int fp16) {
    cuuint64_t gd[2] = {(cuuint64_t)K, (cuuint64_t)rowsPad};
    cuuint64_t gs[1] = {(cuuint64_t)(K * 2)};
    cuuint32_t box[2] = {64, 128};
    cuuint32_t es[2] = {1, 1};
    enc(m, fp16 ? CU_TENSOR_MAP_DATA_TYPE_FLOAT16 : CU_TENSOR_MAP_DATA_TYPE_BFLOAT16,
        2, (void*)p, gd, gs, box, es,
        CU_TENSOR_MAP_INTERLEAVE_NONE, CU_TENSOR_MAP_SWIZZLE_128B,
        CU_TENSOR_MAP_L2_PROMOTION_L2_128B, CU_TENSOR_MAP_FLOAT_OOB_FILL_NONE);
}

#define SMEM_P0 (2048 + 3 * 65536)
#define SMEM_P1 (2048 + 5 * 32768)

static void launch_tc(encode_fn_t enc, int epi, int split, int prec, int swapg,
                      int M, int N, int K, int Mpad, int Npad,
                      const void* Ah, const void* Al,
                      const void* Bh, const void* Bl,
                      const float* bias, float* C, const float* norm,
                      void* Ohi, __nv_bfloat16* Olo) {
    CUtensorMap mAh, mAl, mBh, mBl;
    make_map(enc, &mAh, Ah, K, Mpad, prec);
    make_map(enc, &mBh, Bh, K, Npad, prec);
    if (!prec) {
        make_map(enc, &mAl, Al, K, Mpad, 0);
        make_map(enc, &mBl, Bl, K, Npad, 0);
    } else { mAl = mAh; mBl = mBh; }
    int mt = (M + 127) / 128, ntt = (N + 127) / 128;
    dim3 grid(swapg ? mt : ntt, swapg ? ntt : mt);
    if (prec == 0 && epi == 0) {
        cudaFuncSetAttribute(tma_gemm<0,0,0>, cudaFuncAttributeMaxDynamicSharedMemorySize, SMEM_P0);
        tma_gemm<0,0,0><<<grid, 256, SMEM_P0>>>(M, N, K, swapg, mAh, mAl, mBh, mBl, bias, C, norm, Ohi, Olo);
    } else if (prec == 0 && epi == 2) {
        cudaFuncSetAttribute(tma_gemm<2,1,0>, cudaFuncAttributeMaxDynamicSharedMemorySize, SMEM_P0);
        tma_gemm<2,1,0><<<grid, 256, SMEM_P0>>>(M, N, K, swapg, mAh, mAl, mBh, mBl, bias, C, norm, Ohi, Olo);
    } else if (prec == 0 && epi == 1 && split == 1) {
        cudaFuncSetAttribute(tma_gemm<1,1,0>, cudaFuncAttributeMaxDynamicSharedMemorySize, SMEM_P0);
        tma_gemm<1,1,0><<<grid, 256, SMEM_P0>>>(M, N, K, swapg, mAh, mAl, mBh, mBl, bias, C, norm, Ohi, Olo);
    } else if (prec == 0 && epi == 1 && split == 2) {
        cudaFuncSetAttribute(tma_gemm<1,2,0>, cudaFuncAttributeMaxDynamicSharedMemorySize, SMEM_P0);
        tma_gemm<1,2,0><<<grid, 256, SMEM_P0>>>(M, N, K, swapg, mAh, mAl, mBh, mBl, bias, C, norm, Ohi, Olo);
    } else if (prec == 1 && epi == 0) {
        cudaFuncSetAttribute(tma_gemm<0,0,1>, cudaFuncAttributeMaxDynamicSharedMemorySize, SMEM_P1);
        tma_gemm<0,0,1><<<grid, 256, SMEM_P1>>>(M, N, K, swapg, mAh, mAl, mBh, mBl, bias, C, norm, Ohi, Olo);
    } else {
        cudaFuncSetAttribute(tma_gemm<1,0,1>, cudaFuncAttributeMaxDynamicSharedMemorySize, SMEM_P1);
        tma_gemm<1,0,1><<<grid, 256, SMEM_P1>>>(M, N, K, swapg, mAh, mAl, mBh, mBl, bias, C, norm, Ohi, Olo);
    }
}

static inline void zero(float* p, long n) {
    fill_kernel<<<(int)((n + 255) / 256), 256>>>(p, (int)n, 0.0f);
}

static inline void conv_pad(const float* src, __nv_bfloat16* hi, __nv_bfloat16* lo,
                            int M, int K, int Kp) {
    long total = (long)M * Kp;
    conv_pad_kernel<<<(int)((total + 255) / 256), 256>>>(src, hi, lo, M, K, Kp);
}

static inline void transconv(const float* W, void* Thi, __nv_bfloat16* Tlo,
                             int K, int N, int Kp, int mode) {
    dim3 grid((N + 31) / 32, (Kp + 31) / 32);
    transconv_kernel<<<grid, dim3(32, 8)>>>(W, Thi, Tlo, K, N, Kp, mode);
}

static void run_bn(int M, int C, const float* h, const float* g, const float* beta,
                   float* outf, void* ohi, __nv_bfloat16* olo, int mode,
                   float* pbs, float* pbq, float* pmean, float* prstd) {
    int chunks = (M > 20000) ? 128 : 32;
    dim3 grid(C / 32, chunks);
    dim3 blk(32, 8);
    bn_stats_partial<<<grid, blk>>>(M, C, h, pbs, pbq);
    bn_finalize<<<(C + 127) / 128, 128>>>(C, chunks, 1.0f / (float)M, pbs, pbq, pmean, prstd);
    long total = (long)M * C;
    bn_apply_relu_split<<<(int)((total + 255) / 256), 256>>>(total, C, h, pmean, prstd, g, beta,
                                                             outf, ohi, olo, mode);
}

extern "C" void kernel_launch(void* const* d_in, const int* in_sizes, int n_in,
                              void* d_out, int out_size) {
    const float* atom_features = (const float*)d_in[0];
    const float* r             = (const float*)d_in[1];
    const int*   src           = (const int*)d_in[2];
    const int*   dst           = (const int*)d_in[3];
    const float* ae_w   = (const float*)d_in[4];
    const float* ae_b   = (const float*)d_in[5];
    const float* ae_g   = (const float*)d_in[6];
    const float* ae_be  = (const float*)d_in[7];
    const float* ee1_w  = (const float*)d_in[8];
    const float* ee1_b  = (const float*)d_in[9];
    const float* ee1_g  = (const float*)d_in[10];
    const float* ee1_be = (const float*)d_in[11];
    const float* ee2_w  = (const float*)d_in[12];
    const float* ee2_b  = (const float*)d_in[13];
    const float* ee2_g  = (const float*)d_in[14];
    const float* ee2_be = (const float*)d_in[15];
    const float* gcn_w  = (const float*)d_in[16];
    const float* gcn_b  = (const float*)d_in[17];
    const float* sg_w   = (const float*)d_in[18];
    const float* sg_b   = (const float*)d_in[19];
    const float* dg_w   = (const float*)d_in[20];
    const float* dg_b   = (const float*)d_in[21];
    const float* eg_w   = (const float*)d_in[22];
    const float* eg_b   = (const float*)d_in[23];
    const float* fc1_w  = (const float*)d_in[24];
    const float* fc1_b  = (const float*)d_in[25];
    const float* fc2_w  = (const float*)d_in[26];
    const float* fc2_b  = (const float*)d_in[27];
    const float* fc3_w  = (const float*)d_in[28];
    const float* fc3_b  = (const float*)d_in[29];

    const int N = in_sizes[0] / 92;
    const int E = in_sizes[2];
    encode_fn_t enc = get_encoder();

    float* px    = symaddr(g_x);
    float* ppre  = symaddr(g_pre);
    float* pgate = symaddr(g_gate);
    float* pagg  = symaddr(g_agg);
    float* pbond = symaddr(g_bond);
    float* ph1   = symaddr(g_h1);
    float* py    = symaddr(g_y);
    float* pee   = symaddr(g_ee);
    float* pdegs = symaddr(g_degs);
    float* pdegd = symaddr(g_degd);
    float* pnl   = symaddr(g_nl);
    float* pnr   = symaddr(g_nr);
    float* pbs   = symaddr(g_bps);
    float* pbq   = symaddr(g_bpq);
    float* pmean = symaddr(g_mean);
    float* prstd = symaddr(g_rstd);
    float* pgb   = symaddr(g_gateb);

    __nv_bfloat16 *xa_h = symaddr_bf(g_xa_hi),  *xa_l = symaddr_bf(g_xa_lo);
    __nv_bfloat16 *x_h  = symaddr_bf(g_x_hi),   *x_l  = symaddr_bf(g_x_lo);
    __nv_bfloat16 *ag_h = symaddr_bf(g_agg_hi), *ag_l = symaddr_bf(g_agg_lo);
    __nv_bfloat16 *f1_h = symaddr_bf(g_fc1_hi), *f1_l = symaddr_bf(g_fc1_lo);
    __half        *f2_h = symaddr_h(g_fc2_h);
    __nv_bfloat16 *rb_h = symaddr_bf(g_rbf_hi), *rb_l = symaddr_bf(g_rbf_lo);
    __nv_bfloat16 *h1_h = symaddr_bf(g_h1_hi),  *h1_l = symaddr_bf(g_h1_lo);
    __half        *y_h  = symaddr_h(g_y_h);

    __nv_bfloat16 *aew_h = symaddr_bf(g_aewT_hi),  *aew_l = symaddr_bf(g_aewT_lo);
    __nv_bfloat16 *e1w_h = symaddr_bf(g_ee1wT_hi), *e1w_l = symaddr_bf(g_ee1wT_lo);
    __nv_bfloat16 *e2w_h = symaddr_bf(g_ee2wT_hi), *e2w_l = symaddr_bf(g_ee2wT_lo);
    __nv_bfloat16 *gtw_h = symaddr_bf(g_gatewT_hi),*gtw_l = symaddr_bf(g_gatewT_lo);
    __half        *egw_h = symaddr_h(g_egwT_h);
    __nv_bfloat16 *gw_h  = symaddr_bf(g_gwT_hi),   *gw_l  = symaddr_bf(g_gwT_lo);
    __nv_bfloat16 *f1w_h = symaddr_bf(g_fc1wT_hi), *f1w_l = symaddr_bf(g_fc1wT_lo);
    __nv_bfloat16 *f2w_h = symaddr_bf(g_fc2wT_hi), *f2w_l = symaddr_bf(g_fc2wT_lo);
    __half        *f3w_h = symaddr_h(g_fc3wT_h);

    // ---- launches 0..4: prerequisites for the ee1 GEMM (launch #5 = GEMM for ncu) ----
    bond_kernel<<<(E + 255) / 256, 256>>>(E, r, pbond);                         // 0
    {
        long tot = (long)E * 80;
        rbf_split_kernel<<<(int)((tot + 255) / 256), 256>>>((int)tot, pbond, rb_h, rb_l); // 1
    }
    transconv(ee1_w, e1w_h, e1w_l, 80, 64, 128, 0);                             // 2
    conv_pad(atom_features, xa_h, xa_l, N, 92, 128);                            // 3
    transconv(ae_w, aew_h, aew_l, 92, 256, 128, 0);                             // 4
    launch_tc(enc, 0, 0, 0, 0, E, 64, 128, E, 128,                              // 5 (profiled)
              rb_h, rb_l, e1w_h, e1w_l, ee1_b, ph1, nullptr, nullptr, nullptr);

    // ---- remaining weight prep ----
    transconv(ee2_w, e2w_h, e2w_l, 64, 256, 64, 0);
    for (int i = 0; i < 4; i++) {
        long wo = (long)i * 256 * 256;
        long go = (long)i * 512 * 256;
        transconv(sg_w + wo, gtw_h + go, gtw_l + go, 256, 256, 256, 0);
        transconv(dg_w + wo, gtw_h + go + 256 * 256, gtw_l + go + 256 * 256, 256, 256, 256, 0);
        transconv(eg_w + wo, egw_h + wo, nullptr, 256, 256, 256, 1);    // fp16
        transconv(gcn_w + wo, gw_h + wo, gw_l + wo, 256, 256, 256, 0);
    }
    transconv(fc1_w, f1w_h, f1w_l, 256, 1024, 256, 0);
    transconv(fc2_w, f2w_h, f2w_l, 1024, 2048, 1024, 0);
    transconv(fc3_w, f3w_h, nullptr, 2048, 10000, 2048, 1);             // fp16
    gate_bias_concat<<<8, 256>>>(sg_b, dg_b, pgb);

    // ---- degrees & norms ----
    zero(pdegs, N); zero(pdegd, N);
    deg_kernel<<<(E + 255) / 256, 256>>>(E, src, dst, pdegs, pdegd);
    norm_kernel<<<(N + 255) / 256, 256>>>(N, pdegs, pdegd, pnl, pnr);

    // ---- atom embedding MLP ----
    launch_tc(enc, 0, 0, 0, 0, N, 256, 128, NPAD, 256,
              xa_h, xa_l, aew_h, aew_l, ae_b, ppre, nullptr, nullptr, nullptr);
    run_bn(N, 256, ppre, ae_g, ae_be, px, x_h, x_l, 0, pbs, pbq, pmean, prstd);

    // ---- edge embedding MLP chain ----
    run_bn(E, 64, ph1, ee1_g, ee1_be, nullptr, h1_h, h1_l, 0, pbs, pbq, pmean, prstd);
    launch_tc(enc, 0, 0, 0, 0, E, 256, 64, E, 256,
              h1_h, h1_l, e2w_h, e2w_l, ee2_b, py, nullptr, nullptr, nullptr);
    run_bn(E, 256, py, ee2_g, ee2_be, nullptr, y_h, nullptr, 1, pbs, pbq, pmean, prstd); // y fp16

    // ---- 4 gated GCN layers ----
    for (int i = 0; i < 4; i++) {
        long wo = (long)i * 256 * 256;
        long go = (long)i * 512 * 256;
        const float* egb = eg_b + i * 256;
        const float* gb  = gcn_b + i * 256;

        launch_tc(enc, 0, 0, 0, 0, N, 512, 256, NPAD, 512,
                  x_h, x_l, gtw_h + go, gtw_l + go, pgb + i * 512, pgate, nullptr, nullptr, nullptr);
        // fp16 single-product edge gate GEMM
        launch_tc(enc, 0, 0, 1, 0, E, 256, 256, E, 256,
                  y_h, nullptr, egw_h + wo, nullptr, egb, pee, nullptr, nullptr, nullptr);

        zero(pagg, (long)N * 256);
        edge_gate_agg<<<(E + 3) / 4, 256>>>(E, px, pgate, pee, src, dst, pnl, pagg);
        conv_pad(pagg, ag_h, ag_l, N, 256, 256);

        launch_tc(enc, 2, 1, 0, 0, N, 256, 256, NPAD, 256,
                  ag_h, ag_l, gw_h + wo, gw_l + wo, gb, px, pnr, x_h, x_l);
    }

    // ---- readout MLP ----
    launch_tc(enc, 1, 1, 0, 0, N, 1024, 256, NPAD, 1024,
              x_h, x_l, f1w_h, f1w_l, fc1_b, nullptr, nullptr, f1_h, f1_l);
    // fc2: bf16-split inputs, fp16 single output
    launch_tc(enc, 1, 2, 0, 1, N, 2048, 1024, NPAD, 2048,
              f1_h, f1_l, f2w_h, f2w_l, fc2_b, nullptr, nullptr, f2_h, nullptr);
    // fc3: fp16 single product
    launch_tc(enc, 1, 0, 1, 1, N, 10000, 2048, NPAD, 10112,
              f2_h, nullptr, f3w_h, nullptr, fc3_b, (float*)d_out, nullptr, nullptr, nullptr);
}

// round 17
// speedup vs baseline: 5.5095x; 1.1180x over previous
#include <cuda_runtime.h>
#include <cuda.h>
#include <cuda_bf16.h>
#include <cuda_fp16.h>
#include <stdint.h>
#include <math.h>

// ---------------- problem-size constants ----------------
#define NMAXV 5000
#define NPAD  5120
#define EMAXV 160000
#define HD 256

// ---------------- fp32 scratch ----------------
__device__ float g_x   [NMAXV * 256];
__device__ float g_pre [NMAXV * 256];
__device__ float g_gate[NMAXV * 512];
__device__ float g_agg [NMAXV * 256];
__device__ float g_bond[EMAXV];
__device__ float g_h1  [EMAXV * 64];
__device__ float g_y   [EMAXV * 256];
__device__ float g_degs[NMAXV];
__device__ float g_degd[NMAXV];
__device__ float g_nl  [NMAXV];
__device__ float g_nr  [NMAXV];
__device__ float g_bps [128 * 256];
__device__ float g_bpq [128 * 256];
__device__ float g_mean[256];
__device__ float g_rstd[256];
__device__ float g_gateb[4 * 512];

// ---------------- activations ----------------
__device__ __align__(128) __nv_bfloat16 g_xa_hi[NPAD * 128];
__device__ __align__(128) __nv_bfloat16 g_xa_lo[NPAD * 128];
__device__ __align__(128) __half        g_x_f16[NPAD * 256];        // x fp16 (gates+fc1)
__device__ __align__(128) __nv_bfloat16 g_agg_hi[NPAD * 256];
__device__ __align__(128) __nv_bfloat16 g_agg_lo[NPAD * 256];
__device__ __align__(128) __half        g_fc1_f16[NPAD * 1024];
__device__ __align__(128) __half        g_fc2_f16[NPAD * 2048];
__device__ __align__(128) __nv_bfloat16 g_rbf_hi[EMAXV * 128];
__device__ __align__(128) __nv_bfloat16 g_rbf_lo[EMAXV * 128];
__device__ __align__(128) __half        g_h1_f16[EMAXV * 64];
__device__ __align__(128) __half        g_y_f16 [EMAXV * 256];
__device__ __align__(128) __half        g_ee_f16[EMAXV * 256];      // edge gate logits fp16

// ---------------- weights: transposed [rowsPad][Kpad] ----------------
__device__ __align__(128) __nv_bfloat16 g_aewT_hi [256 * 128];
__device__ __align__(128) __nv_bfloat16 g_aewT_lo [256 * 128];
__device__ __align__(128) __nv_bfloat16 g_ee1wT_hi[128 * 128];
__device__ __align__(128) __nv_bfloat16 g_ee1wT_lo[128 * 128];
__device__ __align__(128) __half        g_ee2wT_f16[256 * 64];
__device__ __align__(128) __half        g_gatewT_f16[4 * 512 * 256];
__device__ __align__(128) __half        g_egwT_f16[4 * 256 * 256];
__device__ __align__(128) __nv_bfloat16 g_gwT_hi  [4 * 256 * 256];
__device__ __align__(128) __nv_bfloat16 g_gwT_lo  [4 * 256 * 256];
__device__ __align__(128) __half        g_fc1wT_f16[1024 * 256];
__device__ __align__(128) __half        g_fc2wT_f16[2048 * 1024];
__device__ __align__(128) __half        g_fc3wT_f16[10112 * 2048];

// ---------------- small utility kernels ----------------
__global__ void fill_kernel(float* p, int n, float v) {
    int i = blockIdx.x * blockDim.x + threadIdx.x;
    if (i < n) p[i] = v;
}

__global__ void gate_bias_concat(const float* __restrict__ sgb, const float* __restrict__ dgb,
                                 float* out) {
    int i = blockIdx.x * blockDim.x + threadIdx.x;
    if (i < 4 * 512) {
        int layer = i >> 9;
        int c = i & 511;
        out[i] = (c < 256) ? sgb[layer * 256 + c] : dgb[layer * 256 + (c - 256)];
    }
}

__global__ void deg_kernel(int E, const int* __restrict__ src, const int* __restrict__ dst,
                           float* degs, float* degd) {
    int e = blockIdx.x * blockDim.x + threadIdx.x;
    if (e < E) {
        atomicAdd(&degs[src[e]], 1.0f);
        atomicAdd(&degd[dst[e]], 1.0f);
    }
}

__global__ void norm_kernel(int N, const float* __restrict__ degs, const float* __restrict__ degd,
                            float* nl, float* nr) {
    int i = blockIdx.x * blockDim.x + threadIdx.x;
    if (i < N) {
        nl[i] = rsqrtf(fmaxf(degs[i], 1.0f));
        nr[i] = rsqrtf(fmaxf(degd[i], 1.0f));
    }
}

__global__ void bond_kernel(int E, const float* __restrict__ r, float* bond) {
    int e = blockIdx.x * blockDim.x + threadIdx.x;
    if (e < E) {
        float a = r[e * 3 + 0], b = r[e * 3 + 1], c = r[e * 3 + 2];
        bond[e] = sqrtf(a * a + b * b + c * c);
    }
}

__global__ void rbf_split_kernel(int total, const float* __restrict__ bond,
                                 __nv_bfloat16* __restrict__ hi, __nv_bfloat16* __restrict__ lo) {
    int idx = blockIdx.x * blockDim.x + threadIdx.x;
    if (idx < total) {
        int e = idx / 80;
        int j = idx - e * 80;
        const float gamma = 79.0f / 8.0f;
        float cj = (8.0f / 79.0f) * (float)j;
        float d = bond[e] - cj;
        float v = expf(-gamma * d * d);
        __nv_bfloat16 h = __float2bfloat16(v);
        long o = (long)e * 128 + j;
        hi[o] = h;
        lo[o] = __float2bfloat16(v - __bfloat162float(h));
    }
}

__global__ void conv_pad_kernel(const float* __restrict__ src,
                                __nv_bfloat16* __restrict__ hi, __nv_bfloat16* __restrict__ lo,
                                int M, int K, int Kp) {
    long idx = (long)blockIdx.x * blockDim.x + threadIdx.x;
    long total = (long)M * Kp;
    if (idx >= total) return;
    int r = (int)(idx / Kp);
    int c = (int)(idx - (long)r * Kp);
    float v = (c < K) ? src[(long)r * K + c] : 0.0f;
    __nv_bfloat16 h = __float2bfloat16(v);
    hi[idx] = h;
    lo[idx] = __float2bfloat16(v - __bfloat162float(h));
}

// transpose + convert: mode 0 = bf16 hi/lo pair, 1 = fp16 single
__global__ void transconv_kernel(const float* __restrict__ W,
                                 void* __restrict__ Thi, __nv_bfloat16* __restrict__ Tlo,
                                 int K, int N, int Kp, int mode) {
    __shared__ float t[32][33];
    int k0 = blockIdx.y * 32, n0 = blockIdx.x * 32;
    int tx = threadIdx.x, ty = threadIdx.y;
    #pragma unroll
    for (int i = ty; i < 32; i += 8) {
        int k = k0 + i, n = n0 + tx;
        t[i][tx] = (k < K && n < N) ? W[(long)k * N + n] : 0.0f;
    }
    __syncthreads();
    #pragma unroll
    for (int i = ty; i < 32; i += 8) {
        int n = n0 + i, k = k0 + tx;
        if (n < N && k < Kp) {
            float v = t[tx][i];
            long o = (long)n * Kp + k;
            if (mode == 0) {
                __nv_bfloat16 h = __float2bfloat16(v);
                ((__nv_bfloat16*)Thi)[o] = h;
                Tlo[o] = __float2bfloat16(v - __bfloat162float(h));
            } else {
                ((__half*)Thi)[o] = __float2half(v);
            }
        }
    }
}

// ---------------- BatchNorm ----------------
__global__ void bn_stats_partial(int M, int C, const float* __restrict__ h,
                                 float* psum, float* psumsq) {
    int c = blockIdx.x * 32 + threadIdx.x;
    int rowsPerChunk = (M + gridDim.y - 1) / gridDim.y;
    int r0 = blockIdx.y * rowsPerChunk;
    int r1 = min(M, r0 + rowsPerChunk);
    float s = 0.f, s2 = 0.f;
    if (c < C) {
        for (int r = r0 + threadIdx.y; r < r1; r += 8) {
            float v = h[(long)r * C + c];
            s += v; s2 += v * v;
        }
    }
    __shared__ float sh[2][8][32];
    sh[0][threadIdx.y][threadIdx.x] = s;
    sh[1][threadIdx.y][threadIdx.x] = s2;
    __syncthreads();
    if (threadIdx.y == 0 && c < C) {
        float ts = 0.f, t2 = 0.f;
        #pragma unroll
        for (int i = 0; i < 8; i++) { ts += sh[0][i][threadIdx.x]; t2 += sh[1][i][threadIdx.x]; }
        psum[blockIdx.y * C + c] = ts;
        psumsq[blockIdx.y * C + c] = t2;
    }
}

__global__ void bn_finalize(int C, int chunks, float invM,
                            const float* __restrict__ psum, const float* __restrict__ psumsq,
                            float* mean, float* rstd) {
    int c = blockIdx.x * blockDim.x + threadIdx.x;
    if (c < C) {
        float s = 0.f, s2 = 0.f;
        for (int k = 0; k < chunks; k++) { s += psum[k * C + c]; s2 += psumsq[k * C + c]; }
        float m = s * invM;
        float var = fmaxf(s2 * invM - m * m, 0.0f);
        mean[c] = m;
        rstd[c] = rsqrtf(var + 1e-5f);
    }
}

// BN apply + ReLU; writes fp16 to ohi; optional fp32 outf.
__global__ void bn_apply_relu_f16(long total, int C, const float* __restrict__ h,
                                  const float* __restrict__ mean, const float* __restrict__ rstd,
                                  const float* __restrict__ g, const float* __restrict__ beta,
                                  float* outf, __half* __restrict__ ohi) {
    long idx = (long)blockIdx.x * blockDim.x + threadIdx.x;
    if (idx < total) {
        int c = (int)(idx % C);
        float v = g[c] * (h[idx] - mean[c]) * rstd[c] + beta[c];
        v = fmaxf(v, 0.0f);
        if (outf) outf[idx] = v;
        ohi[idx] = __float2half(v);
    }
}

// ---------------- edge gate + scatter-aggregate (ee in fp16) ----------------
__global__ void edge_gate_agg(int E, const float* __restrict__ x,
                              const float* __restrict__ gate,
                              const __half* __restrict__ ee,
                              const int* __restrict__ src, const int* __restrict__ dst,
                              const float* __restrict__ nl, float* agg) {
    int e = blockIdx.x * 4 + (threadIdx.x >> 6);
    if (e >= E) return;
    int j = (threadIdx.x & 63) * 4;
    int s = src[e], d = dst[e];
    float nls = nl[s];
    float4 es = *(const float4*)&gate[s * 512 + j];
    float4 ed = *(const float4*)&gate[d * 512 + 256 + j];
    const __half2* evp = (const __half2*)&ee[(long)e * HD + j];
    float2 e01 = __half22float2(evp[0]);
    float2 e23 = __half22float2(evp[1]);
    float4 xv = *(const float4*)&x[s * HD + j];
    float m0 = xv.x * nls / (1.0f + expf(-(es.x + ed.x + e01.x)));
    float m1 = xv.y * nls / (1.0f + expf(-(es.y + ed.y + e01.y)));
    float m2 = xv.z * nls / (1.0f + expf(-(es.z + ed.z + e23.x)));
    float m3 = xv.w * nls / (1.0f + expf(-(es.w + ed.w + e23.y)));
    float* a = &agg[d * HD + j];
    atomicAdd(a + 0, m0);
    atomicAdd(a + 1, m1);
    atomicAdd(a + 2, m2);
    atomicAdd(a + 3, m3);
}

// ================= TMA + mma.sync GEMM =================
// PREC 0: split-bf16 3-product; PREC 1: fp16 single product.
// EPI 0: acc+bias  1: relu(acc+bias)  2: residual (C += acc*norm + bias)
// SPLIT 0: fp32 only  2: fp16 out (EPI0/1: fp16 only; EPI2: fp32 + fp16)

#define MBAR_INIT(addr, cnt) \
    asm volatile("mbarrier.init.shared.b64 [%0], %1;" :: "r"(addr), "r"(cnt) : "memory")
#define MBAR_EXPECT_TX(addr, bytes) \
    asm volatile("mbarrier.arrive.expect_tx.shared.b64 _, [%0], %1;" :: "r"(addr), "r"(bytes) : "memory")

__device__ __forceinline__ void mbar_wait(uint32_t addr, uint32_t parity) {
    asm volatile(
        "{\n\t"
        ".reg .pred P;\n\t"
        "WAITLOOP%=:\n\t"
        "mbarrier.try_wait.parity.acquire.cta.shared::cta.b64 P, [%0], %1, 0x989680;\n\t"
        "@!P bra WAITLOOP%=;\n\t"
        "}"
        :: "r"(addr), "r"(parity) : "memory");
}

#define TMA2D(saddr, mapp, cx, cy, mbar) \
    asm volatile("cp.async.bulk.tensor.2d.shared::cta.global.tile.mbarrier::complete_tx::bytes " \
                 "[%0], [%1, {%2, %3}], [%4];" \
                 :: "r"(saddr), "l"(mapp), "r"(cx), "r"(cy), "r"(mbar) : "memory")

#define LDSM4(R0, R1, R2, R3, addr) \
    asm volatile("ldmatrix.sync.aligned.m8n8.x4.shared.b16 {%0,%1,%2,%3}, [%4];" \
                 : "=r"(R0), "=r"(R1), "=r"(R2), "=r"(R3) : "r"(addr))

#define MMABF16(d, a, b) \
    asm volatile("mma.sync.aligned.m16n8k16.row.col.f32.bf16.bf16.f32 " \
                 "{%0,%1,%2,%3}, {%4,%5,%6,%7}, {%8,%9}, {%0,%1,%2,%3};" \
                 : "+f"((d)[0]), "+f"((d)[1]), "+f"((d)[2]), "+f"((d)[3]) \
                 : "r"((a)[0]), "r"((a)[1]), "r"((a)[2]), "r"((a)[3]), \
                   "r"((b)[0]), "r"((b)[1]))

#define MMAFP16(d, a, b) \
    asm volatile("mma.sync.aligned.m16n8k16.row.col.f32.f16.f16.f32 " \
                 "{%0,%1,%2,%3}, {%4,%5,%6,%7}, {%8,%9}, {%0,%1,%2,%3};" \
                 : "+f"((d)[0]), "+f"((d)[1]), "+f"((d)[2]), "+f"((d)[3]) \
                 : "r"((a)[0]), "r"((a)[1]), "r"((a)[2]), "r"((a)[3]), \
                   "r"((b)[0]), "r"((b)[1]))

__device__ __forceinline__ uint32_t swadr(uint32_t base, int rl, int cb) {
    return base + rl * 128 + (cb ^ ((rl & 7) << 4));
}

template <int EPI, int SPLIT, int PREC>
__global__ __launch_bounds__(256, 1) void tma_gemm(
    int M, int N, int K, int swapg,
    const __grid_constant__ CUtensorMap tmAh,
    const __grid_constant__ CUtensorMap tmAl,
    const __grid_constant__ CUtensorMap tmBh,
    const __grid_constant__ CUtensorMap tmBl,
    const float* __restrict__ bias, float* __restrict__ C,
    const float* __restrict__ norm,
    __half* __restrict__ Oh) {
    constexpr int NSTG = PREC ? 5 : 3;
    constexpr int STB  = PREC ? 32768 : 65536;
    extern __shared__ char smem[];
    uint32_t sbraw = (uint32_t)__cvta_generic_to_shared(smem);
    uint32_t sb = (sbraw + 1023u) & ~1023u;

    const int tid = threadIdx.x, wid = tid >> 5, lane = tid & 31;
    const int m0 = (swapg ? blockIdx.x : blockIdx.y) * 128;
    const int n0 = (swapg ? blockIdx.y : blockIdx.x) * 128;
    const int nc = K / 64;
    const int wm = (wid & 1) * 64;
    const int wn = (wid >> 1) * 32;

    uint32_t fullb = sb;
    uint32_t tile0 = sb + 1024;

    if (tid == 0) {
        #pragma unroll
        for (int s = 0; s < NSTG; s++) MBAR_INIT(fullb + 8 * s, 1);
    }
    __syncthreads();

    auto issue = [&](int chunk, int s) {
        uint32_t fb = fullb + 8 * s;
        MBAR_EXPECT_TX(fb, STB);
        uint32_t tb = tile0 + s * STB;
        int k0 = chunk * 64;
        if (PREC) {
            TMA2D(tb,         (const void*)&tmAh, k0, m0, fb);
            TMA2D(tb + 16384, (const void*)&tmBh, k0, n0, fb);
        } else {
            TMA2D(tb,         (const void*)&tmAh, k0, m0, fb);
            TMA2D(tb + 16384, (const void*)&tmAl, k0, m0, fb);
            TMA2D(tb + 32768, (const void*)&tmBh, k0, n0, fb);
            TMA2D(tb + 49152, (const void*)&tmBl, k0, n0, fb);
        }
    };

    if (tid == 0) {
        int P = nc < NSTG ? nc : NSTG;
        for (int s = 0; s < P; s++) issue(s, s);
    }

    float acc[4][4][4];
    #pragma unroll
    for (int i = 0; i < 4; i++)
        #pragma unroll
        for (int j = 0; j < 4; j++)
            #pragma unroll
            for (int q = 0; q < 4; q++) acc[i][j][q] = 0.0f;

    for (int c = 0; c < nc; c++) {
        int s = c % NSTG;
        uint32_t ph = (uint32_t)((c / NSTG) & 1);
        mbar_wait(fullb + 8 * s, ph);
        uint32_t tb = tile0 + s * STB;
        uint32_t tAh = tb;
        uint32_t tBh = tb + (PREC ? 16384 : 32768);
        uint32_t tAl = tb + 16384, tBl = tb + 49152;

        #pragma unroll
        for (int ks = 0; ks < 4; ks++) {
            int cbA = ks * 32 + ((lane >> 4) & 1) * 16;
            uint32_t afh[4][4], afl[4][4];
            #pragma unroll
            for (int mi = 0; mi < 4; mi++) {
                int rl = wm + mi * 16 + (lane & 15);
                LDSM4(afh[mi][0], afh[mi][1], afh[mi][2], afh[mi][3], swadr(tAh, rl, cbA));
                if (!PREC)
                    LDSM4(afl[mi][0], afl[mi][1], afl[mi][2], afl[mi][3], swadr(tAl, rl, cbA));
            }
            int cbB = ks * 32 + ((lane >> 3) & 1) * 16;
            uint32_t bfh[4][2], bfl[4][2];
            #pragma unroll
            for (int p = 0; p < 2; p++) {
                int rl = wn + (2 * p + ((lane >> 4) & 1)) * 8 + (lane & 7);
                LDSM4(bfh[2*p][0], bfh[2*p][1], bfh[2*p+1][0], bfh[2*p+1][1], swadr(tBh, rl, cbB));
                if (!PREC)
                    LDSM4(bfl[2*p][0], bfl[2*p][1], bfl[2*p+1][0], bfl[2*p+1][1], swadr(tBl, rl, cbB));
            }
            #pragma unroll
            for (int mi = 0; mi < 4; mi++)
                #pragma unroll
                for (int ni = 0; ni < 4; ni++) {
                    if (PREC) {
                        MMAFP16(acc[mi][ni], afh[mi], bfh[ni]);
                    } else {
                        MMABF16(acc[mi][ni], afh[mi], bfh[ni]);
                        MMABF16(acc[mi][ni], afh[mi], bfl[ni]);
                        MMABF16(acc[mi][ni], afl[mi], bfh[ni]);
                    }
                }
        }
        __syncthreads();
        if (tid == 0 && c + NSTG < nc) issue(c + NSTG, s);
    }

    // ---- epilogue ----
    #pragma unroll
    for (int mi = 0; mi < 4; mi++) {
        #pragma unroll
        for (int half = 0; half < 2; half++) {
            int r = m0 + wm + mi * 16 + (lane >> 2) + half * 8;
            if (r >= M) continue;
            float nr = (EPI == 2) ? norm[r] : 0.0f;
            #pragma unroll
            for (int ni = 0; ni < 4; ni++) {
                int cc = n0 + wn + ni * 8 + (lane & 3) * 2;
                if (cc >= N) continue;
                long idx = (long)r * N + cc;
                float a0 = acc[mi][ni][half * 2 + 0];
                float a1 = acc[mi][ni][half * 2 + 1];
                float v0, v1;
                if (EPI == 0) {
                    v0 = a0 + bias[cc]; v1 = a1 + bias[cc + 1];
                    if (SPLIT == 0) { C[idx] = v0; C[idx + 1] = v1; }
                } else if (EPI == 1) {
                    v0 = fmaxf(a0 + bias[cc], 0.0f); v1 = fmaxf(a1 + bias[cc + 1], 0.0f);
                    if (SPLIT == 0) { C[idx] = v0; C[idx + 1] = v1; }
                } else {
                    v0 = C[idx]     + a0 * nr + bias[cc];
                    v1 = C[idx + 1] + a1 * nr + bias[cc + 1];
                    C[idx] = v0; C[idx + 1] = v1;
                }
                if (SPLIT == 2) {
                    __half2 hh = __floats2half2_rn(v0, v1);
                    *reinterpret_cast<__half2*>(&Oh[idx]) = hh;
                }
            }
        }
    }
}

// ---------------- host-side helpers ----------------
static float* symaddr(const void* sym) {
    void* p = nullptr;
    cudaGetSymbolAddress(&p, sym);
    return (float*)p;
}
static __nv_bfloat16* symaddr_bf(const void* sym) {
    void* p = nullptr;
    cudaGetSymbolAddress(&p, sym);
    return (__nv_bfloat16*)p;
}
static __half* symaddr_h(const void* sym) {
    void* p = nullptr;
    cudaGetSymbolAddress(&p, sym);
    return (__half*)p;
}

typedef CUresult (*encode_fn_t)(CUtensorMap*, CUtensorMapDataType, cuuint32_t, void*,
                                const cuuint64_t*, const cuuint64_t*, const cuuint32_t*,
                                const cuuint32_t*, CUtensorMapInterleave, CUtensorMapSwizzle,
                                CUtensorMapL2promotion, CUtensorMapFloatOOBfill);

static encode_fn_t get_encoder() {
    void* fp = nullptr;
    cudaDriverEntryPointQueryResult qr;
    cudaGetDriverEntryPoint("cuTensorMapEncodeTiled", &fp, cudaEnableDefault, &qr);
    return (encode_fn_t)fp;
}

static void make_map(encode_fn_t enc, CUtensorMap* m, const void* p,
                     long K, long rowsPad, int fp16) {
    cuuint64_t gd[2] = {(cuuint64_t)K, (cuuint64_t)rowsPad};
    cuuint64_t gs[1] = {(cuuint64_t)(K * 2)};
    cuuint32_t box[2] = {64, 128};
    cuuint32_t es[2] = {1, 1};
    enc(m, fp16 ? CU_TENSOR_MAP_DATA_TYPE_FLOAT16 : CU_TENSOR_MAP_DATA_TYPE_BFLOAT16,
        2, (void*)p, gd, gs, box, es,
        CU_TENSOR_MAP_INTERLEAVE_NONE, CU_TENSOR_MAP_SWIZZLE_128B,
        CU_TENSOR_MAP_L2_PROMOTION_L2_128B, CU_TENSOR_MAP_FLOAT_OOB_FILL_NONE);
}

#define SMEM_P0 (2048 + 3 * 65536)
#define SMEM_P1 (2048 + 5 * 32768)

// mode encodes (EPI, SPLIT, PREC)
static void launch_tc(encode_fn_t enc, int epi, int split, int prec, int swapg,
                      int M, int N, int K, int Mpad, int Npad,
                      const void* Ah, const void* Al,
                      const void* Bh, const void* Bl,
                      const float* bias, float* C, const float* norm,
                      __half* Oh) {
    CUtensorMap mAh, mAl, mBh, mBl;
    make_map(enc, &mAh, Ah, K, Mpad, prec);
    make_map(enc, &mBh, Bh, K, Npad, prec);
    if (!prec) {
        make_map(enc, &mAl, Al, K, Mpad, 0);
        make_map(enc, &mBl, Bl, K, Npad, 0);
    } else { mAl = mAh; mBl = mBh; }
    int mt = (M + 127) / 128, ntt = (N + 127) / 128;
    dim3 grid(swapg ? mt : ntt, swapg ? ntt : mt);
    if (prec == 0 && epi == 0) {
        cudaFuncSetAttribute(tma_gemm<0,0,0>, cudaFuncAttributeMaxDynamicSharedMemorySize, SMEM_P0);
        tma_gemm<0,0,0><<<grid, 256, SMEM_P0>>>(M, N, K, swapg, mAh, mAl, mBh, mBl, bias, C, norm, Oh);
    } else if (prec == 0 && epi == 2) {
        cudaFuncSetAttribute(tma_gemm<2,2,0>, cudaFuncAttributeMaxDynamicSharedMemorySize, SMEM_P0);
        tma_gemm<2,2,0><<<grid, 256, SMEM_P0>>>(M, N, K, swapg, mAh, mAl, mBh, mBl, bias, C, norm, Oh);
    } else if (prec == 1 && epi == 0 && split == 0) {
        cudaFuncSetAttribute(tma_gemm<0,0,1>, cudaFuncAttributeMaxDynamicSharedMemorySize, SMEM_P1);
        tma_gemm<0,0,1><<<grid, 256, SMEM_P1>>>(M, N, K, swapg, mAh, mAl, mBh, mBl, bias, C, norm, Oh);
    } else if (prec == 1 && epi == 0 && split == 2) {
        cudaFuncSetAttribute(tma_gemm<0,2,1>, cudaFuncAttributeMaxDynamicSharedMemorySize, SMEM_P1);
        tma_gemm<0,2,1><<<grid, 256, SMEM_P1>>>(M, N, K, swapg, mAh, mAl, mBh, mBl, bias, C, norm, Oh);
    } else if (prec == 1 && epi == 1 && split == 2) {
        cudaFuncSetAttribute(tma_gemm<1,2,1>, cudaFuncAttributeMaxDynamicSharedMemorySize, SMEM_P1);
        tma_gemm<1,2,1><<<grid, 256, SMEM_P1>>>(M, N, K, swapg, mAh, mAl, mBh, mBl, bias, C, norm, Oh);
    } else {
        cudaFuncSetAttribute(tma_gemm<1,0,1>, cudaFuncAttributeMaxDynamicSharedMemorySize, SMEM_P1);
        tma_gemm<1,0,1><<<grid, 256, SMEM_P1>>>(M, N, K, swapg, mAh, mAl, mBh, mBl, bias, C, norm, Oh);
    }
}

static inline void zero(float* p, long n) {
    fill_kernel<<<(int)((n + 255) / 256), 256>>>(p, (int)n, 0.0f);
}

static inline void conv_pad(const float* src, __nv_bfloat16* hi, __nv_bfloat16* lo,
                            int M, int K, int Kp) {
    long total = (long)M * Kp;
    conv_pad_kernel<<<(int)((total + 255) / 256), 256>>>(src, hi, lo, M, K, Kp);
}

static inline void transconv(const float* W, void* Thi, __nv_bfloat16* Tlo,
                             int K, int N, int Kp, int mode) {
    dim3 grid((N + 31) / 32, (Kp + 31) / 32);
    transconv_kernel<<<grid, dim3(32, 8)>>>(W, Thi, Tlo, K, N, Kp, mode);
}

static void run_bn(int M, int C, const float* h, const float* g, const float* beta,
                   float* outf, __half* ohi,
                   float* pbs, float* pbq, float* pmean, float* prstd) {
    int chunks = (M > 20000) ? 128 : 32;
    dim3 grid(C / 32, chunks);
    dim3 blk(32, 8);
    bn_stats_partial<<<grid, blk>>>(M, C, h, pbs, pbq);
    bn_finalize<<<(C + 127) / 128, 128>>>(C, chunks, 1.0f / (float)M, pbs, pbq, pmean, prstd);
    long total = (long)M * C;
    bn_apply_relu_f16<<<(int)((total + 255) / 256), 256>>>(total, C, h, pmean, prstd, g, beta,
                                                           outf, ohi);
}

extern "C" void kernel_launch(void* const* d_in, const int* in_sizes, int n_in,
                              void* d_out, int out_size) {
    const float* atom_features = (const float*)d_in[0];
    const float* r             = (const float*)d_in[1];
    const int*   src           = (const int*)d_in[2];
    const int*   dst           = (const int*)d_in[3];
    const float* ae_w   = (const float*)d_in[4];
    const float* ae_b   = (const float*)d_in[5];
    const float* ae_g   = (const float*)d_in[6];
    const float* ae_be  = (const float*)d_in[7];
    const float* ee1_w  = (const float*)d_in[8];
    const float* ee1_b  = (const float*)d_in[9];
    const float* ee1_g  = (const float*)d_in[10];
    const float* ee1_be = (const float*)d_in[11];
    const float* ee2_w  = (const float*)d_in[12];
    const float* ee2_b  = (const float*)d_in[13];
    const float* ee2_g  = (const float*)d_in[14];
    const float* ee2_be = (const float*)d_in[15];
    const float* gcn_w  = (const float*)d_in[16];
    const float* gcn_b  = (const float*)d_in[17];
    const float* sg_w   = (const float*)d_in[18];
    const float* sg_b   = (const float*)d_in[19];
    const float* dg_w   = (const float*)d_in[20];
    const float* dg_b   = (const float*)d_in[21];
    const float* eg_w   = (const float*)d_in[22];
    const float* eg_b   = (const float*)d_in[23];
    const float* fc1_w  = (const float*)d_in[24];
    const float* fc1_b  = (const float*)d_in[25];
    const float* fc2_w  = (const float*)d_in[26];
    const float* fc2_b  = (const float*)d_in[27];
    const float* fc3_w  = (const float*)d_in[28];
    const float* fc3_b  = (const float*)d_in[29];

    const int N = in_sizes[0] / 92;
    const int E = in_sizes[2];
    encode_fn_t enc = get_encoder();

    float* px    = symaddr(g_x);
    float* ppre  = symaddr(g_pre);
    float* pgate = symaddr(g_gate);
    float* pagg  = symaddr(g_agg);
    float* pbond = symaddr(g_bond);
    float* ph1   = symaddr(g_h1);
    float* py    = symaddr(g_y);
    float* pdegs = symaddr(g_degs);
    float* pdegd = symaddr(g_degd);
    float* pnl   = symaddr(g_nl);
    float* pnr   = symaddr(g_nr);
    float* pbs   = symaddr(g_bps);
    float* pbq   = symaddr(g_bpq);
    float* pmean = symaddr(g_mean);
    float* prstd = symaddr(g_rstd);
    float* pgb   = symaddr(g_gateb);

    __nv_bfloat16 *xa_h = symaddr_bf(g_xa_hi),  *xa_l = symaddr_bf(g_xa_lo);
    __half        *x_f  = symaddr_h(g_x_f16);
    __nv_bfloat16 *ag_h = symaddr_bf(g_agg_hi), *ag_l = symaddr_bf(g_agg_lo);
    __half        *f1_f = symaddr_h(g_fc1_f16);
    __half        *f2_f = symaddr_h(g_fc2_f16);
    __nv_bfloat16 *rb_h = symaddr_bf(g_rbf_hi), *rb_l = symaddr_bf(g_rbf_lo);
    __half        *h1_f = symaddr_h(g_h1_f16);
    __half        *y_f  = symaddr_h(g_y_f16);
    __half        *ee_f = symaddr_h(g_ee_f16);

    __nv_bfloat16 *aew_h = symaddr_bf(g_aewT_hi),  *aew_l = symaddr_bf(g_aewT_lo);
    __nv_bfloat16 *e1w_h = symaddr_bf(g_ee1wT_hi), *e1w_l = symaddr_bf(g_ee1wT_lo);
    __half        *e2w_f = symaddr_h(g_ee2wT_f16);
    __half        *gtw_f = symaddr_h(g_gatewT_f16);
    __half        *egw_f = symaddr_h(g_egwT_f16);
    __nv_bfloat16 *gw_h  = symaddr_bf(g_gwT_hi),   *gw_l  = symaddr_bf(g_gwT_lo);
    __half        *f1w_f = symaddr_h(g_fc1wT_f16);
    __half        *f2w_f = symaddr_h(g_fc2wT_f16);
    __half        *f3w_f = symaddr_h(g_fc3wT_f16);

    // ---- launches 0..4: prerequisites for ee1 GEMM (launch #5 profiled) ----
    bond_kernel<<<(E + 255) / 256, 256>>>(E, r, pbond);
    {
        long tot = (long)E * 80;
        rbf_split_kernel<<<(int)((tot + 255) / 256), 256>>>((int)tot, pbond, rb_h, rb_l);
    }
    transconv(ee1_w, e1w_h, e1w_l, 80, 64, 128, 0);
    conv_pad(atom_features, xa_h, xa_l, N, 92, 128);
    transconv(ae_w, aew_h, aew_l, 92, 256, 128, 0);
    launch_tc(enc, 0, 0, 0, 0, E, 64, 128, E, 128,
              rb_h, rb_l, e1w_h, e1w_l, ee1_b, ph1, nullptr, nullptr);

    // ---- remaining weight prep ----
    transconv(ee2_w, e2w_f, nullptr, 64, 256, 64, 1);
    for (int i = 0; i < 4; i++) {
        long wo = (long)i * 256 * 256;
        long go = (long)i * 512 * 256;
        transconv(sg_w + wo, gtw_f + go, nullptr, 256, 256, 256, 1);
        transconv(dg_w + wo, gtw_f + go + 256 * 256, nullptr, 256, 256, 256, 1);
        transconv(eg_w + wo, egw_f + wo, nullptr, 256, 256, 256, 1);
        transconv(gcn_w + wo, gw_h + wo, gw_l + wo, 256, 256, 256, 0);
    }
    transconv(fc1_w, f1w_f, nullptr, 256, 1024, 256, 1);
    transconv(fc2_w, f2w_f, nullptr, 1024, 2048, 1024, 1);
    transconv(fc3_w, f3w_f, nullptr, 2048, 10000, 2048, 1);
    gate_bias_concat<<<8, 256>>>(sg_b, dg_b, pgb);

    // ---- degrees & norms ----
    zero(pdegs, N); zero(pdegd, N);
    deg_kernel<<<(E + 255) / 256, 256>>>(E, src, dst, pdegs, pdegd);
    norm_kernel<<<(N + 255) / 256, 256>>>(N, pdegs, pdegd, pnl, pnr);

    // ---- atom embedding MLP (bf16 3-product; x -> fp32 + fp16) ----
    launch_tc(enc, 0, 0, 0, 0, N, 256, 128, NPAD, 256,
              xa_h, xa_l, aew_h, aew_l, ae_b, ppre, nullptr, nullptr);
    run_bn(N, 256, ppre, ae_g, ae_be, px, x_f, pbs, pbq, pmean, prstd);

    // ---- edge embedding chain ----
    run_bn(E, 64, ph1, ee1_g, ee1_be, nullptr, h1_f, pbs, pbq, pmean, prstd);
    launch_tc(enc, 0, 0, 1, 0, E, 256, 64, E, 256,            // ee2 fp16
              h1_f, nullptr, e2w_f, nullptr, ee2_b, py, nullptr, nullptr);
    run_bn(E, 256, py, ee2_g, ee2_be, nullptr, y_f, pbs, pbq, pmean, prstd);

    // ---- 4 gated GCN layers ----
    for (int i = 0; i < 4; i++) {
        long wo = (long)i * 256 * 256;
        long go = (long)i * 512 * 256;
        const float* egb = eg_b + i * 256;
        const float* gb  = gcn_b + i * 256;

        // fused gate GEMM: fp16 single product, fp32 out
        launch_tc(enc, 0, 0, 1, 0, N, 512, 256, NPAD, 512,
                  x_f, nullptr, gtw_f + go, nullptr, pgb + i * 512, pgate, nullptr, nullptr);
        // edge gate GEMM: fp16 single product, fp16-only out
        launch_tc(enc, 0, 2, 1, 0, E, 256, 256, E, 256,
                  y_f, nullptr, egw_f + wo, nullptr, egb, nullptr, nullptr, ee_f);

        zero(pagg, (long)N * 256);
        edge_gate_agg<<<(E + 3) / 4, 256>>>(E, px, pgate, ee_f, src, dst, pnl, pagg);
        conv_pad(pagg, ag_h, ag_l, N, 256, 256);

        // residual GCN GEMM: bf16 3-product; writes px fp32 + x fp16
        launch_tc(enc, 2, 2, 0, 0, N, 256, 256, NPAD, 256,
                  ag_h, ag_l, gw_h + wo, gw_l + wo, gb, px, pnr, x_f);
    }

    // ---- readout MLP: all fp16 single product ----
    launch_tc(enc, 1, 2, 1, 0, N, 1024, 256, NPAD, 1024,
              x_f, nullptr, f1w_f, nullptr, fc1_b, nullptr, nullptr, f1_f);
    launch_tc(enc, 1, 2, 1, 1, N, 2048, 1024, NPAD, 2048,
              f1_f, nullptr, f2w_f, nullptr, fc2_b, nullptr, nullptr, f2_f);
    launch_tc(enc, 1, 0, 1, 1, N, 10000, 2048, NPAD, 10112,
              f2_f, nullptr, f3w_f, nullptr, fc3_b, (float*)d_out, nullptr, nullptr);
}